// round 2
// baseline (speedup 1.0000x reference)
#include <cuda_runtime.h>
#include <math.h>

#define NTOK 8192
#define NSEQ 1024
#define NBAT 8
#define NHEAD 8

// ---------------- device scratch ----------------
__device__ float g_mv [NTOK*256];
__device__ float g_s  [NTOK*32];
__device__ float g_nmv[NTOK*256];
__device__ float g_ns [NTOK*32];
__device__ float g_hmv[NTOK*768];   // qkv (48ch) or mlp hidden (32ch)
__device__ float g_hs [NTOK*96];    // qkv_s (96) or mlp hidden s (64)
__device__ float g_Q[(size_t)64*NSEQ*20];
__device__ float g_K[(size_t)64*NSEQ*20];
__device__ float g_V[(size_t)64*NSEQ*36];
__device__ float g_O[(size_t)64*NSEQ*36];

// ---------------- blade tables ----------------
__constant__ int   c_kdiag[16] = {0,1,1,1,1,2,2,2,2,2,2,3,3,3,3,4};
__constant__ int   c_pair [16] = {-1,0,-1,-1,-1,2,3,4,-1,-1,-1,8,9,10,-1,14};
__constant__ int   c_koff [16] = {0,5,0,0,0,6,6,6,0,0,0,7,7,7,0,8};
__constant__ float c_inner[16] = {1,0,1,1,1,0,0,0,1,1,1,0,0,0,1,0};
__constant__ int   c_iblades[8]= {0,2,3,4,8,9,10,14};

// compile-time blade algebra (for geometric product)
__host__ __device__ constexpr int blade_mask(int i){
  return i==0?0: i==1?1: i==2?2: i==3?4: i==4?8: i==5?3: i==6?5: i==7?9:
         i==8?6: i==9?10: i==10?12: i==11?7: i==12?11: i==13?13: i==14?14: 15;
}
__host__ __device__ constexpr int mask_idx(int m){
  return m==0?0: m==1?1: m==2?2: m==3?5: m==4?3: m==5?6: m==6?8: m==7?11:
         m==8?4: m==9?7: m==10?9: m==11?12: m==12?10: m==13?13: m==14?14: 15;
}
__host__ __device__ constexpr int pc4(int v){ return (v&1)+((v>>1)&1)+((v>>2)&1)+((v>>3)&1); }
__host__ __device__ constexpr int gp_par(int ma,int mb){
  return ( ((mb&1)?pc4(ma>>1):0) + (((mb>>1)&1)?pc4(ma>>2):0) + (((mb>>2)&1)?pc4(ma>>3):0) ) & 1;
}

template<int I,int J>
__device__ __forceinline__ void gp_term(float (&acc)[16], const float* x, const float* y){
  constexpr int ma = blade_mask(I);
  constexpr int mb = blade_mask(J);
  if constexpr (!(ma & mb & 1)) {
    constexpr int k  = mask_idx(ma ^ mb);
    constexpr int sg = gp_par(ma, mb);
    float p = x[I]*y[J];
    if constexpr (sg) acc[k] -= p; else acc[k] += p;
  }
}
#define GP_ROW(I) \
  gp_term<I,0>(acc,x,y);  gp_term<I,1>(acc,x,y);  gp_term<I,2>(acc,x,y);  gp_term<I,3>(acc,x,y); \
  gp_term<I,4>(acc,x,y);  gp_term<I,5>(acc,x,y);  gp_term<I,6>(acc,x,y);  gp_term<I,7>(acc,x,y); \
  gp_term<I,8>(acc,x,y);  gp_term<I,9>(acc,x,y);  gp_term<I,10>(acc,x,y); gp_term<I,11>(acc,x,y);\
  gp_term<I,12>(acc,x,y); gp_term<I,13>(acc,x,y); gp_term<I,14>(acc,x,y); gp_term<I,15>(acc,x,y);

__device__ __forceinline__ float gelu_f(float v){
  float v3 = v*v*v;
  return 0.5f*v*(1.f + tanhf(0.7978845608028654f*(v + 0.044715f*v3)));
}

// ---------------- embed ----------------
__global__ void embed_kernel(const float* __restrict__ inp,
                             const float* __restrict__ win_mv,
                             const float* __restrict__ win_bs){
  int idx = blockIdx.x*blockDim.x + threadIdx.x;
  if (idx < NTOK*16){
    int t = idx>>4, o = idx&15;
    float x = inp[t*3+0], y = inp[t*3+1], z = inp[t*3+2];
    float w3 = win_mv[o*9+3], w8 = win_mv[o*9+8];
    float* M = g_mv + (size_t)t*256 + o*16;
    #pragma unroll
    for(int a=0;a<16;a++) M[a]=0.f;
    M[11] = -z*w3;  M[12] = y*w3;  M[13] = -x*w3;  M[14] = w3;  M[15] = w8;
  } else if (idx < NTOK*16 + NTOK*32){
    int r = idx - NTOK*16; int t = r>>5, j = r&31;
    g_s[t*32+j] = win_bs[j];
  }
}

// ---------------- fused (LN) + equi_linear ----------------
template<int OMV,int OS,bool LN,bool RES>
__global__ void __launch_bounds__(256) equi_kernel(
    const float* __restrict__ xmv, const float* __restrict__ xs,
    const float* __restrict__ wmv, const float* __restrict__ wsm,
    const float* __restrict__ wms, const float* __restrict__ wss,
    float* __restrict__ ymv, float* __restrict__ ys)
{
  constexpr int OMVP = OMV + 1;   // pad to kill LDS bank conflicts
  extern __shared__ float sm[];
  float* SWmv = sm;                    // [144][OMVP]
  float* SWsm = SWmv + 144*OMVP;       // [32][OMV]
  float* SWms = SWsm + 32*OMV;         // [16][OS]
  float* SWss = SWms + 16*OS;          // [32][OS]
  float* SX   = SWss + 32*OS;          // [8][288]
  int tid = threadIdx.x;

  for(int idx=tid; idx<OMV*144; idx+=256){ int o=idx/144, r=idx%144; SWmv[r*OMVP+o]=wmv[idx]; }
  for(int idx=tid; idx<OMV*32 ; idx+=256){ int o=idx/32 , j=idx%32 ; SWsm[j*OMV+o]=wsm[idx]; }
  for(int idx=tid; idx<OS*16  ; idx+=256){ int o=idx/16 , i=idx%16 ; SWms[i*OS+o]=wms[idx]; }
  for(int idx=tid; idx<OS*32  ; idx+=256){ int o=idx/32 , j=idx%32 ; SWss[j*OS+o]=wss[idx]; }

  size_t t0 = (size_t)blockIdx.x * 8;
  for(int idx=tid; idx<8*256; idx+=256){ int tt=idx>>8; SX[tt*288+(idx&255)] = xmv[(t0+tt)*256+(idx&255)]; }
  for(int idx=tid; idx<8*32 ; idx+=256){ int tt=idx>>5; SX[tt*288+256+(idx&31)] = xs[(t0+tt)*32+(idx&31)]; }
  __syncthreads();

  if (LN){
    int w = tid>>5, lane = tid&31;     // warp w normalizes token w
    float* X = SX + w*288;
    float ss = 0.f;
    #pragma unroll
    for(int r=0;r<8;r++){ int i=lane+32*r; float v=X[i]; ss += v*v*c_inner[i&15]; }
    #pragma unroll
    for(int off=16;off;off>>=1) ss += __shfl_xor_sync(0xffffffffu, ss, off);
    float sc = rsqrtf(ss*0.0625f + 1e-6f);
    #pragma unroll
    for(int r=0;r<8;r++) X[lane+32*r] *= sc;
    float v = X[256+lane]; float s2 = v*v;
    #pragma unroll
    for(int off=16;off;off>>=1) s2 += __shfl_xor_sync(0xffffffffu, s2, off);
    X[256+lane] = v * rsqrtf(s2*0.03125f + 1e-6f);
    __syncthreads();
  }

  const int NOUT = OMV*16 + OS;
  for(int tt=0; tt<8; tt++){
    const float* X  = SX + tt*288;
    const float* XS = X + 256;
    size_t t = t0 + tt;
    for(int out=tid; out<NOUT; out+=256){
      float val = 0.f;
      if (out < OMV*16){
        int o = out>>4, a = out&15;
        int kd = c_kdiag[a];
        #pragma unroll
        for(int i=0;i<16;i++) val += SWmv[(i*9+kd)*OMVP+o] * X[i*16+a];
        int b = c_pair[a];
        if (b >= 0){
          int ko = c_koff[a];
          #pragma unroll
          for(int i=0;i<16;i++) val += SWmv[(i*9+ko)*OMVP+o] * X[i*16+b];
        }
        if (a == 0){
          #pragma unroll
          for(int j=0;j<32;j++) val += SWsm[j*OMV+o] * XS[j];
        }
        float* Y = ymv + t*(OMV*16) + out;
        if (RES) *Y += val; else *Y = val;
      } else {
        int o = out - OMV*16;
        #pragma unroll
        for(int j=0;j<32;j++) val += SWss[j*OS+o] * XS[j];
        #pragma unroll
        for(int i=0;i<16;i++) val += SWms[i*OS+o] * X[i*16];
        float* Y = ys + t*OS + o;
        if (RES) *Y += val; else *Y = val;
      }
    }
  }
}

// ---------------- pack / attention / unpack ----------------
__global__ void pack_kernel(){
  int idx = blockIdx.x*blockDim.x + threadIdx.x;
  if (idx >= NTOK*8) return;
  int t = idx>>3, h = idx&7;
  int b = t>>10, n = t&1023;
  size_t pe = ((size_t)(b*8+h))*NSEQ + n;
  const float* M = g_hmv + (size_t)t*768;
  const float* S = g_hs  + (size_t)t*96;
  float* q = g_Q + pe*20; float* k = g_K + pe*20; float* v = g_V + pe*36;
  #pragma unroll
  for(int ci=0; ci<2; ci++){
    #pragma unroll
    for(int ib=0; ib<8; ib++){
      int a = c_iblades[ib];
      q[ci*8+ib] = M[(2*h+ci)*16 + a];
      k[ci*8+ib] = M[(16+2*h+ci)*16 + a];
    }
    #pragma unroll
    for(int a=0;a<16;a++) v[ci*16+a] = M[(32+2*h+ci)*16 + a];
  }
  #pragma unroll
  for(int d=0;d<4;d++){
    q[16+d] = S[h*4+d];
    k[16+d] = S[32+h*4+d];
    v[32+d] = S[64+h*4+d];
  }
}

__global__ void __launch_bounds__(128) attn_kernel(){
  int bh = blockIdx.x, qt = blockIdx.y, tid = threadIdx.x;
  int qi = qt*128 + tid;
  const float SCALE = 0.22360679774997896f;  // 1/sqrt(20)
  float q[20];
  const float* qp = g_Q + ((size_t)bh*NSEQ + qi)*20;
  #pragma unroll
  for(int d=0; d<20; d++) q[d] = qp[d]*SCALE;
  float m = -1e30f, l = 0.f, acc[36];
  #pragma unroll
  for(int d=0; d<36; d++) acc[d] = 0.f;
  __shared__ float sk[128*20];
  __shared__ float sv[128*36];
  for(int kt=0; kt<8; kt++){
    __syncthreads();
    const float* kp = g_K + ((size_t)bh*NSEQ + kt*128)*20;
    const float* vp = g_V + ((size_t)bh*NSEQ + kt*128)*36;
    for(int i=tid; i<128*20; i+=128) sk[i] = kp[i];
    for(int i=tid; i<128*36; i+=128) sv[i] = vp[i];
    __syncthreads();
    #pragma unroll 4
    for(int j=0; j<128; j++){
      float s = 0.f;
      #pragma unroll
      for(int d=0; d<20; d++) s += q[d]*sk[j*20+d];
      if (s <= m){
        float p = __expf(s - m);
        l += p;
        #pragma unroll
        for(int d=0; d<36; d++) acc[d] += p*sv[j*36+d];
      } else {
        float corr = __expf(m - s);
        m = s; l = l*corr + 1.f;
        #pragma unroll
        for(int d=0; d<36; d++) acc[d] = acc[d]*corr + sv[j*36+d];
      }
    }
  }
  float inv = 1.f/l;
  float* op = g_O + ((size_t)bh*NSEQ + qi)*36;
  #pragma unroll
  for(int d=0; d<36; d++) op[d] = acc[d]*inv;
}

__global__ void unpack_kernel(){
  int idx = blockIdx.x*blockDim.x + threadIdx.x;
  if (idx >= NTOK*8) return;
  int t = idx>>3, h = idx&7;
  int b = t>>10, n = t&1023;
  const float* o = g_O + (((size_t)(b*8+h))*NSEQ + n)*36;
  float* M = g_nmv + (size_t)t*256;
  float* S = g_ns  + (size_t)t*32;
  #pragma unroll
  for(int ci=0; ci<2; ci++)
    #pragma unroll
    for(int a=0;a<16;a++) M[(2*h+ci)*16+a] = o[ci*16+a];
  #pragma unroll
  for(int d=0;d<4;d++) S[h*4+d] = o[32+d];
}

// ---------------- geometric product + gated gelu ----------------
__global__ void gp_kernel(){
  int idx = blockIdx.x*blockDim.x + threadIdx.x;
  if (idx < NTOK*16){
    int t = idx>>4, c = idx&15;
    const float* h1 = g_hmv + (size_t)t*512 + c*16;   // channels 0..15
    const float* h2 = h1 + 256;                        // channels 16..31
    float x[16], y[16], acc[16];
    #pragma unroll
    for(int i=0;i<16;i++){ x[i]=h1[i]; y[i]=h2[i]; acc[i]=0.f; }
    GP_ROW(0)  GP_ROW(1)  GP_ROW(2)  GP_ROW(3)
    GP_ROW(4)  GP_ROW(5)  GP_ROW(6)  GP_ROW(7)
    GP_ROW(8)  GP_ROW(9)  GP_ROW(10) GP_ROW(11)
    GP_ROW(12) GP_ROW(13) GP_ROW(14) GP_ROW(15)
    float g = gelu_f(acc[0]);
    float* out = g_nmv + (size_t)t*256 + c*16;
    #pragma unroll
    for(int k=0;k<16;k++) out[k] = acc[k]*g;
  } else if (idx < NTOK*16 + NTOK*32){
    int r = idx - NTOK*16; int t = r>>5, j = r&31;
    const float* hs = g_hs + (size_t)t*64;
    g_ns[t*32+j] = hs[j] * gelu_f(hs[32+j]);
  }
}

// ---------------- final projection + mean ----------------
__global__ void final_kernel(const float* __restrict__ wout_mv,
                             const float* __restrict__ wout_sm,
                             float* __restrict__ out){
  int b = blockIdx.x, tid = threadIdx.x;
  __shared__ float red[256];
  float acc = 0.f;
  for(int n=tid; n<NSEQ; n+=256){
    size_t t = (size_t)b*NSEQ + n;
    const float* M = g_mv + t*256;
    const float* S = g_s + t*32;
    float v = 0.f;
    #pragma unroll
    for(int i=0;i<16;i++) v += wout_mv[i*9] * M[i*16];
    #pragma unroll
    for(int j=0;j<32;j++) v += wout_sm[j] * S[j];
    acc += v;
  }
  red[tid] = acc; __syncthreads();
  for(int s=128; s; s>>=1){ if (tid < s) red[tid] += red[tid+s]; __syncthreads(); }
  if (tid == 0) out[b] = red[0] * (1.f/NSEQ);
}

// ---------------- host ----------------
extern "C" void kernel_launch(void* const* d_in, const int* in_sizes, int n_in,
                              void* d_out, int out_size) {
  const float* inputs    = (const float*)d_in[0];
  const float* win_mv    = (const float*)d_in[1];
  // d_in[2] (win_ms) multiplies an all-zero component; unused.
  const float* win_bs    = (const float*)d_in[3];
  const float* qkv_wmv   = (const float*)d_in[4];
  const float* qkv_wsm   = (const float*)d_in[5];
  const float* qkv_wms   = (const float*)d_in[6];
  const float* qkv_wss   = (const float*)d_in[7];
  const float* aout_wmv  = (const float*)d_in[8];
  const float* aout_wsm  = (const float*)d_in[9];
  const float* aout_wms  = (const float*)d_in[10];
  const float* aout_wss  = (const float*)d_in[11];
  const float* m1_wmv    = (const float*)d_in[12];
  const float* m1_wsm    = (const float*)d_in[13];
  const float* m1_wms    = (const float*)d_in[14];
  const float* m1_wss    = (const float*)d_in[15];
  const float* m2_wmv    = (const float*)d_in[16];
  const float* m2_wsm    = (const float*)d_in[17];
  const float* m2_wms    = (const float*)d_in[18];
  const float* m2_wss    = (const float*)d_in[19];
  const float* wout_mv   = (const float*)d_in[20];
  const float* wout_sm   = (const float*)d_in[21];

  float *p_mv, *p_s, *p_nmv, *p_ns, *p_hmv, *p_hs;
  cudaGetSymbolAddress((void**)&p_mv , g_mv);
  cudaGetSymbolAddress((void**)&p_s  , g_s);
  cudaGetSymbolAddress((void**)&p_nmv, g_nmv);
  cudaGetSymbolAddress((void**)&p_ns , g_ns);
  cudaGetSymbolAddress((void**)&p_hmv, g_hmv);
  cudaGetSymbolAddress((void**)&p_hs , g_hs);

  // dynamic smem sizes (floats): SWmv 144*(OMV+1) + SWsm 32*OMV + SWms 16*OS + SWss 32*OS + SX 2304
  const int sz48 = (144*49 + 32*48 + 16*96 + 32*96 + 2304) * 4;  // 62016 B
  const int sz32 = (144*33 + 32*32 + 16*64 + 32*64 + 2304) * 4;  // 44608 B
  const int sz16 = (144*17 + 32*16 + 16*32 + 32*32 + 2304) * 4;  // 27200 B
  cudaFuncSetAttribute((const void*)equi_kernel<48,96,true ,false>,
                       cudaFuncAttributeMaxDynamicSharedMemorySize, sz48);

  embed_kernel<<<(NTOK*48 + 255)/256, 256>>>(inputs, win_mv, win_bs);

  for (int l = 0; l < 8; l++){
    // --- attention block ---
    equi_kernel<48,96,true ,false><<<NTOK/8, 256, sz48>>>(
        p_mv, p_s,
        qkv_wmv + (size_t)l*48*16*9, qkv_wsm + (size_t)l*48*32,
        qkv_wms + (size_t)l*96*16,   qkv_wss + (size_t)l*96*32,
        p_hmv, p_hs);
    pack_kernel<<<(NTOK*8 + 255)/256, 256>>>();
    attn_kernel<<<dim3(64, NSEQ/128), 128>>>();
    unpack_kernel<<<(NTOK*8 + 255)/256, 256>>>();
    equi_kernel<16,32,false,true ><<<NTOK/8, 256, sz16>>>(
        p_nmv, p_ns,
        aout_wmv + (size_t)l*16*16*9, aout_wsm + (size_t)l*16*32,
        aout_wms + (size_t)l*32*16,   aout_wss + (size_t)l*32*32,
        p_mv, p_s);
    // --- mlp block ---
    equi_kernel<32,64,true ,false><<<NTOK/8, 256, sz32>>>(
        p_mv, p_s,
        m1_wmv + (size_t)l*32*16*9, m1_wsm + (size_t)l*32*32,
        m1_wms + (size_t)l*64*16,   m1_wss + (size_t)l*64*32,
        p_hmv, p_hs);
    gp_kernel<<<(NTOK*48 + 255)/256, 256>>>();
    equi_kernel<16,32,false,true ><<<NTOK/8, 256, sz16>>>(
        p_nmv, p_ns,
        m2_wmv + (size_t)l*16*16*9, m2_wsm + (size_t)l*16*32,
        m2_wms + (size_t)l*32*16,   m2_wss + (size_t)l*32*32,
        p_mv, p_s);
  }

  final_kernel<<<NBAT, 256>>>(wout_mv, wout_sm, (float*)d_out);
}

// round 3
// speedup vs baseline: 1.2654x; 1.2654x over previous
#include <cuda_runtime.h>
#include <math.h>

#define NTOK 8192
#define NSEQ 1024
#define NBAT 8

// ---------------- device scratch ----------------
__device__ float g_mv [NTOK*256];
__device__ float g_s  [NTOK*32];
__device__ float g_nmv[NTOK*256];
__device__ float g_ns [NTOK*32];
__device__ float g_hmv[NTOK*512];   // mlp hidden (32ch)
__device__ float g_hs [NTOK*64];    // mlp hidden s
__device__ float g_Q[(size_t)64*NSEQ*20];
__device__ float g_K[(size_t)64*NSEQ*20];
__device__ float g_V[(size_t)64*NSEQ*36];
__device__ float g_O[(size_t)64*NSEQ*36];

// ---------------- blade tables ----------------
__constant__ int   c_kdiag[16] = {0,1,1,1,1,2,2,2,2,2,2,3,3,3,3,4};
__constant__ int   c_pair [16] = {-1,0,-1,-1,-1,2,3,4,-1,-1,-1,8,9,10,-1,14};
__constant__ int   c_koff [16] = {0,5,0,0,0,6,6,6,0,0,0,7,7,7,0,8};
__constant__ float c_inner[16] = {1,0,1,1,1,0,0,0,1,1,1,0,0,0,1,0};
__constant__ int   c_ibidx[16] = {0,-1,1,2,3,-1,-1,-1,4,5,6,-1,-1,-1,7,-1};

// compile-time blade algebra (for geometric product)
__host__ __device__ constexpr int blade_mask(int i){
  return i==0?0: i==1?1: i==2?2: i==3?4: i==4?8: i==5?3: i==6?5: i==7?9:
         i==8?6: i==9?10: i==10?12: i==11?7: i==12?11: i==13?13: i==14?14: 15;
}
__host__ __device__ constexpr int mask_idx(int m){
  return m==0?0: m==1?1: m==2?2: m==3?5: m==4?3: m==5?6: m==6?8: m==7?11:
         m==8?4: m==9?7: m==10?9: m==11?12: m==12?10: m==13?13: m==14?14: 15;
}
__host__ __device__ constexpr int pc4(int v){ return (v&1)+((v>>1)&1)+((v>>2)&1)+((v>>3)&1); }
__host__ __device__ constexpr int gp_par(int ma,int mb){
  return ( ((mb&1)?pc4(ma>>1):0) + (((mb>>1)&1)?pc4(ma>>2):0) + (((mb>>2)&1)?pc4(ma>>3):0) ) & 1;
}
template<int I,int J>
__device__ __forceinline__ void gp_term(float (&acc)[16], const float* x, const float* y){
  constexpr int ma = blade_mask(I);
  constexpr int mb = blade_mask(J);
  if constexpr (!(ma & mb & 1)) {
    constexpr int k  = mask_idx(ma ^ mb);
    constexpr int sg = gp_par(ma, mb);
    float p = x[I]*y[J];
    if constexpr (sg) acc[k] -= p; else acc[k] += p;
  }
}
#define GP_ROW(I) \
  gp_term<I,0>(acc,x,y);  gp_term<I,1>(acc,x,y);  gp_term<I,2>(acc,x,y);  gp_term<I,3>(acc,x,y); \
  gp_term<I,4>(acc,x,y);  gp_term<I,5>(acc,x,y);  gp_term<I,6>(acc,x,y);  gp_term<I,7>(acc,x,y); \
  gp_term<I,8>(acc,x,y);  gp_term<I,9>(acc,x,y);  gp_term<I,10>(acc,x,y); gp_term<I,11>(acc,x,y);\
  gp_term<I,12>(acc,x,y); gp_term<I,13>(acc,x,y); gp_term<I,14>(acc,x,y); gp_term<I,15>(acc,x,y);

__device__ __forceinline__ float gelu_f(float v){
  float v3 = v*v*v;
  return 0.5f*v*(1.f + tanhf(0.7978845608028654f*(v + 0.044715f*v3)));
}

// ---------------- embed ----------------
__global__ void embed_kernel(const float* __restrict__ inp,
                             const float* __restrict__ win_mv,
                             const float* __restrict__ win_bs){
  int idx = blockIdx.x*blockDim.x + threadIdx.x;
  if (idx < NTOK*16){
    int t = idx>>4, o = idx&15;
    float x = inp[t*3+0], y = inp[t*3+1], z = inp[t*3+2];
    float w3 = win_mv[o*9+3], w8 = win_mv[o*9+8];
    float* M = g_mv + (size_t)t*256 + o*16;
    #pragma unroll
    for(int a=0;a<16;a++) M[a]=0.f;
    M[11] = -z*w3;  M[12] = y*w3;  M[13] = -x*w3;  M[14] = w3;  M[15] = w8;
  } else if (idx < NTOK*16 + NTOK*32){
    int r = idx - NTOK*16; int t = r>>5, j = r&31;
    g_s[t*32+j] = win_bs[j];
  }
}

// ---------------- fused (LN) + equi_linear v2 ----------------
// SX layout per token: blade-major mv [a*20 + i] (a=0..15, i=0..15, pad 20),
// scalars at 320..351. Token stride 352 floats.
// INM: 0 = read g-layout mv/s, 1 = gather from g_O (fused unpack)
// OUTM: 0 = write [t][o*16+a] (+scalars), 1 = write packed Q/K/V (fused pack)
template<int OMV,int OS,bool LN,bool RES,int INM,int OUTM,int T,int NT>
__global__ void __launch_bounds__(NT) equi2_kernel(
    const float* __restrict__ xmv, const float* __restrict__ xs,
    const float* __restrict__ wmv, const float* __restrict__ wsm,
    const float* __restrict__ wms, const float* __restrict__ wss,
    float* __restrict__ ymv, float* __restrict__ ys)
{
  __shared__ float SX[T*352];
  const int tid = threadIdx.x;
  const size_t t0 = (size_t)blockIdx.x * T;

  // ---- stage inputs ----
  if (INM == 0){
    for(int idx=tid; idx<T*256; idx+=NT){
      int t = idx>>8, r = idx&255, i = r>>4, a = r&15;
      SX[t*352 + a*20 + i] = xmv[(t0+t)*256 + r];
    }
    for(int idx=tid; idx<T*32; idx+=NT){
      int t = idx>>5, j = idx&31;
      SX[t*352 + 320 + j] = xs[(t0+t)*32 + j];
    }
  } else {
    for(int idx=tid; idx<T*256; idx+=NT){
      int t = idx>>8, r = idx&255, i = r>>4, a = r&15;
      int tok = (int)(t0+t); int b = tok>>10, n = tok&1023;
      int h = i>>1, ci = i&1;
      size_t pe = ((size_t)(b*8+h)<<10) + n;
      SX[t*352 + a*20 + i] = g_O[pe*36 + ci*16 + a];
    }
    for(int idx=tid; idx<T*32; idx+=NT){
      int t = idx>>5, j = idx&31;
      int tok = (int)(t0+t); int b = tok>>10, n = tok&1023;
      int h = j>>2, d = j&3;
      size_t pe = ((size_t)(b*8+h)<<10) + n;
      SX[t*352 + 320 + j] = g_O[pe*36 + 32 + d];
    }
  }
  __syncthreads();

  // ---- layernorm (warp w -> token w) ----
  if (LN){
    int w = tid>>5, lane = tid&31;
    if (w < T){
      float* X = SX + w*352;
      int a = lane>>1;
      int base = a*20 + (lane&1)*8;
      float msk = c_inner[a];
      float ss = 0.f;
      #pragma unroll
      for(int r=0;r<8;r++){ float v = X[base+r]; ss += v*v*msk; }
      #pragma unroll
      for(int off=16;off;off>>=1) ss += __shfl_xor_sync(0xffffffffu, ss, off);
      float sc = rsqrtf(ss*0.0625f + 1e-6f);
      #pragma unroll
      for(int r=0;r<8;r++) X[base+r] *= sc;
      float v = X[320+lane];
      float s2 = v*v;
      #pragma unroll
      for(int off=16;off;off>>=1) s2 += __shfl_xor_sync(0xffffffffu, s2, off);
      X[320+lane] = v * rsqrtf(s2*0.03125f + 1e-6f);
    }
    __syncthreads();
  }

  // ---- compute ----
  if (tid < OMV*16){
    // mv output: a uniform within warp groups (threads ordered o-fastest)
    int o = tid % OMV, a = tid / OMV;
    int kd = c_kdiag[a], pr = c_pair[a], ko = c_koff[a];
    float wd[16];
    #pragma unroll
    for(int i=0;i<16;i++) wd[i] = wmv[o*144 + i*9 + kd];
    float wp[16];
    if (pr >= 0){
      #pragma unroll
      for(int i=0;i<16;i++) wp[i] = wmv[o*144 + i*9 + ko];
    }
    for(int t=0; t<T; t++){
      const float* X = SX + t*352;
      const float4* Xa = (const float4*)(X + a*20);
      float val = 0.f;
      #pragma unroll
      for(int c=0;c<4;c++){
        float4 x4 = Xa[c];
        val += wd[c*4+0]*x4.x + wd[c*4+1]*x4.y + wd[c*4+2]*x4.z + wd[c*4+3]*x4.w;
      }
      if (pr >= 0){
        const float4* Xb = (const float4*)(X + pr*20);
        #pragma unroll
        for(int c=0;c<4;c++){
          float4 x4 = Xb[c];
          val += wp[c*4+0]*x4.x + wp[c*4+1]*x4.y + wp[c*4+2]*x4.z + wp[c*4+3]*x4.w;
        }
      }
      if (a == 0){
        const float4* XS = (const float4*)(X + 320);
        const float4* W  = (const float4*)(wsm + o*32);
        #pragma unroll
        for(int c=0;c<8;c++){
          float4 x4 = XS[c]; float4 w4 = __ldg(W + c);
          val += w4.x*x4.x + w4.y*x4.y + w4.z*x4.z + w4.w*x4.w;
        }
      }
      int tok = (int)(t0+t);
      if (OUTM == 0){
        float* Y = ymv + (size_t)tok*(OMV*16) + o*16 + a;
        if (RES) *Y += val; else *Y = val;
      } else {
        // packed QKV write
        int grp = o >> 4, oc = o & 15, h = oc>>1, ci = oc&1;
        int b = tok>>10, n = tok&1023;
        size_t pe = ((size_t)(b*8+h)<<10) + n;
        if (grp == 2){
          g_V[pe*36 + ci*16 + a] = val;
        } else {
          int ib = c_ibidx[a];
          if (ib >= 0){
            float* dst = (grp == 0) ? g_Q : g_K;
            dst[pe*20 + ci*8 + ib] = val;
          }
        }
      }
    }
  } else if (tid < OMV*16 + OS){
    int o = tid - OMV*16;
    float wsr[32];
    #pragma unroll
    for(int j=0;j<32;j++) wsr[j] = wss[o*32 + j];
    for(int t=0; t<T; t++){
      const float* X = SX + t*352;
      const float4* XS = (const float4*)(X + 320);
      float val = 0.f;
      #pragma unroll
      for(int c=0;c<8;c++){
        float4 x4 = XS[c];
        val += wsr[c*4+0]*x4.x + wsr[c*4+1]*x4.y + wsr[c*4+2]*x4.z + wsr[c*4+3]*x4.w;
      }
      // ms term: blade-0 row is contiguous [0..15]
      const float4* X0 = (const float4*)(X);
      const float4* Wm = (const float4*)(wms + o*16);
      #pragma unroll
      for(int c=0;c<4;c++){
        float4 x4 = X0[c]; float4 w4 = __ldg(Wm + c);
        val += w4.x*x4.x + w4.y*x4.y + w4.z*x4.z + w4.w*x4.w;
      }
      int tok = (int)(t0+t);
      if (OUTM == 0){
        float* Y = ys + (size_t)tok*OS + o;
        if (RES) *Y += val; else *Y = val;
      } else {
        int grp = o>>5, rem = o&31, h = rem>>2, d = rem&3;
        int b = tok>>10, n = tok&1023;
        size_t pe = ((size_t)(b*8+h)<<10) + n;
        if (grp == 0)      g_Q[pe*20 + 16 + d] = val;
        else if (grp == 1) g_K[pe*20 + 16 + d] = val;
        else               g_V[pe*36 + 32 + d] = val;
      }
    }
  }
}

// ---------------- attention (2 queries/thread, float4 K/V) ----------------
__global__ void __launch_bounds__(128) attn_kernel(){
  const int bh = blockIdx.x, qt = blockIdx.y, tid = threadIdx.x;
  const int qi0 = qt*256 + tid;           // second query: qi0 + 128
  const float SCALE = 0.22360679774997896f;  // 1/sqrt(20)

  float4 q0[5], q1[5];
  {
    const float4* qp0 = (const float4*)(g_Q + ((size_t)bh*NSEQ + qi0)*20);
    const float4* qp1 = (const float4*)(g_Q + ((size_t)bh*NSEQ + qi0 + 128)*20);
    #pragma unroll
    for(int c=0;c<5;c++){
      float4 v = qp0[c]; v.x*=SCALE; v.y*=SCALE; v.z*=SCALE; v.w*=SCALE; q0[c]=v;
      float4 w = qp1[c]; w.x*=SCALE; w.y*=SCALE; w.z*=SCALE; w.w*=SCALE; q1[c]=w;
    }
  }
  float m0=-1e30f, l0=0.f, m1=-1e30f, l1=0.f;
  float4 a0[9], a1[9];
  #pragma unroll
  for(int c=0;c<9;c++){ a0[c]=make_float4(0,0,0,0); a1[c]=make_float4(0,0,0,0); }

  __shared__ float4 sk4[128*5];
  __shared__ float4 sv4[128*9];

  for(int kt=0; kt<8; kt++){
    __syncthreads();
    const float4* kp = (const float4*)(g_K + ((size_t)bh*NSEQ + kt*128)*20);
    const float4* vp = (const float4*)(g_V + ((size_t)bh*NSEQ + kt*128)*36);
    #pragma unroll
    for(int i=0;i<5;i++) sk4[tid + 128*i] = kp[tid + 128*i];
    #pragma unroll
    for(int i=0;i<9;i++) sv4[tid + 128*i] = vp[tid + 128*i];
    __syncthreads();

    for(int j=0; j<128; j++){
      float s0 = 0.f, s1 = 0.f;
      #pragma unroll
      for(int c=0;c<5;c++){
        float4 k4 = sk4[j*5+c];
        s0 += q0[c].x*k4.x + q0[c].y*k4.y + q0[c].z*k4.z + q0[c].w*k4.w;
        s1 += q1[c].x*k4.x + q1[c].y*k4.y + q1[c].z*k4.z + q1[c].w*k4.w;
      }
      float p0, p1;
      if (s0 > m0){
        float cc = __expf(m0 - s0); m0 = s0; l0 *= cc; p0 = 1.f;
        #pragma unroll
        for(int c=0;c<9;c++){ a0[c].x*=cc; a0[c].y*=cc; a0[c].z*=cc; a0[c].w*=cc; }
      } else p0 = __expf(s0 - m0);
      if (s1 > m1){
        float cc = __expf(m1 - s1); m1 = s1; l1 *= cc; p1 = 1.f;
        #pragma unroll
        for(int c=0;c<9;c++){ a1[c].x*=cc; a1[c].y*=cc; a1[c].z*=cc; a1[c].w*=cc; }
      } else p1 = __expf(s1 - m1);
      l0 += p0; l1 += p1;
      #pragma unroll
      for(int c=0;c<9;c++){
        float4 v4 = sv4[j*9+c];
        a0[c].x += p0*v4.x; a0[c].y += p0*v4.y; a0[c].z += p0*v4.z; a0[c].w += p0*v4.w;
        a1[c].x += p1*v4.x; a1[c].y += p1*v4.y; a1[c].z += p1*v4.z; a1[c].w += p1*v4.w;
      }
    }
  }
  float inv0 = 1.f/l0, inv1 = 1.f/l1;
  float4* op0 = (float4*)(g_O + ((size_t)bh*NSEQ + qi0)*36);
  float4* op1 = (float4*)(g_O + ((size_t)bh*NSEQ + qi0 + 128)*36);
  #pragma unroll
  for(int c=0;c<9;c++){
    float4 v = a0[c]; v.x*=inv0; v.y*=inv0; v.z*=inv0; v.w*=inv0; op0[c]=v;
    float4 w = a1[c]; w.x*=inv1; w.y*=inv1; w.z*=inv1; w.w*=inv1; op1[c]=w;
  }
}

// ---------------- geometric product + gated gelu ----------------
__global__ void gp_kernel(){
  int idx = blockIdx.x*blockDim.x + threadIdx.x;
  if (idx < NTOK*16){
    int t = idx>>4, c = idx&15;
    const float* h1 = g_hmv + (size_t)t*512 + c*16;   // channels 0..15
    const float* h2 = h1 + 256;                        // channels 16..31
    float x[16], y[16], acc[16];
    #pragma unroll
    for(int i=0;i<4;i++){
      float4 v = ((const float4*)h1)[i];
      x[i*4]=v.x; x[i*4+1]=v.y; x[i*4+2]=v.z; x[i*4+3]=v.w;
      float4 w = ((const float4*)h2)[i];
      y[i*4]=w.x; y[i*4+1]=w.y; y[i*4+2]=w.z; y[i*4+3]=w.w;
    }
    #pragma unroll
    for(int i=0;i<16;i++) acc[i]=0.f;
    GP_ROW(0)  GP_ROW(1)  GP_ROW(2)  GP_ROW(3)
    GP_ROW(4)  GP_ROW(5)  GP_ROW(6)  GP_ROW(7)
    GP_ROW(8)  GP_ROW(9)  GP_ROW(10) GP_ROW(11)
    GP_ROW(12) GP_ROW(13) GP_ROW(14) GP_ROW(15)
    float g = gelu_f(acc[0]);
    float4* out = (float4*)(g_nmv + (size_t)t*256 + c*16);
    #pragma unroll
    for(int i=0;i<4;i++)
      out[i] = make_float4(acc[i*4]*g, acc[i*4+1]*g, acc[i*4+2]*g, acc[i*4+3]*g);
  } else if (idx < NTOK*16 + NTOK*32){
    int r = idx - NTOK*16; int t = r>>5, j = r&31;
    const float* hs = g_hs + (size_t)t*64;
    g_ns[t*32+j] = hs[j] * gelu_f(hs[32+j]);
  }
}

// ---------------- final projection + mean ----------------
__global__ void final_kernel(const float* __restrict__ wout_mv,
                             const float* __restrict__ wout_sm,
                             float* __restrict__ out){
  int b = blockIdx.x, tid = threadIdx.x;
  __shared__ float red[256];
  float acc = 0.f;
  for(int n=tid; n<NSEQ; n+=256){
    size_t t = (size_t)b*NSEQ + n;
    const float* M = g_mv + t*256;
    const float* S = g_s + t*32;
    float v = 0.f;
    #pragma unroll
    for(int i=0;i<16;i++) v += wout_mv[i*9] * M[i*16];
    #pragma unroll
    for(int j=0;j<32;j++) v += wout_sm[j] * S[j];
    acc += v;
  }
  red[tid] = acc; __syncthreads();
  for(int s=128; s; s>>=1){ if (tid < s) red[tid] += red[tid+s]; __syncthreads(); }
  if (tid == 0) out[b] = red[0] * (1.f/NSEQ);
}

// ---------------- host ----------------
extern "C" void kernel_launch(void* const* d_in, const int* in_sizes, int n_in,
                              void* d_out, int out_size) {
  const float* inputs    = (const float*)d_in[0];
  const float* win_mv    = (const float*)d_in[1];
  const float* win_bs    = (const float*)d_in[3];
  const float* qkv_wmv   = (const float*)d_in[4];
  const float* qkv_wsm   = (const float*)d_in[5];
  const float* qkv_wms   = (const float*)d_in[6];
  const float* qkv_wss   = (const float*)d_in[7];
  const float* aout_wmv  = (const float*)d_in[8];
  const float* aout_wsm  = (const float*)d_in[9];
  const float* aout_wms  = (const float*)d_in[10];
  const float* aout_wss  = (const float*)d_in[11];
  const float* m1_wmv    = (const float*)d_in[12];
  const float* m1_wsm    = (const float*)d_in[13];
  const float* m1_wms    = (const float*)d_in[14];
  const float* m1_wss    = (const float*)d_in[15];
  const float* m2_wmv    = (const float*)d_in[16];
  const float* m2_wsm    = (const float*)d_in[17];
  const float* m2_wms    = (const float*)d_in[18];
  const float* m2_wss    = (const float*)d_in[19];
  const float* wout_mv   = (const float*)d_in[20];
  const float* wout_sm   = (const float*)d_in[21];

  float *p_mv, *p_s, *p_nmv, *p_ns, *p_hmv, *p_hs;
  cudaGetSymbolAddress((void**)&p_mv , g_mv);
  cudaGetSymbolAddress((void**)&p_s  , g_s);
  cudaGetSymbolAddress((void**)&p_nmv, g_nmv);
  cudaGetSymbolAddress((void**)&p_ns , g_ns);
  cudaGetSymbolAddress((void**)&p_hmv, g_hmv);
  cudaGetSymbolAddress((void**)&p_hs , g_hs);

  embed_kernel<<<(NTOK*48 + 255)/256, 256>>>(inputs, win_mv, win_bs);

  for (int l = 0; l < 8; l++){
    // --- attention block: LN + QKV equi (fused pack) ---
    equi2_kernel<48,96,true ,false,0,1,16,864><<<NTOK/16, 864>>>(
        p_mv, p_s,
        qkv_wmv + (size_t)l*48*16*9, qkv_wsm + (size_t)l*48*32,
        qkv_wms + (size_t)l*96*16,   qkv_wss + (size_t)l*96*32,
        nullptr, nullptr);
    attn_kernel<<<dim3(64, NSEQ/256), 128>>>();
    // out-projection with fused unpack (reads g_O), residual add
    equi2_kernel<16,32,false,true ,1,0,16,288><<<NTOK/16, 288>>>(
        p_mv, p_s,
        aout_wmv + (size_t)l*16*16*9, aout_wsm + (size_t)l*16*32,
        aout_wms + (size_t)l*32*16,   aout_wss + (size_t)l*32*32,
        p_mv, p_s);
    // --- mlp block ---
    equi2_kernel<32,64,true ,false,0,0,16,576><<<NTOK/16, 576>>>(
        p_mv, p_s,
        m1_wmv + (size_t)l*32*16*9, m1_wsm + (size_t)l*32*32,
        m1_wms + (size_t)l*64*16,   m1_wss + (size_t)l*64*32,
        p_hmv, p_hs);
    gp_kernel<<<(NTOK*48 + 255)/256, 256>>>();
    equi2_kernel<16,32,false,true ,0,0,16,288><<<NTOK/16, 288>>>(
        p_nmv, p_ns,
        m2_wmv + (size_t)l*16*16*9, m2_wsm + (size_t)l*16*32,
        m2_wms + (size_t)l*32*16,   m2_wss + (size_t)l*32*32,
        p_mv, p_s);
  }

  final_kernel<<<NBAT, 256>>>(wout_mv, wout_sm, (float*)d_out);
}

// round 6
// speedup vs baseline: 1.2705x; 1.0040x over previous
#include <cuda_runtime.h>
#include <math.h>

#define NTOK 8192
#define NSEQ 1024
#define NBAT 8

typedef unsigned long long u64;

// ---------------- f32x2 packed helpers (Blackwell) ----------------
__device__ __forceinline__ u64 pack2f(float lo, float hi){
  u64 r; asm("mov.b64 %0, {%1, %2};" : "=l"(r) : "f"(lo), "f"(hi)); return r;
}
__device__ __forceinline__ u64 ffma2(u64 a, u64 b, u64 c){
  u64 d; asm("fma.rn.f32x2 %0, %1, %2, %3;" : "=l"(d) : "l"(a), "l"(b), "l"(c)); return d;
}
__device__ __forceinline__ u64 fmul2(u64 a, u64 b){
  u64 d; asm("mul.rn.f32x2 %0, %1, %2;" : "=l"(d) : "l"(a), "l"(b)); return d;
}
__device__ __forceinline__ u64 fadd2(u64 a, u64 b){
  u64 d; asm("add.rn.f32x2 %0, %1, %2;" : "=l"(d) : "l"(a), "l"(b)); return d;
}
__device__ __forceinline__ float hadd2(u64 v){
  float a,b; asm("mov.b64 {%0, %1}, %2;" : "=f"(a), "=f"(b) : "l"(v)); return a+b;
}

// ---------------- device scratch ----------------
__device__ float g_mv [NTOK*256];
__device__ float g_s  [NTOK*32];
__device__ float g_nmv[NTOK*256];
__device__ float g_ns [NTOK*32];
__device__ float g_hmv[NTOK*512];
__device__ float g_hs [NTOK*64];
__device__ float g_Q[(size_t)64*NSEQ*20];
__device__ float g_K[(size_t)64*NSEQ*20];
__device__ float g_V[(size_t)64*NSEQ*36];
__device__ float g_O[(size_t)64*NSEQ*36];

// ---------------- blade tables ----------------
__constant__ int   c_kdiag[16] = {0,1,1,1,1,2,2,2,2,2,2,3,3,3,3,4};
__constant__ int   c_pair [16] = {-1,0,-1,-1,-1,2,3,4,-1,-1,-1,8,9,10,-1,14};
__constant__ int   c_koff [16] = {0,5,0,0,0,6,6,6,0,0,0,7,7,7,0,8};
__constant__ float c_inner[16] = {1,0,1,1,1,0,0,0,1,1,1,0,0,0,1,0};
__constant__ int   c_ibidx[16] = {0,-1,1,2,3,-1,-1,-1,4,5,6,-1,-1,-1,7,-1};

// compile-time blade algebra
__host__ __device__ constexpr int blade_mask(int i){
  return i==0?0: i==1?1: i==2?2: i==3?4: i==4?8: i==5?3: i==6?5: i==7?9:
         i==8?6: i==9?10: i==10?12: i==11?7: i==12?11: i==13?13: i==14?14: 15;
}
__host__ __device__ constexpr int mask_idx(int m){
  return m==0?0: m==1?1: m==2?2: m==3?5: m==4?3: m==5?6: m==6?8: m==7?11:
         m==8?4: m==9?7: m==10?9: m==11?12: m==12?10: m==13?13: m==14?14: 15;
}
__host__ __device__ constexpr int pc4(int v){ return (v&1)+((v>>1)&1)+((v>>2)&1)+((v>>3)&1); }
__host__ __device__ constexpr int gp_par(int ma,int mb){
  return ( ((mb&1)?pc4(ma>>1):0) + (((mb>>1)&1)?pc4(ma>>2):0) + (((mb>>2)&1)?pc4(ma>>3):0) ) & 1;
}
template<int I,int J>
__device__ __forceinline__ void gp_term(float (&acc)[16], const float* x, const float* y){
  constexpr int ma = blade_mask(I);
  constexpr int mb = blade_mask(J);
  if constexpr (!(ma & mb & 1)) {
    constexpr int k  = mask_idx(ma ^ mb);
    constexpr int sg = gp_par(ma, mb);
    float p = x[I]*y[J];
    if constexpr (sg) acc[k] -= p; else acc[k] += p;
  }
}
#define GP_ROW(I) \
  gp_term<I,0>(acc,x,y);  gp_term<I,1>(acc,x,y);  gp_term<I,2>(acc,x,y);  gp_term<I,3>(acc,x,y); \
  gp_term<I,4>(acc,x,y);  gp_term<I,5>(acc,x,y);  gp_term<I,6>(acc,x,y);  gp_term<I,7>(acc,x,y); \
  gp_term<I,8>(acc,x,y);  gp_term<I,9>(acc,x,y);  gp_term<I,10>(acc,x,y); gp_term<I,11>(acc,x,y);\
  gp_term<I,12>(acc,x,y); gp_term<I,13>(acc,x,y); gp_term<I,14>(acc,x,y); gp_term<I,15>(acc,x,y);

__device__ __forceinline__ float gelu_f(float v){
  float v3 = v*v*v;
  return 0.5f*v*(1.f + tanhf(0.7978845608028654f*(v + 0.044715f*v3)));
}

// ---------------- embed ----------------
__global__ void embed_kernel(const float* __restrict__ inp,
                             const float* __restrict__ win_mv,
                             const float* __restrict__ win_bs){
  int idx = blockIdx.x*blockDim.x + threadIdx.x;
  if (idx < NTOK*16){
    int t = idx>>4, o = idx&15;
    float x = inp[t*3+0], y = inp[t*3+1], z = inp[t*3+2];
    float w3 = win_mv[o*9+3], w8 = win_mv[o*9+8];
    float* M = g_mv + (size_t)t*256 + o*16;
    #pragma unroll
    for(int a=0;a<16;a++) M[a]=0.f;
    M[11] = -z*w3;  M[12] = y*w3;  M[13] = -x*w3;  M[14] = w3;  M[15] = w8;
  } else if (idx < NTOK*16 + NTOK*32){
    int r = idx - NTOK*16; int t = r>>5, j = r&31;
    g_s[t*32+j] = win_bs[j];
  }
}

// ---------------- fused (LN) + equi_linear (f32x2 + staged output) ------
// SX per token: blade-major mv [a*20+i], scalars at 320..351, stride 352.
template<int OMV,int OS,bool LN,bool RES,int INM,int OUTM,int T,int NT>
__global__ void __launch_bounds__(NT) equi2_kernel(
    const float* __restrict__ xmv, const float* __restrict__ xs,
    const float* __restrict__ wmv, const float* __restrict__ wsm,
    const float* __restrict__ wms, const float* __restrict__ wss,
    float* __restrict__ ymv, float* __restrict__ ys)
{
  extern __shared__ float smbuf[];
  float* SX = smbuf;                 // T*352
  float* SY = smbuf + T*352;        // T*(OMV*16+OS)  (OUTM==0 only)
  constexpr int OSZ = OMV*16 + OS;
  const int tid = threadIdx.x;
  const size_t t0 = (size_t)blockIdx.x * T;

  // ---- stage inputs ----
  if (INM == 0){
    for(int idx=tid; idx<T*256; idx+=NT){
      int t = idx>>8, r = idx&255, i = r>>4, a = r&15;
      SX[t*352 + a*20 + i] = xmv[(t0+t)*256 + r];
    }
    for(int idx=tid; idx<T*32; idx+=NT){
      int t = idx>>5, j = idx&31;
      SX[t*352 + 320 + j] = xs[(t0+t)*32 + j];
    }
  } else {
    for(int idx=tid; idx<T*256; idx+=NT){
      int t = idx>>8, r = idx&255, i = r>>4, a = r&15;
      int tok = (int)(t0+t); int b = tok>>10, n = tok&1023;
      int h = i>>1, ci = i&1;
      size_t pe = ((size_t)(b*8+h)<<10) + n;
      SX[t*352 + a*20 + i] = g_O[pe*36 + ci*16 + a];
    }
    for(int idx=tid; idx<T*32; idx+=NT){
      int t = idx>>5, j = idx&31;
      int tok = (int)(t0+t); int b = tok>>10, n = tok&1023;
      int h = j>>2, d = j&3;
      size_t pe = ((size_t)(b*8+h)<<10) + n;
      SX[t*352 + 320 + j] = g_O[pe*36 + 32 + d];
    }
  }
  __syncthreads();

  // ---- layernorm (warp w -> token w) ----
  if (LN){
    int w = tid>>5, lane = tid&31;
    if (w < T){
      float* X = SX + w*352;
      int a = lane>>1;
      int base = a*20 + (lane&1)*8;
      float msk = c_inner[a];
      float ss = 0.f;
      #pragma unroll
      for(int r=0;r<8;r++){ float v = X[base+r]; ss += v*v*msk; }
      #pragma unroll
      for(int off=16;off;off>>=1) ss += __shfl_xor_sync(0xffffffffu, ss, off);
      float sc = rsqrtf(ss*0.0625f + 1e-6f);
      #pragma unroll
      for(int r=0;r<8;r++) X[base+r] *= sc;
      float v = X[320+lane];
      float s2 = v*v;
      #pragma unroll
      for(int off=16;off;off>>=1) s2 += __shfl_xor_sync(0xffffffffu, s2, off);
      X[320+lane] = v * rsqrtf(s2*0.03125f + 1e-6f);
    }
    __syncthreads();
  }

  // ---- compute ----
  if (tid < OMV*16){
    int o = tid % OMV, a = tid / OMV;
    int kd = c_kdiag[a], pr = c_pair[a], ko = c_koff[a];
    u64 wd2[8], wp2[8];
    #pragma unroll
    for(int i=0;i<8;i++)
      wd2[i] = pack2f(wmv[o*144 + (2*i)*9 + kd], wmv[o*144 + (2*i+1)*9 + kd]);
    if (pr >= 0){
      #pragma unroll
      for(int i=0;i<8;i++)
        wp2[i] = pack2f(wmv[o*144 + (2*i)*9 + ko], wmv[o*144 + (2*i+1)*9 + ko]);
    }
    for(int t=0; t<T; t++){
      const float* X = SX + t*352;
      const u64* Xa = (const u64*)(X + a*20);
      u64 v0 = fmul2(wd2[0], Xa[0]);
      u64 v1 = fmul2(wd2[1], Xa[1]);
      #pragma unroll
      for(int c=2;c<8;c+=2){
        v0 = ffma2(wd2[c],   Xa[c],   v0);
        v1 = ffma2(wd2[c+1], Xa[c+1], v1);
      }
      if (pr >= 0){
        const u64* Xb = (const u64*)(X + pr*20);
        #pragma unroll
        for(int c=0;c<8;c+=2){
          v0 = ffma2(wp2[c],   Xb[c],   v0);
          v1 = ffma2(wp2[c+1], Xb[c+1], v1);
        }
      }
      if (a == 0){
        const u64* XS = (const u64*)(X + 320);
        const u64* Wm = (const u64*)(wsm + o*32);
        #pragma unroll
        for(int c=0;c<16;c+=2){
          v0 = ffma2(Wm[c],   XS[c],   v0);
          v1 = ffma2(Wm[c+1], XS[c+1], v1);
        }
      }
      float val = hadd2(fadd2(v0, v1));
      if (OUTM == 0){
        SY[t*OSZ + a*OMV + o] = val;     // thread-ordered: conflict-free
      } else {
        int tok = (int)(t0+t);
        int grp = o >> 4, oc = o & 15, h = oc>>1, ci = oc&1;
        int b = tok>>10, n = tok&1023;
        size_t pe = ((size_t)(b*8+h)<<10) + n;
        if (grp == 2){
          g_V[pe*36 + ci*16 + a] = val;
        } else {
          int ib = c_ibidx[a];
          if (ib >= 0){
            float* dst = (grp == 0) ? g_Q : g_K;
            dst[pe*20 + ci*8 + ib] = val;
          }
        }
      }
    }
  } else if (tid < OMV*16 + OS){
    int o = tid - OMV*16;
    u64 wss2[16], wms2[8];
    #pragma unroll
    for(int j=0;j<16;j++) wss2[j] = pack2f(wss[o*32+2*j], wss[o*32+2*j+1]);
    #pragma unroll
    for(int i=0;i<8;i++)  wms2[i] = pack2f(wms[o*16+2*i], wms[o*16+2*i+1]);
    for(int t=0; t<T; t++){
      const float* X = SX + t*352;
      const u64* XS = (const u64*)(X + 320);
      u64 v0 = fmul2(wss2[0], XS[0]);
      u64 v1 = fmul2(wss2[1], XS[1]);
      #pragma unroll
      for(int c=2;c<16;c+=2){
        v0 = ffma2(wss2[c],   XS[c],   v0);
        v1 = ffma2(wss2[c+1], XS[c+1], v1);
      }
      const u64* X0 = (const u64*)(X);
      #pragma unroll
      for(int c=0;c<8;c+=2){
        v0 = ffma2(wms2[c],   X0[c],   v0);
        v1 = ffma2(wms2[c+1], X0[c+1], v1);
      }
      float val = hadd2(fadd2(v0, v1));
      if (OUTM == 0){
        SY[t*OSZ + OMV*16 + o] = val;
      } else {
        int tok = (int)(t0+t);
        int grp = o>>5, rem = o&31, h = rem>>2, d = rem&3;
        int b = tok>>10, n = tok&1023;
        size_t pe = ((size_t)(b*8+h)<<10) + n;
        if (grp == 0)      g_Q[pe*20 + 16 + d] = val;
        else if (grp == 1) g_K[pe*20 + 16 + d] = val;
        else               g_V[pe*36 + 32 + d] = val;
      }
    }
  }

  // ---- coalesced output copy (OUTM==0), float2 granularity ----
  if (OUTM == 0){
    __syncthreads();
    for(int idx=tid; idx<T*OMV*8; idx+=NT){
      int t = idx/(OMV*8), r2 = idx%(OMV*8);   // r2 indexes pairs
      int o = r2>>3, ap = r2&7;                 // blade pair ap -> blades 2ap,2ap+1
      float vlo = SY[t*OSZ + (2*ap)*OMV + o];
      float vhi = SY[t*OSZ + (2*ap+1)*OMV + o];
      float2* Y = (float2*)(ymv + (t0+t)*(size_t)(OMV*16) + o*16 + 2*ap);
      if (RES){ float2 old = *Y; old.x += vlo; old.y += vhi; *Y = old; }
      else    { *Y = make_float2(vlo, vhi); }
    }
    for(int idx=tid; idx<T*OS/2; idx+=NT){
      int t = idx/(OS/2), j = idx%(OS/2);
      float vlo = SY[t*OSZ + OMV*16 + 2*j];
      float vhi = SY[t*OSZ + OMV*16 + 2*j+1];
      float2* Y = (float2*)(ys + (t0+t)*(size_t)OS + 2*j);
      if (RES){ float2 old = *Y; old.x += vlo; old.y += vhi; *Y = old; }
      else    { *Y = make_float2(vlo, vhi); }
    }
  }
}

// ---------------- attention (2 q/thread, f32x2 math) ----------------
__global__ void __launch_bounds__(128) attn_kernel(){
  const int bh = blockIdx.x, qt = blockIdx.y, tid = threadIdx.x;
  const int qi0 = qt*256 + tid;
  const float SCALE = 0.22360679774997896f;  // 1/sqrt(20)

  u64 q0[10], q1[10];
  {
    const float* qp0 = g_Q + ((size_t)bh*NSEQ + qi0)*20;
    const float* qp1 = qp0 + 128*20;
    #pragma unroll
    for(int c=0;c<10;c++){
      q0[c] = pack2f(qp0[2*c]*SCALE, qp0[2*c+1]*SCALE);
      q1[c] = pack2f(qp1[2*c]*SCALE, qp1[2*c+1]*SCALE);
    }
  }
  float m0=-1e30f, l0=0.f, m1=-1e30f, l1=0.f;
  u64 a0[18], a1[18];
  #pragma unroll
  for(int c=0;c<18;c++){ a0[c]=0ull; a1[c]=0ull; }

  __shared__ float4 sk4[128*5];
  __shared__ float4 sv4[128*9];

  for(int kt=0; kt<8; kt++){
    __syncthreads();
    const float4* kp = (const float4*)(g_K + ((size_t)bh*NSEQ + kt*128)*20);
    const float4* vp = (const float4*)(g_V + ((size_t)bh*NSEQ + kt*128)*36);
    #pragma unroll
    for(int i=0;i<5;i++) sk4[tid + 128*i] = kp[tid + 128*i];
    #pragma unroll
    for(int i=0;i<9;i++) sv4[tid + 128*i] = vp[tid + 128*i];
    __syncthreads();

    for(int j=0; j<128; j++){
      const u64* kk = (const u64*)(sk4 + j*5);
      const u64* vv = (const u64*)(sv4 + j*9);
      u64 t0a = fmul2(q0[0], kk[0]), t0b = fmul2(q0[1], kk[1]);
      u64 t1a = fmul2(q1[0], kk[0]), t1b = fmul2(q1[1], kk[1]);
      #pragma unroll
      for(int c=2;c<10;c+=2){
        t0a = ffma2(q0[c], kk[c], t0a);  t0b = ffma2(q0[c+1], kk[c+1], t0b);
        t1a = ffma2(q1[c], kk[c], t1a);  t1b = ffma2(q1[c+1], kk[c+1], t1b);
      }
      float s0 = hadd2(fadd2(t0a, t0b));
      float s1 = hadd2(fadd2(t1a, t1b));
      float p0, p1;
      if (s0 > m0){
        float cc = __expf(m0 - s0); m0 = s0; l0 = l0*cc + 1.f;
        u64 cp = pack2f(cc, cc);
        #pragma unroll
        for(int c=0;c<18;c++) a0[c] = fmul2(a0[c], cp);
        p0 = 1.f;
      } else { p0 = __expf(s0 - m0); l0 += p0; }
      if (s1 > m1){
        float cc = __expf(m1 - s1); m1 = s1; l1 = l1*cc + 1.f;
        u64 cp = pack2f(cc, cc);
        #pragma unroll
        for(int c=0;c<18;c++) a1[c] = fmul2(a1[c], cp);
        p1 = 1.f;
      } else { p1 = __expf(s1 - m1); l1 += p1; }
      u64 pp0 = pack2f(p0, p0), pp1 = pack2f(p1, p1);
      #pragma unroll
      for(int c=0;c<18;c++){
        a0[c] = ffma2(pp0, vv[c], a0[c]);
        a1[c] = ffma2(pp1, vv[c], a1[c]);
      }
    }
  }
  u64 i0 = pack2f(1.f/l0, 1.f/l0), i1 = pack2f(1.f/l1, 1.f/l1);
  u64* op0 = (u64*)(g_O + ((size_t)bh*NSEQ + qi0)*36);
  u64* op1 = (u64*)(g_O + ((size_t)bh*NSEQ + qi0 + 128)*36);
  #pragma unroll
  for(int c=0;c<18;c++){
    op0[c] = fmul2(a0[c], i0);
    op1[c] = fmul2(a1[c], i1);
  }
}

// ---------------- geometric product + gated gelu ----------------
__global__ void gp_kernel(){
  int idx = blockIdx.x*blockDim.x + threadIdx.x;
  if (idx < NTOK*16){
    int t = idx>>4, c = idx&15;
    const float* h1 = g_hmv + (size_t)t*512 + c*16;
    const float* h2 = h1 + 256;
    float x[16], y[16], acc[16];
    #pragma unroll
    for(int i=0;i<4;i++){
      float4 v = ((const float4*)h1)[i];
      x[i*4]=v.x; x[i*4+1]=v.y; x[i*4+2]=v.z; x[i*4+3]=v.w;
      float4 w = ((const float4*)h2)[i];
      y[i*4]=w.x; y[i*4+1]=w.y; y[i*4+2]=w.z; y[i*4+3]=w.w;
    }
    #pragma unroll
    for(int i=0;i<16;i++) acc[i]=0.f;
    GP_ROW(0)  GP_ROW(1)  GP_ROW(2)  GP_ROW(3)
    GP_ROW(4)  GP_ROW(5)  GP_ROW(6)  GP_ROW(7)
    GP_ROW(8)  GP_ROW(9)  GP_ROW(10) GP_ROW(11)
    GP_ROW(12) GP_ROW(13) GP_ROW(14) GP_ROW(15)
    float g = gelu_f(acc[0]);
    float4* out = (float4*)(g_nmv + (size_t)t*256 + c*16);
    #pragma unroll
    for(int i=0;i<4;i++)
      out[i] = make_float4(acc[i*4]*g, acc[i*4+1]*g, acc[i*4+2]*g, acc[i*4+3]*g);
  } else if (idx < NTOK*16 + NTOK*32){
    int r = idx - NTOK*16; int t = r>>5, j = r&31;
    const float* hs = g_hs + (size_t)t*64;
    g_ns[t*32+j] = hs[j] * gelu_f(hs[32+j]);
  }
}

// ---------------- final projection + mean ----------------
__global__ void final_kernel(const float* __restrict__ wout_mv,
                             const float* __restrict__ wout_sm,
                             float* __restrict__ out){
  int b = blockIdx.x, tid = threadIdx.x;
  __shared__ float red[256];
  float acc = 0.f;
  for(int n=tid; n<NSEQ; n+=256){
    size_t t = (size_t)b*NSEQ + n;
    const float* M = g_mv + t*256;
    const float* S = g_s + t*32;
    float v = 0.f;
    #pragma unroll
    for(int i=0;i<16;i++) v += wout_mv[i*9] * M[i*16];
    #pragma unroll
    for(int j=0;j<32;j++) v += wout_sm[j] * S[j];
    acc += v;
  }
  red[tid] = acc; __syncthreads();
  for(int s=128; s; s>>=1){ if (tid < s) red[tid] += red[tid+s]; __syncthreads(); }
  if (tid == 0) out[b] = red[0] * (1.f/NSEQ);
}

// ---------------- host ----------------
extern "C" void kernel_launch(void* const* d_in, const int* in_sizes, int n_in,
                              void* d_out, int out_size) {
  const float* inputs    = (const float*)d_in[0];
  const float* win_mv    = (const float*)d_in[1];
  const float* win_bs    = (const float*)d_in[3];
  const float* qkv_wmv   = (const float*)d_in[4];
  const float* qkv_wsm   = (const float*)d_in[5];
  const float* qkv_wms   = (const float*)d_in[6];
  const float* qkv_wss   = (const float*)d_in[7];
  const float* aout_wmv  = (const float*)d_in[8];
  const float* aout_wsm  = (const float*)d_in[9];
  const float* aout_wms  = (const float*)d_in[10];
  const float* aout_wss  = (const float*)d_in[11];
  const float* m1_wmv    = (const float*)d_in[12];
  const float* m1_wsm    = (const float*)d_in[13];
  const float* m1_wms    = (const float*)d_in[14];
  const float* m1_wss    = (const float*)d_in[15];
  const float* m2_wmv    = (const float*)d_in[16];
  const float* m2_wsm    = (const float*)d_in[17];
  const float* m2_wms    = (const float*)d_in[18];
  const float* m2_wss    = (const float*)d_in[19];
  const float* wout_mv   = (const float*)d_in[20];
  const float* wout_sm   = (const float*)d_in[21];

  float *p_mv, *p_s, *p_nmv, *p_ns, *p_hmv, *p_hs;
  cudaGetSymbolAddress((void**)&p_mv , g_mv);
  cudaGetSymbolAddress((void**)&p_s  , g_s);
  cudaGetSymbolAddress((void**)&p_nmv, g_nmv);
  cudaGetSymbolAddress((void**)&p_ns , g_ns);
  cudaGetSymbolAddress((void**)&p_hmv, g_hmv);
  cudaGetSymbolAddress((void**)&p_hs , g_hs);

  // dynamic smem: SX = 16*352*4 = 22528 B; + SY = 16*OSZ*4 for OUTM==0
  const int smem_qkv = 16*352*4;                    // 22528
  const int smem_out = 16*352*4 + 16*288*4;         // 40960
  const int smem_m1  = 16*352*4 + 16*576*4;         // 59392
  cudaFuncSetAttribute((const void*)equi2_kernel<48,96,true ,false,0,1,16,864>,
                       cudaFuncAttributeMaxDynamicSharedMemorySize, smem_qkv);
  cudaFuncSetAttribute((const void*)equi2_kernel<16,32,false,true ,1,0,16,288>,
                       cudaFuncAttributeMaxDynamicSharedMemorySize, smem_out);
  cudaFuncSetAttribute((const void*)equi2_kernel<32,64,true ,false,0,0,16,576>,
                       cudaFuncAttributeMaxDynamicSharedMemorySize, smem_m1);
  cudaFuncSetAttribute((const void*)equi2_kernel<16,32,false,true ,0,0,16,288>,
                       cudaFuncAttributeMaxDynamicSharedMemorySize, smem_out);

  embed_kernel<<<(NTOK*48 + 255)/256, 256>>>(inputs, win_mv, win_bs);

  for (int l = 0; l < 8; l++){
    equi2_kernel<48,96,true ,false,0,1,16,864><<<NTOK/16, 864, smem_qkv>>>(
        p_mv, p_s,
        qkv_wmv + (size_t)l*48*16*9, qkv_wsm + (size_t)l*48*32,
        qkv_wms + (size_t)l*96*16,   qkv_wss + (size_t)l*96*32,
        nullptr, nullptr);
    attn_kernel<<<dim3(64, NSEQ/256), 128>>>();
    equi2_kernel<16,32,false,true ,1,0,16,288><<<NTOK/16, 288, smem_out>>>(
        p_mv, p_s,
        aout_wmv + (size_t)l*16*16*9, aout_wsm + (size_t)l*16*32,
        aout_wms + (size_t)l*32*16,   aout_wss + (size_t)l*32*32,
        p_mv, p_s);
    equi2_kernel<32,64,true ,false,0,0,16,576><<<NTOK/16, 576, smem_m1>>>(
        p_mv, p_s,
        m1_wmv + (size_t)l*32*16*9, m1_wsm + (size_t)l*32*32,
        m1_wms + (size_t)l*64*16,   m1_wss + (size_t)l*64*32,
        p_hmv, p_hs);
    gp_kernel<<<(NTOK*48 + 255)/256, 256>>>();
    equi2_kernel<16,32,false,true ,0,0,16,288><<<NTOK/16, 288, smem_out>>>(
        p_nmv, p_ns,
        m2_wmv + (size_t)l*16*16*9, m2_wsm + (size_t)l*16*32,
        m2_wms + (size_t)l*32*16,   m2_wss + (size_t)l*32*32,
        p_mv, p_s);
  }

  final_kernel<<<NBAT, 256>>>(wout_mv, wout_sm, (float*)d_out);
}

// round 7
// speedup vs baseline: 1.4009x; 1.1026x over previous
#include <cuda_runtime.h>
#include <math.h>

#define NTOK 8192
#define NSEQ 1024
#define NBAT 8

typedef unsigned long long u64;

// ---------------- f32x2 packed helpers (Blackwell) ----------------
__device__ __forceinline__ u64 pack2f(float lo, float hi){
  u64 r; asm("mov.b64 %0, {%1, %2};" : "=l"(r) : "f"(lo), "f"(hi)); return r;
}
__device__ __forceinline__ u64 ffma2(u64 a, u64 b, u64 c){
  u64 d; asm("fma.rn.f32x2 %0, %1, %2, %3;" : "=l"(d) : "l"(a), "l"(b), "l"(c)); return d;
}
__device__ __forceinline__ u64 fmul2(u64 a, u64 b){
  u64 d; asm("mul.rn.f32x2 %0, %1, %2;" : "=l"(d) : "l"(a), "l"(b)); return d;
}
__device__ __forceinline__ u64 fadd2(u64 a, u64 b){
  u64 d; asm("add.rn.f32x2 %0, %1, %2;" : "=l"(d) : "l"(a), "l"(b)); return d;
}
__device__ __forceinline__ float hadd2(u64 v){
  float a,b; asm("mov.b64 {%0, %1}, %2;" : "=f"(a), "=f"(b) : "l"(v)); return a+b;
}

// ---------------- device scratch ----------------
__device__ float g_mv [NTOK*256];
__device__ float g_s  [NTOK*32];
__device__ float g_Q[(size_t)64*NSEQ*20];
__device__ float g_K[(size_t)64*NSEQ*20];
__device__ float g_V[(size_t)64*NSEQ*36];
__device__ float g_O[(size_t)NTOK*288];     // token-major: [tok][h][36]

// ---------------- blade tables ----------------
__constant__ int   c_kdiag[16] = {0,1,1,1,1,2,2,2,2,2,2,3,3,3,3,4};
__constant__ int   c_pair [16] = {-1,0,-1,-1,-1,2,3,4,-1,-1,-1,8,9,10,-1,14};
__constant__ int   c_koff [16] = {0,5,0,0,0,6,6,6,0,0,0,7,7,7,0,8};
__constant__ float c_inner[16] = {1,0,1,1,1,0,0,0,1,1,1,0,0,0,1,0};
__constant__ int   c_iblades[8]= {0,2,3,4,8,9,10,14};

// compile-time blade algebra (geometric product)
__host__ __device__ constexpr int blade_mask(int i){
  return i==0?0: i==1?1: i==2?2: i==3?4: i==4?8: i==5?3: i==6?5: i==7?9:
         i==8?6: i==9?10: i==10?12: i==11?7: i==12?11: i==13?13: i==14?14: 15;
}
__host__ __device__ constexpr int mask_idx(int m){
  return m==0?0: m==1?1: m==2?2: m==3?5: m==4?3: m==5?6: m==6?8: m==7?11:
         m==8?4: m==9?7: m==10?9: m==11?12: m==12?10: m==13?13: m==14?14: 15;
}
__host__ __device__ constexpr int pc4(int v){ return (v&1)+((v>>1)&1)+((v>>2)&1)+((v>>3)&1); }
__host__ __device__ constexpr int gp_par(int ma,int mb){
  return ( ((mb&1)?pc4(ma>>1):0) + (((mb>>1)&1)?pc4(ma>>2):0) + (((mb>>2)&1)?pc4(ma>>3):0) ) & 1;
}
template<int I,int J>
__device__ __forceinline__ void gp_term(float (&acc)[16], const float* x, const float* y){
  constexpr int ma = blade_mask(I);
  constexpr int mb = blade_mask(J);
  if constexpr (!(ma & mb & 1)) {
    constexpr int k  = mask_idx(ma ^ mb);
    constexpr int sg = gp_par(ma, mb);
    float p = x[I]*y[J];
    if constexpr (sg) acc[k] -= p; else acc[k] += p;
  }
}
#define GP_ROW(I) \
  gp_term<I,0>(acc,x,y);  gp_term<I,1>(acc,x,y);  gp_term<I,2>(acc,x,y);  gp_term<I,3>(acc,x,y); \
  gp_term<I,4>(acc,x,y);  gp_term<I,5>(acc,x,y);  gp_term<I,6>(acc,x,y);  gp_term<I,7>(acc,x,y); \
  gp_term<I,8>(acc,x,y);  gp_term<I,9>(acc,x,y);  gp_term<I,10>(acc,x,y); gp_term<I,11>(acc,x,y);\
  gp_term<I,12>(acc,x,y); gp_term<I,13>(acc,x,y); gp_term<I,14>(acc,x,y); gp_term<I,15>(acc,x,y);

__device__ __forceinline__ float gelu_f(float v){
  float v3 = v*v*v;
  return 0.5f*v*(1.f + tanhf(0.7978845608028654f*(v + 0.044715f*v3)));
}

// ---- equi building blocks (X = blade-major token: [a*20+i], scalars at 320) ----
__device__ __forceinline__ void load_wmv_row(const float* wmv, int o, int kd, int ko, int pr,
                                             u64* wd2, u64* wp2){
  #pragma unroll
  for(int i=0;i<8;i++)
    wd2[i] = pack2f(wmv[o*144 + (2*i)*9 + kd], wmv[o*144 + (2*i+1)*9 + kd]);
  if (pr >= 0){
    #pragma unroll
    for(int i=0;i<8;i++)
      wp2[i] = pack2f(wmv[o*144 + (2*i)*9 + ko], wmv[o*144 + (2*i+1)*9 + ko]);
  }
}
__device__ __forceinline__ float equi_mv_val(const float* X, int a, int pr,
    const u64* wd2, const u64* wp2, const u64* wsm2){
  const u64* Xa = (const u64*)(X + a*20);
  u64 v0 = fmul2(wd2[0], Xa[0]);
  u64 v1 = fmul2(wd2[1], Xa[1]);
  #pragma unroll
  for(int c=2;c<8;c+=2){ v0 = ffma2(wd2[c],Xa[c],v0); v1 = ffma2(wd2[c+1],Xa[c+1],v1); }
  if (pr >= 0){
    const u64* Xb = (const u64*)(X + pr*20);
    #pragma unroll
    for(int c=0;c<8;c+=2){ v0 = ffma2(wp2[c],Xb[c],v0); v1 = ffma2(wp2[c+1],Xb[c+1],v1); }
  }
  if (a == 0){
    const u64* XS = (const u64*)(X + 320);
    #pragma unroll
    for(int c=0;c<16;c+=2){ v0 = ffma2(wsm2[c],XS[c],v0); v1 = ffma2(wsm2[c+1],XS[c+1],v1); }
  }
  return hadd2(fadd2(v0, v1));
}
__device__ __forceinline__ float equi_s_val(const float* X, const u64* wss2, const u64* wms2){
  const u64* XS = (const u64*)(X + 320);
  u64 v0 = fmul2(wss2[0], XS[0]);
  u64 v1 = fmul2(wss2[1], XS[1]);
  #pragma unroll
  for(int c=2;c<16;c+=2){ v0 = ffma2(wss2[c],XS[c],v0); v1 = ffma2(wss2[c+1],XS[c+1],v1); }
  const u64* X0 = (const u64*)(X);
  #pragma unroll
  for(int c=0;c<8;c+=2){ v0 = ffma2(wms2[c],X0[c],v0); v1 = ffma2(wms2[c+1],X0[c+1],v1); }
  return hadd2(fadd2(v0, v1));
}

// ---------------- embed ----------------
__global__ void embed_kernel(const float* __restrict__ inp,
                             const float* __restrict__ win_mv,
                             const float* __restrict__ win_bs){
  int idx = blockIdx.x*blockDim.x + threadIdx.x;
  if (idx < NTOK*16){
    int t = idx>>4, o = idx&15;
    float x = inp[t*3+0], y = inp[t*3+1], z = inp[t*3+2];
    float w3 = win_mv[o*9+3], w8 = win_mv[o*9+8];
    float* M = g_mv + (size_t)t*256 + o*16;
    #pragma unroll
    for(int a=0;a<16;a++) M[a]=0.f;
    M[11] = -z*w3;  M[12] = y*w3;  M[13] = -x*w3;  M[14] = w3;  M[15] = w8;
  } else if (idx < NTOK*16 + NTOK*32){
    int r = idx - NTOK*16; int t = r>>5, j = r&31;
    g_s[t*32+j] = win_bs[j];
  }
}

// ---------------- LN + QKV equi, staged coalesced pack ----------------
// T=16, NT=864. SX: T*352 (blade-major); SY: T*864 (mv [a*48+o], s at 768+o).
__global__ void __launch_bounds__(864) qkv_kernel(
    const float* __restrict__ wmv, const float* __restrict__ wsm,
    const float* __restrict__ wms, const float* __restrict__ wss)
{
  constexpr int T = 16, NT = 864;
  extern __shared__ float sm[];
  float* SX = sm;            // T*352
  float* SY = sm + T*352;    // T*864
  const int tid = threadIdx.x;
  const size_t t0 = (size_t)blockIdx.x * T;
  const int b = (int)(t0 >> 10), n0 = (int)(t0 & 1023);

  for(int idx=tid; idx<T*256; idx+=NT){
    int t = idx>>8, r = idx&255, i = r>>4, a = r&15;
    SX[t*352 + a*20 + i] = g_mv[(t0+t)*256 + r];
  }
  for(int idx=tid; idx<T*32; idx+=NT){
    int t = idx>>5, j = idx&31;
    SX[t*352 + 320 + j] = g_s[(t0+t)*32 + j];
  }
  __syncthreads();

  { // LN: warp w -> token w
    int w = tid>>5, lane = tid&31;
    if (w < T){
      float* X = SX + w*352;
      int a = lane>>1;
      int base = a*20 + (lane&1)*8;
      float msk = c_inner[a];
      float ss = 0.f;
      #pragma unroll
      for(int r=0;r<8;r++){ float v = X[base+r]; ss += v*v*msk; }
      #pragma unroll
      for(int off=16;off;off>>=1) ss += __shfl_xor_sync(0xffffffffu, ss, off);
      float sc = rsqrtf(ss*0.0625f + 1e-6f);
      #pragma unroll
      for(int r=0;r<8;r++) X[base+r] *= sc;
      float v = X[320+lane];
      float s2 = v*v;
      #pragma unroll
      for(int off=16;off;off>>=1) s2 += __shfl_xor_sync(0xffffffffu, s2, off);
      X[320+lane] = v * rsqrtf(s2*0.03125f + 1e-6f);
    }
  }
  __syncthreads();

  // compute: 768 mv outs + 96 s outs
  if (tid < 768){
    int o = tid % 48, a = tid / 48;
    int kd = c_kdiag[a], pr = c_pair[a], ko = c_koff[a];
    u64 wd2[8], wp2[8], wsm2[16];
    load_wmv_row(wmv, o, kd, ko, pr, wd2, wp2);
    if (a == 0){
      #pragma unroll
      for(int j=0;j<16;j++) wsm2[j] = pack2f(wsm[o*32+2*j], wsm[o*32+2*j+1]);
    }
    for(int t=0; t<T; t++)
      SY[t*864 + a*48 + o] = equi_mv_val(SX + t*352, a, pr, wd2, wp2, wsm2);
  } else {
    int o = tid - 768;  // 0..95
    u64 wss2[16], wms2[8];
    #pragma unroll
    for(int j=0;j<16;j++) wss2[j] = pack2f(wss[o*32+2*j], wss[o*32+2*j+1]);
    #pragma unroll
    for(int i=0;i<8;i++)  wms2[i] = pack2f(wms[o*16+2*i], wms[o*16+2*i+1]);
    for(int t=0; t<T; t++)
      SY[t*864 + 768 + o] = equi_s_val(SX + t*352, wss2, wms2);
  }
  __syncthreads();

  // coalesced pack: per-head contiguous runs
  for(int idx=tid; idx<8*T*20; idx+=NT){           // Q
    int h = idx/(T*20), rem = idx%(T*20), t = rem/20, e = rem%20;
    float v;
    if (e < 16){ int ci=e>>3, ib=e&7, a=c_iblades[ib]; v = SY[t*864 + a*48 + (h*2+ci)]; }
    else       { v = SY[t*864 + 768 + h*4 + (e-16)]; }
    g_Q[((size_t)(b*8+h)*NSEQ + n0 + t)*20 + e] = v;
  }
  for(int idx=tid; idx<8*T*20; idx+=NT){           // K
    int h = idx/(T*20), rem = idx%(T*20), t = rem/20, e = rem%20;
    float v;
    if (e < 16){ int ci=e>>3, ib=e&7, a=c_iblades[ib]; v = SY[t*864 + a*48 + (16 + h*2+ci)]; }
    else       { v = SY[t*864 + 768 + 32 + h*4 + (e-16)]; }
    g_K[((size_t)(b*8+h)*NSEQ + n0 + t)*20 + e] = v;
  }
  for(int idx=tid; idx<8*T*36; idx+=NT){           // V
    int h = idx/(T*36), rem = idx%(T*36), t = rem/36, e = rem%36;
    float v;
    if (e < 32){ int ci=e>>4, a=e&15; v = SY[t*864 + a*48 + (32 + h*2+ci)]; }
    else       { v = SY[t*864 + 768 + 64 + h*4 + (e-32)]; }
    g_V[((size_t)(b*8+h)*NSEQ + n0 + t)*36 + e] = v;
  }
}

// ---------------- attention (2 q/thread, f32x2, token-major output) ------
__global__ void __launch_bounds__(128) attn_kernel(){
  const int bh = blockIdx.x, qt = blockIdx.y, tid = threadIdx.x;
  const int b = bh>>3, h = bh&7;
  const int qi0 = qt*256 + tid;
  const float SCALE = 0.22360679774997896f;  // 1/sqrt(20)

  u64 q0[10], q1[10];
  {
    const float* qp0 = g_Q + ((size_t)bh*NSEQ + qi0)*20;
    const float* qp1 = qp0 + 128*20;
    #pragma unroll
    for(int c=0;c<10;c++){
      q0[c] = pack2f(qp0[2*c]*SCALE, qp0[2*c+1]*SCALE);
      q1[c] = pack2f(qp1[2*c]*SCALE, qp1[2*c+1]*SCALE);
    }
  }
  float m0=-1e30f, l0=0.f, m1=-1e30f, l1=0.f;
  u64 a0[18], a1[18];
  #pragma unroll
  for(int c=0;c<18;c++){ a0[c]=0ull; a1[c]=0ull; }

  __shared__ float4 sk4[128*5];
  __shared__ float4 sv4[128*9];

  for(int kt=0; kt<8; kt++){
    __syncthreads();
    const float4* kp = (const float4*)(g_K + ((size_t)bh*NSEQ + kt*128)*20);
    const float4* vp = (const float4*)(g_V + ((size_t)bh*NSEQ + kt*128)*36);
    #pragma unroll
    for(int i=0;i<5;i++) sk4[tid + 128*i] = kp[tid + 128*i];
    #pragma unroll
    for(int i=0;i<9;i++) sv4[tid + 128*i] = vp[tid + 128*i];
    __syncthreads();

    for(int j=0; j<128; j++){
      const u64* kk = (const u64*)(sk4 + j*5);
      const u64* vv = (const u64*)(sv4 + j*9);
      u64 t0a = fmul2(q0[0], kk[0]), t0b = fmul2(q0[1], kk[1]);
      u64 t1a = fmul2(q1[0], kk[0]), t1b = fmul2(q1[1], kk[1]);
      #pragma unroll
      for(int c=2;c<10;c+=2){
        t0a = ffma2(q0[c], kk[c], t0a);  t0b = ffma2(q0[c+1], kk[c+1], t0b);
        t1a = ffma2(q1[c], kk[c], t1a);  t1b = ffma2(q1[c+1], kk[c+1], t1b);
      }
      float s0 = hadd2(fadd2(t0a, t0b));
      float s1 = hadd2(fadd2(t1a, t1b));
      float p0, p1;
      if (s0 > m0){
        float cc = __expf(m0 - s0); m0 = s0; l0 = l0*cc + 1.f;
        u64 cp = pack2f(cc, cc);
        #pragma unroll
        for(int c=0;c<18;c++) a0[c] = fmul2(a0[c], cp);
        p0 = 1.f;
      } else { p0 = __expf(s0 - m0); l0 += p0; }
      if (s1 > m1){
        float cc = __expf(m1 - s1); m1 = s1; l1 = l1*cc + 1.f;
        u64 cp = pack2f(cc, cc);
        #pragma unroll
        for(int c=0;c<18;c++) a1[c] = fmul2(a1[c], cp);
        p1 = 1.f;
      } else { p1 = __expf(s1 - m1); l1 += p1; }
      u64 pp0 = pack2f(p0, p0), pp1 = pack2f(p1, p1);
      #pragma unroll
      for(int c=0;c<18;c++){
        a0[c] = ffma2(pp0, vv[c], a0[c]);
        a1[c] = ffma2(pp1, vv[c], a1[c]);
      }
    }
  }
  u64 i0 = pack2f(1.f/l0, 1.f/l0), i1 = pack2f(1.f/l1, 1.f/l1);
  size_t tok0 = (size_t)b*NSEQ + qi0;
  u64* op0 = (u64*)(g_O + (tok0*8 + h)*36);
  u64* op1 = (u64*)(g_O + ((tok0+128)*8 + h)*36);
  #pragma unroll
  for(int c=0;c<18;c++){
    op0[c] = fmul2(a0[c], i0);
    op1[c] = fmul2(a1[c], i1);
  }
}

// ---------------- fused: out-proj + res + LN + mlp1 + GP + mlp2 + res ----
// T=16 tokens/block, NT=576 threads.
__global__ void __launch_bounds__(576) block2_kernel(
    const float* __restrict__ ao_wmv, const float* __restrict__ ao_wsm,
    const float* __restrict__ ao_wms, const float* __restrict__ ao_wss,
    const float* __restrict__ m1_wmv, const float* __restrict__ m1_wsm,
    const float* __restrict__ m1_wms, const float* __restrict__ m1_wss,
    const float* __restrict__ m2_wmv, const float* __restrict__ m2_wsm,
    const float* __restrict__ m2_wms, const float* __restrict__ m2_wss)
{
  constexpr int T = 16, NT = 576;
  extern __shared__ float sm[];
  float* SA  = sm;             // T*352  attn-out (blade-major)
  float* SR  = SA + T*352;     // T*288  residual (token-major mv[256], s[32])
  float* SX2 = SR + T*288;     // T*352  LN'd input / GP output (blade-major)
  float* SH  = SX2 + T*352;    // T*608  mlp1 hidden ([o*17+a], s at 544)
  const int tid = threadIdx.x;
  const size_t t0 = (size_t)blockIdx.x * T;

  // ---- stage 1: load attn-out (coalesced, token-major) + residual ----
  for(int idx=tid; idx<T*288; idx+=NT){
    int t = idx/288, r = idx%288;
    float v = g_O[(t0+t)*288 + r];
    int h = r/36, e = r%36;
    if (e < 32){ int ci=e>>4, a=e&15; SA[t*352 + a*20 + (h*2+ci)] = v; }
    else       { SA[t*352 + 320 + h*4 + (e-32)] = v; }
  }
  for(int idx=tid; idx<T*256; idx+=NT){
    int t = idx>>8, r = idx&255;
    SR[t*288 + r] = g_mv[(t0+t)*256 + r];
  }
  for(int idx=tid; idx<T*32; idx+=NT){
    int t = idx>>5, j = idx&31;
    SR[t*288 + 256 + j] = g_s[(t0+t)*32 + j];
  }
  __syncthreads();

  // ---- stage 2: out-projection equi + residual add into SR ----
  {
    int out = tid % 288, tp = tid / 288;
    if (out < 256){
      int o = out & 15, a = out >> 4;
      int kd = c_kdiag[a], pr = c_pair[a], ko = c_koff[a];
      u64 wd2[8], wp2[8], wsm2[16];
      load_wmv_row(ao_wmv, o, kd, ko, pr, wd2, wp2);
      if (a == 0){
        #pragma unroll
        for(int j=0;j<16;j++) wsm2[j] = pack2f(ao_wsm[o*32+2*j], ao_wsm[o*32+2*j+1]);
      }
      for(int t=tp; t<T; t+=2)
        SR[t*288 + o*16 + a] += equi_mv_val(SA + t*352, a, pr, wd2, wp2, wsm2);
    } else {
      int o = out - 256;
      u64 wss2[16], wms2[8];
      #pragma unroll
      for(int j=0;j<16;j++) wss2[j] = pack2f(ao_wss[o*32+2*j], ao_wss[o*32+2*j+1]);
      #pragma unroll
      for(int i=0;i<8;i++)  wms2[i] = pack2f(ao_wms[o*16+2*i], ao_wms[o*16+2*i+1]);
      for(int t=tp; t<T; t+=2)
        SR[t*288 + 256 + o] += equi_s_val(SA + t*352, wss2, wms2);
    }
  }
  __syncthreads();

  // ---- stage 3: LN(SR) -> SX2 (blade-major) ----
  {
    int w = tid>>5, lane = tid&31;
    if (w < T){
      const float* R = SR + w*288;
      float ss = 0.f;
      #pragma unroll
      for(int r=0;r<8;r++){ int li = lane + 32*r; float v = R[li]; ss += v*v*c_inner[li&15]; }
      #pragma unroll
      for(int off=16;off;off>>=1) ss += __shfl_xor_sync(0xffffffffu, ss, off);
      float sc = rsqrtf(ss*0.0625f + 1e-6f);
      #pragma unroll
      for(int r=0;r<8;r++){
        int li = lane + 32*r; int o = li>>4, a = li&15;
        SX2[w*352 + a*20 + o] = R[li]*sc;
      }
      float v = R[256+lane];
      float s2 = v*v;
      #pragma unroll
      for(int off=16;off;off>>=1) s2 += __shfl_xor_sync(0xffffffffu, s2, off);
      SX2[w*352 + 320 + lane] = v * rsqrtf(s2*0.03125f + 1e-6f);
    }
  }
  __syncthreads();

  // ---- stage 4: mlp1 equi (32 mv ch + 64 s) -> SH ----
  if (tid < 512){
    int o = tid % 32, a = tid / 32;
    int kd = c_kdiag[a], pr = c_pair[a], ko = c_koff[a];
    u64 wd2[8], wp2[8], wsm2[16];
    load_wmv_row(m1_wmv, o, kd, ko, pr, wd2, wp2);
    if (a == 0){
      #pragma unroll
      for(int j=0;j<16;j++) wsm2[j] = pack2f(m1_wsm[o*32+2*j], m1_wsm[o*32+2*j+1]);
    }
    for(int t=0; t<T; t++)
      SH[t*608 + o*17 + a] = equi_mv_val(SX2 + t*352, a, pr, wd2, wp2, wsm2);
  } else {
    int o = tid - 512;  // 0..63
    u64 wss2[16], wms2[8];
    #pragma unroll
    for(int j=0;j<16;j++) wss2[j] = pack2f(m1_wss[o*32+2*j], m1_wss[o*32+2*j+1]);
    #pragma unroll
    for(int i=0;i<8;i++)  wms2[i] = pack2f(m1_wms[o*16+2*i], m1_wms[o*16+2*i+1]);
    for(int t=0; t<T; t++)
      SH[t*608 + 544 + o] = equi_s_val(SX2 + t*352, wss2, wms2);
  }
  __syncthreads();

  // ---- stage 5: geometric product + gated gelu -> SX2 (blade-major) ----
  for(int idx=tid; idx<768; idx+=NT){
    if (idx < 256){
      int t = idx>>4, c = idx&15;
      const float* h1 = SH + t*608 + c*17;
      const float* h2 = SH + t*608 + (16+c)*17;
      float x[16], y[16], acc[16];
      #pragma unroll
      for(int i=0;i<16;i++){ x[i]=h1[i]; y[i]=h2[i]; acc[i]=0.f; }
      GP_ROW(0)  GP_ROW(1)  GP_ROW(2)  GP_ROW(3)
      GP_ROW(4)  GP_ROW(5)  GP_ROW(6)  GP_ROW(7)
      GP_ROW(8)  GP_ROW(9)  GP_ROW(10) GP_ROW(11)
      GP_ROW(12) GP_ROW(13) GP_ROW(14) GP_ROW(15)
      float g = gelu_f(acc[0]);
      #pragma unroll
      for(int a=0;a<16;a++) SX2[t*352 + a*20 + c] = acc[a]*g;
    } else {
      int r = idx - 256; int t = r>>5, j = r&31;
      const float* hs = SH + t*608 + 544;
      SX2[t*352 + 320 + j] = hs[j] * gelu_f(hs[32+j]);
    }
  }
  __syncthreads();

  // ---- stage 6: mlp2 equi + residual add into SR ----
  {
    int out = tid % 288, tp = tid / 288;
    if (out < 256){
      int o = out & 15, a = out >> 4;
      int kd = c_kdiag[a], pr = c_pair[a], ko = c_koff[a];
      u64 wd2[8], wp2[8], wsm2[16];
      load_wmv_row(m2_wmv, o, kd, ko, pr, wd2, wp2);
      if (a == 0){
        #pragma unroll
        for(int j=0;j<16;j++) wsm2[j] = pack2f(m2_wsm[o*32+2*j], m2_wsm[o*32+2*j+1]);
      }
      for(int t=tp; t<T; t+=2)
        SR[t*288 + o*16 + a] += equi_mv_val(SX2 + t*352, a, pr, wd2, wp2, wsm2);
    } else {
      int o = out - 256;
      u64 wss2[16], wms2[8];
      #pragma unroll
      for(int j=0;j<16;j++) wss2[j] = pack2f(m2_wss[o*32+2*j], m2_wss[o*32+2*j+1]);
      #pragma unroll
      for(int i=0;i<8;i++)  wms2[i] = pack2f(m2_wms[o*16+2*i], m2_wms[o*16+2*i+1]);
      for(int t=tp; t<T; t+=2)
        SR[t*288 + 256 + o] += equi_s_val(SX2 + t*352, wss2, wms2);
    }
  }
  __syncthreads();

  // ---- stage 7: store residual (coalesced float4) ----
  for(int idx=tid; idx<T*64; idx+=NT){
    int t = idx>>6, r4 = idx&63;
    ((float4*)(g_mv + (t0+t)*256))[r4] = ((const float4*)(SR + t*288))[r4];
  }
  for(int idx=tid; idx<T*8; idx+=NT){
    int t = idx>>3, j4 = idx&7;
    ((float4*)(g_s + (t0+t)*32))[j4] = ((const float4*)(SR + t*288 + 256))[j4];
  }
}

// ---------------- final projection + mean ----------------
__global__ void final_kernel(const float* __restrict__ wout_mv,
                             const float* __restrict__ wout_sm,
                             float* __restrict__ out){
  int b = blockIdx.x, tid = threadIdx.x;
  __shared__ float red[256];
  float acc = 0.f;
  for(int n=tid; n<NSEQ; n+=256){
    size_t t = (size_t)b*NSEQ + n;
    const float* M = g_mv + t*256;
    const float* S = g_s + t*32;
    float v = 0.f;
    #pragma unroll
    for(int i=0;i<16;i++) v += wout_mv[i*9] * M[i*16];
    #pragma unroll
    for(int j=0;j<32;j++) v += wout_sm[j] * S[j];
    acc += v;
  }
  red[tid] = acc; __syncthreads();
  for(int s=128; s; s>>=1){ if (tid < s) red[tid] += red[tid+s]; __syncthreads(); }
  if (tid == 0) out[b] = red[0] * (1.f/NSEQ);
}

// ---------------- host ----------------
extern "C" void kernel_launch(void* const* d_in, const int* in_sizes, int n_in,
                              void* d_out, int out_size) {
  const float* inputs    = (const float*)d_in[0];
  const float* win_mv    = (const float*)d_in[1];
  const float* win_bs    = (const float*)d_in[3];
  const float* qkv_wmv   = (const float*)d_in[4];
  const float* qkv_wsm   = (const float*)d_in[5];
  const float* qkv_wms   = (const float*)d_in[6];
  const float* qkv_wss   = (const float*)d_in[7];
  const float* aout_wmv  = (const float*)d_in[8];
  const float* aout_wsm  = (const float*)d_in[9];
  const float* aout_wms  = (const float*)d_in[10];
  const float* aout_wss  = (const float*)d_in[11];
  const float* m1_wmv    = (const float*)d_in[12];
  const float* m1_wsm    = (const float*)d_in[13];
  const float* m1_wms    = (const float*)d_in[14];
  const float* m1_wss    = (const float*)d_in[15];
  const float* m2_wmv    = (const float*)d_in[16];
  const float* m2_wsm    = (const float*)d_in[17];
  const float* m2_wms    = (const float*)d_in[18];
  const float* m2_wss    = (const float*)d_in[19];
  const float* wout_mv   = (const float*)d_in[20];
  const float* wout_sm   = (const float*)d_in[21];

  const int smem_qkv = (16*352 + 16*864) * 4;                    // 77824
  const int smem_blk = (16*352 + 16*288 + 16*352 + 16*608) * 4;  // 102400
  cudaFuncSetAttribute((const void*)qkv_kernel,
                       cudaFuncAttributeMaxDynamicSharedMemorySize, smem_qkv);
  cudaFuncSetAttribute((const void*)block2_kernel,
                       cudaFuncAttributeMaxDynamicSharedMemorySize, smem_blk);

  embed_kernel<<<(NTOK*48 + 255)/256, 256>>>(inputs, win_mv, win_bs);

  for (int l = 0; l < 8; l++){
    qkv_kernel<<<NTOK/16, 864, smem_qkv>>>(
        qkv_wmv + (size_t)l*48*16*9, qkv_wsm + (size_t)l*48*32,
        qkv_wms + (size_t)l*96*16,   qkv_wss + (size_t)l*96*32);
    attn_kernel<<<dim3(64, NSEQ/256), 128>>>();
    block2_kernel<<<NTOK/16, 576, smem_blk>>>(
        aout_wmv + (size_t)l*16*16*9, aout_wsm + (size_t)l*16*32,
        aout_wms + (size_t)l*32*16,   aout_wss + (size_t)l*32*32,
        m1_wmv  + (size_t)l*32*16*9,  m1_wsm  + (size_t)l*32*32,
        m1_wms  + (size_t)l*64*16,    m1_wss  + (size_t)l*64*32,
        m2_wmv  + (size_t)l*16*16*9,  m2_wsm  + (size_t)l*16*32,
        m2_wms  + (size_t)l*32*16,    m2_wss  + (size_t)l*32*32);
  }

  final_kernel<<<NBAT, 256>>>(wout_mv, wout_sm, (float*)d_out);
}

// round 8
// speedup vs baseline: 1.4188x; 1.0128x over previous
#include <cuda_runtime.h>
#include <math.h>

#define NTOK 8192
#define NSEQ 1024
#define NBAT 8

typedef unsigned long long u64;

// ---------------- f32x2 packed helpers (Blackwell) ----------------
__device__ __forceinline__ u64 pack2f(float lo, float hi){
  u64 r; asm("mov.b64 %0, {%1, %2};" : "=l"(r) : "f"(lo), "f"(hi)); return r;
}
__device__ __forceinline__ u64 ffma2(u64 a, u64 b, u64 c){
  u64 d; asm("fma.rn.f32x2 %0, %1, %2, %3;" : "=l"(d) : "l"(a), "l"(b), "l"(c)); return d;
}
__device__ __forceinline__ u64 fmul2(u64 a, u64 b){
  u64 d; asm("mul.rn.f32x2 %0, %1, %2;" : "=l"(d) : "l"(a), "l"(b)); return d;
}
__device__ __forceinline__ u64 fadd2(u64 a, u64 b){
  u64 d; asm("add.rn.f32x2 %0, %1, %2;" : "=l"(d) : "l"(a), "l"(b)); return d;
}
__device__ __forceinline__ float hadd2(u64 v){
  float a,b; asm("mov.b64 {%0, %1}, %2;" : "=f"(a), "=f"(b) : "l"(v)); return a+b;
}
// ---------------- cp.async helpers ----------------
__device__ __forceinline__ void cpa16(void* s, const void* g){
  unsigned sa = (unsigned)__cvta_generic_to_shared(s);
  asm volatile("cp.async.cg.shared.global [%0], [%1], 16;" :: "r"(sa), "l"(g));
}
__device__ __forceinline__ void cpa_commit(){ asm volatile("cp.async.commit_group;"); }
__device__ __forceinline__ void cpa_wait0(){ asm volatile("cp.async.wait_group 0;"); }

// ---------------- device scratch ----------------
__device__ float g_mv [NTOK*256];
__device__ float g_s  [NTOK*32];
__device__ float g_Q[(size_t)64*NSEQ*20];
__device__ float g_K[(size_t)64*NSEQ*20];
__device__ float g_V[(size_t)64*NSEQ*36];
__device__ float g_O[(size_t)NTOK*288];     // token-major: [tok][h][36]

// ---------------- blade tables ----------------
__constant__ int   c_kdiag[16] = {0,1,1,1,1,2,2,2,2,2,2,3,3,3,3,4};
__constant__ int   c_pair [16] = {-1,0,-1,-1,-1,2,3,4,-1,-1,-1,8,9,10,-1,14};
__constant__ int   c_koff [16] = {0,5,0,0,0,6,6,6,0,0,0,7,7,7,0,8};
__constant__ float c_inner[16] = {1,0,1,1,1,0,0,0,1,1,1,0,0,0,1,0};
__constant__ int   c_iblades[8]= {0,2,3,4,8,9,10,14};

// compile-time blade algebra (geometric product)
__host__ __device__ constexpr int blade_mask(int i){
  return i==0?0: i==1?1: i==2?2: i==3?4: i==4?8: i==5?3: i==6?5: i==7?9:
         i==8?6: i==9?10: i==10?12: i==11?7: i==12?11: i==13?13: i==14?14: 15;
}
__host__ __device__ constexpr int mask_idx(int m){
  return m==0?0: m==1?1: m==2?2: m==3?5: m==4?3: m==5?6: m==6?8: m==7?11:
         m==8?4: m==9?7: m==10?9: m==11?12: m==12?10: m==13?13: m==14?14: 15;
}
__host__ __device__ constexpr int pc4(int v){ return (v&1)+((v>>1)&1)+((v>>2)&1)+((v>>3)&1); }
__host__ __device__ constexpr int gp_par(int ma,int mb){
  return ( ((mb&1)?pc4(ma>>1):0) + (((mb>>1)&1)?pc4(ma>>2):0) + (((mb>>2)&1)?pc4(ma>>3):0) ) & 1;
}
template<int I,int J>
__device__ __forceinline__ void gp_term(float (&acc)[16], const float* x, const float* y){
  constexpr int ma = blade_mask(I);
  constexpr int mb = blade_mask(J);
  if constexpr (!(ma & mb & 1)) {
    constexpr int k  = mask_idx(ma ^ mb);
    constexpr int sg = gp_par(ma, mb);
    float p = x[I]*y[J];
    if constexpr (sg) acc[k] -= p; else acc[k] += p;
  }
}
#define GP_ROW(I) \
  gp_term<I,0>(acc,x,y);  gp_term<I,1>(acc,x,y);  gp_term<I,2>(acc,x,y);  gp_term<I,3>(acc,x,y); \
  gp_term<I,4>(acc,x,y);  gp_term<I,5>(acc,x,y);  gp_term<I,6>(acc,x,y);  gp_term<I,7>(acc,x,y); \
  gp_term<I,8>(acc,x,y);  gp_term<I,9>(acc,x,y);  gp_term<I,10>(acc,x,y); gp_term<I,11>(acc,x,y);\
  gp_term<I,12>(acc,x,y); gp_term<I,13>(acc,x,y); gp_term<I,14>(acc,x,y); gp_term<I,15>(acc,x,y);

__device__ __forceinline__ float gelu_f(float v){
  float v3 = v*v*v;
  return 0.5f*v*(1.f + tanhf(0.7978845608028654f*(v + 0.044715f*v3)));
}

// ---- equi building blocks: TWO tokens per call (8-way ILP) ----
__device__ __forceinline__ void load_wmv_row(const float* wmv, int o, int kd, int ko, int pr,
                                             u64* wd2, u64* wp2){
  #pragma unroll
  for(int i=0;i<8;i++)
    wd2[i] = pack2f(wmv[o*144 + (2*i)*9 + kd], wmv[o*144 + (2*i+1)*9 + kd]);
  if (pr >= 0){
    #pragma unroll
    for(int i=0;i<8;i++)
      wp2[i] = pack2f(wmv[o*144 + (2*i)*9 + ko], wmv[o*144 + (2*i+1)*9 + ko]);
  }
}
__device__ __forceinline__ void equi_mv_val2(const float* X0, const float* X1, int a, int pr,
    const u64* wd2, const u64* wp2, const u64* wsm2, float& r0, float& r1){
  const u64* A0 = (const u64*)(X0 + a*20);
  const u64* A1 = (const u64*)(X1 + a*20);
  u64 p0 = fmul2(wd2[0], A0[0]), p1 = fmul2(wd2[1], A0[1]);
  u64 q0 = fmul2(wd2[0], A1[0]), q1 = fmul2(wd2[1], A1[1]);
  #pragma unroll
  for(int c=2;c<8;c+=2){
    p0 = ffma2(wd2[c],A0[c],p0); p1 = ffma2(wd2[c+1],A0[c+1],p1);
    q0 = ffma2(wd2[c],A1[c],q0); q1 = ffma2(wd2[c+1],A1[c+1],q1);
  }
  if (pr >= 0){
    const u64* B0 = (const u64*)(X0 + pr*20);
    const u64* B1 = (const u64*)(X1 + pr*20);
    #pragma unroll
    for(int c=0;c<8;c+=2){
      p0 = ffma2(wp2[c],B0[c],p0); p1 = ffma2(wp2[c+1],B0[c+1],p1);
      q0 = ffma2(wp2[c],B1[c],q0); q1 = ffma2(wp2[c+1],B1[c+1],q1);
    }
  }
  if (a == 0){
    const u64* S0 = (const u64*)(X0 + 320);
    const u64* S1 = (const u64*)(X1 + 320);
    #pragma unroll
    for(int c=0;c<16;c+=2){
      p0 = ffma2(wsm2[c],S0[c],p0); p1 = ffma2(wsm2[c+1],S0[c+1],p1);
      q0 = ffma2(wsm2[c],S1[c],q0); q1 = ffma2(wsm2[c+1],S1[c+1],q1);
    }
  }
  r0 = hadd2(fadd2(p0, p1));
  r1 = hadd2(fadd2(q0, q1));
}
__device__ __forceinline__ void equi_s_val2(const float* X0, const float* X1,
    const u64* wss2, const u64* wms2, float& r0, float& r1){
  const u64* S0 = (const u64*)(X0 + 320);
  const u64* S1 = (const u64*)(X1 + 320);
  u64 p0 = fmul2(wss2[0], S0[0]), p1 = fmul2(wss2[1], S0[1]);
  u64 q0 = fmul2(wss2[0], S1[0]), q1 = fmul2(wss2[1], S1[1]);
  #pragma unroll
  for(int c=2;c<16;c+=2){
    p0 = ffma2(wss2[c],S0[c],p0); p1 = ffma2(wss2[c+1],S0[c+1],p1);
    q0 = ffma2(wss2[c],S1[c],q0); q1 = ffma2(wss2[c+1],S1[c+1],q1);
  }
  const u64* Z0 = (const u64*)(X0);
  const u64* Z1 = (const u64*)(X1);
  #pragma unroll
  for(int c=0;c<8;c+=2){
    p0 = ffma2(wms2[c],Z0[c],p0); p1 = ffma2(wms2[c+1],Z0[c+1],p1);
    q0 = ffma2(wms2[c],Z1[c],q0); q1 = ffma2(wms2[c+1],Z1[c+1],q1);
  }
  r0 = hadd2(fadd2(p0, p1));
  r1 = hadd2(fadd2(q0, q1));
}

// ---------------- embed ----------------
__global__ void embed_kernel(const float* __restrict__ inp,
                             const float* __restrict__ win_mv,
                             const float* __restrict__ win_bs){
  int idx = blockIdx.x*blockDim.x + threadIdx.x;
  if (idx < NTOK*16){
    int t = idx>>4, o = idx&15;
    float x = inp[t*3+0], y = inp[t*3+1], z = inp[t*3+2];
    float w3 = win_mv[o*9+3], w8 = win_mv[o*9+8];
    float* M = g_mv + (size_t)t*256 + o*16;
    #pragma unroll
    for(int a=0;a<16;a++) M[a]=0.f;
    M[11] = -z*w3;  M[12] = y*w3;  M[13] = -x*w3;  M[14] = w3;  M[15] = w8;
  } else if (idx < NTOK*16 + NTOK*32){
    int r = idx - NTOK*16; int t = r>>5, j = r&31;
    g_s[t*32+j] = win_bs[j];
  }
}

// ---------------- LN + QKV equi, staged coalesced pack ----------------
__global__ void __launch_bounds__(864) qkv_kernel(
    const float* __restrict__ wmv, const float* __restrict__ wsm,
    const float* __restrict__ wms, const float* __restrict__ wss)
{
  constexpr int T = 16, NT = 864;
  extern __shared__ float sm[];
  float* SX = sm;            // T*352
  float* SY = sm + T*352;    // T*864
  const int tid = threadIdx.x;
  const size_t t0 = (size_t)blockIdx.x * T;
  const int b = (int)(t0 >> 10), n0 = (int)(t0 & 1023);

  for(int idx=tid; idx<T*256; idx+=NT){
    int t = idx>>8, r = idx&255, i = r>>4, a = r&15;
    SX[t*352 + a*20 + i] = g_mv[(t0+t)*256 + r];
  }
  for(int idx=tid; idx<T*32; idx+=NT){
    int t = idx>>5, j = idx&31;
    SX[t*352 + 320 + j] = g_s[(t0+t)*32 + j];
  }
  __syncthreads();

  { // LN: warp w -> token w
    int w = tid>>5, lane = tid&31;
    if (w < T){
      float* X = SX + w*352;
      int a = lane>>1;
      int base = a*20 + (lane&1)*8;
      float msk = c_inner[a];
      float ss = 0.f;
      #pragma unroll
      for(int r=0;r<8;r++){ float v = X[base+r]; ss += v*v*msk; }
      #pragma unroll
      for(int off=16;off;off>>=1) ss += __shfl_xor_sync(0xffffffffu, ss, off);
      float sc = rsqrtf(ss*0.0625f + 1e-6f);
      #pragma unroll
      for(int r=0;r<8;r++) X[base+r] *= sc;
      float v = X[320+lane];
      float s2 = v*v;
      #pragma unroll
      for(int off=16;off;off>>=1) s2 += __shfl_xor_sync(0xffffffffu, s2, off);
      X[320+lane] = v * rsqrtf(s2*0.03125f + 1e-6f);
    }
  }
  __syncthreads();

  if (tid < 768){
    int o = tid % 48, a = tid / 48;
    int kd = c_kdiag[a], pr = c_pair[a], ko = c_koff[a];
    u64 wd2[8], wp2[8], wsm2[16];
    load_wmv_row(wmv, o, kd, ko, pr, wd2, wp2);
    if (a == 0){
      #pragma unroll
      for(int j=0;j<16;j++) wsm2[j] = pack2f(wsm[o*32+2*j], wsm[o*32+2*j+1]);
    }
    for(int t=0; t<T; t+=2){
      float r0, r1;
      equi_mv_val2(SX + t*352, SX + (t+1)*352, a, pr, wd2, wp2, wsm2, r0, r1);
      SY[t*864 + a*48 + o] = r0;
      SY[(t+1)*864 + a*48 + o] = r1;
    }
  } else {
    int o = tid - 768;  // 0..95
    u64 wss2[16], wms2[8];
    #pragma unroll
    for(int j=0;j<16;j++) wss2[j] = pack2f(wss[o*32+2*j], wss[o*32+2*j+1]);
    #pragma unroll
    for(int i=0;i<8;i++)  wms2[i] = pack2f(wms[o*16+2*i], wms[o*16+2*i+1]);
    for(int t=0; t<T; t+=2){
      float r0, r1;
      equi_s_val2(SX + t*352, SX + (t+1)*352, wss2, wms2, r0, r1);
      SY[t*864 + 768 + o] = r0;
      SY[(t+1)*864 + 768 + o] = r1;
    }
  }
  __syncthreads();

  for(int idx=tid; idx<8*T*20; idx+=NT){           // Q
    int h = idx/(T*20), rem = idx%(T*20), t = rem/20, e = rem%20;
    float v;
    if (e < 16){ int ci=e>>3, ib=e&7, a=c_iblades[ib]; v = SY[t*864 + a*48 + (h*2+ci)]; }
    else       { v = SY[t*864 + 768 + h*4 + (e-16)]; }
    g_Q[((size_t)(b*8+h)*NSEQ + n0 + t)*20 + e] = v;
  }
  for(int idx=tid; idx<8*T*20; idx+=NT){           // K
    int h = idx/(T*20), rem = idx%(T*20), t = rem/20, e = rem%20;
    float v;
    if (e < 16){ int ci=e>>3, ib=e&7, a=c_iblades[ib]; v = SY[t*864 + a*48 + (16 + h*2+ci)]; }
    else       { v = SY[t*864 + 768 + 32 + h*4 + (e-16)]; }
    g_K[((size_t)(b*8+h)*NSEQ + n0 + t)*20 + e] = v;
  }
  for(int idx=tid; idx<8*T*36; idx+=NT){           // V
    int h = idx/(T*36), rem = idx%(T*36), t = rem/36, e = rem%36;
    float v;
    if (e < 32){ int ci=e>>4, a=e&15; v = SY[t*864 + a*48 + (32 + h*2+ci)]; }
    else       { v = SY[t*864 + 768 + 64 + h*4 + (e-32)]; }
    g_V[((size_t)(b*8+h)*NSEQ + n0 + t)*36 + e] = v;
  }
}

// ---------------- attention (2 q/thread, f32x2, cp.async double buffer) ----
__global__ void __launch_bounds__(128) attn_kernel(){
  const int bh = blockIdx.x, qt = blockIdx.y, tid = threadIdx.x;
  const int b = bh>>3, h = bh&7;
  const int qi0 = qt*256 + tid;
  const float SCALE = 0.22360679774997896f;  // 1/sqrt(20)

  extern __shared__ float4 dyn4[];
  float4* sk4 = dyn4;            // 2 x 640
  float4* sv4 = dyn4 + 1280;     // 2 x 1152

  u64 q0[10], q1[10];
  {
    const float* qp0 = g_Q + ((size_t)bh*NSEQ + qi0)*20;
    const float* qp1 = qp0 + 128*20;
    #pragma unroll
    for(int c=0;c<10;c++){
      q0[c] = pack2f(qp0[2*c]*SCALE, qp0[2*c+1]*SCALE);
      q1[c] = pack2f(qp1[2*c]*SCALE, qp1[2*c+1]*SCALE);
    }
  }
  float m0=-1e30f, l0=0.f, m1=-1e30f, l1=0.f;
  u64 a0[18], a1[18];
  #pragma unroll
  for(int c=0;c<18;c++){ a0[c]=0ull; a1[c]=0ull; }

  const float4* kp = (const float4*)(g_K + (size_t)bh*NSEQ*20);
  const float4* vp = (const float4*)(g_V + (size_t)bh*NSEQ*36);

  // preload tile 0
  #pragma unroll
  for(int i=0;i<5;i++) cpa16(&sk4[tid + 128*i], &kp[tid + 128*i]);
  #pragma unroll
  for(int i=0;i<9;i++) cpa16(&sv4[tid + 128*i], &vp[tid + 128*i]);
  cpa_commit();
  cpa_wait0();
  __syncthreads();

  for(int kt=0; kt<8; kt++){
    const int cur = kt & 1, nxt = cur ^ 1;
    if (kt < 7){
      const float4* kpn = kp + (kt+1)*128*5;
      const float4* vpn = vp + (kt+1)*128*9;
      #pragma unroll
      for(int i=0;i<5;i++) cpa16(&sk4[nxt*640 + tid + 128*i], &kpn[tid + 128*i]);
      #pragma unroll
      for(int i=0;i<9;i++) cpa16(&sv4[nxt*1152 + tid + 128*i], &vpn[tid + 128*i]);
      cpa_commit();
    }
    const float4* skc = sk4 + cur*640;
    const float4* svc = sv4 + cur*1152;

    for(int j=0; j<128; j++){
      const u64* kk = (const u64*)(skc + j*5);
      const u64* vv = (const u64*)(svc + j*9);
      u64 t0a = fmul2(q0[0], kk[0]), t0b = fmul2(q0[1], kk[1]);
      u64 t1a = fmul2(q1[0], kk[0]), t1b = fmul2(q1[1], kk[1]);
      #pragma unroll
      for(int c=2;c<10;c+=2){
        t0a = ffma2(q0[c], kk[c], t0a);  t0b = ffma2(q0[c+1], kk[c+1], t0b);
        t1a = ffma2(q1[c], kk[c], t1a);  t1b = ffma2(q1[c+1], kk[c+1], t1b);
      }
      float s0 = hadd2(fadd2(t0a, t0b));
      float s1 = hadd2(fadd2(t1a, t1b));
      float p0, p1;
      if (s0 > m0){
        float cc = __expf(m0 - s0); m0 = s0; l0 = l0*cc + 1.f;
        u64 cp = pack2f(cc, cc);
        #pragma unroll
        for(int c=0;c<18;c++) a0[c] = fmul2(a0[c], cp);
        p0 = 1.f;
      } else { p0 = __expf(s0 - m0); l0 += p0; }
      if (s1 > m1){
        float cc = __expf(m1 - s1); m1 = s1; l1 = l1*cc + 1.f;
        u64 cp = pack2f(cc, cc);
        #pragma unroll
        for(int c=0;c<18;c++) a1[c] = fmul2(a1[c], cp);
        p1 = 1.f;
      } else { p1 = __expf(s1 - m1); l1 += p1; }
      u64 pp0 = pack2f(p0, p0), pp1 = pack2f(p1, p1);
      #pragma unroll
      for(int c=0;c<18;c++){
        a0[c] = ffma2(pp0, vv[c], a0[c]);
        a1[c] = ffma2(pp1, vv[c], a1[c]);
      }
    }
    if (kt < 7){
      cpa_wait0();
      __syncthreads();
    }
  }
  u64 i0 = pack2f(1.f/l0, 1.f/l0), i1 = pack2f(1.f/l1, 1.f/l1);
  size_t tok0 = (size_t)b*NSEQ + qi0;
  u64* op0 = (u64*)(g_O + (tok0*8 + h)*36);
  u64* op1 = (u64*)(g_O + ((tok0+128)*8 + h)*36);
  #pragma unroll
  for(int c=0;c<18;c++){
    op0[c] = fmul2(a0[c], i0);
    op1[c] = fmul2(a1[c], i1);
  }
}

// ---------------- fused: out-proj + res + LN + mlp1 + GP + mlp2 + res ----
__global__ void __launch_bounds__(576) block2_kernel(
    const float* __restrict__ ao_wmv, const float* __restrict__ ao_wsm,
    const float* __restrict__ ao_wms, const float* __restrict__ ao_wss,
    const float* __restrict__ m1_wmv, const float* __restrict__ m1_wsm,
    const float* __restrict__ m1_wms, const float* __restrict__ m1_wss,
    const float* __restrict__ m2_wmv, const float* __restrict__ m2_wsm,
    const float* __restrict__ m2_wms, const float* __restrict__ m2_wss)
{
  constexpr int T = 16, NT = 576;
  extern __shared__ float sm[];
  float* SA  = sm;             // T*352  attn-out (blade-major); later reused as SX2
  float* SR  = SA + T*352;     // T*288  residual
  float* SH  = SR + T*288;     // T*608  mlp1 hidden
  float* SX2 = SA;             // alias: SA dead after stage 2
  const int tid = threadIdx.x;
  const size_t t0 = (size_t)blockIdx.x * T;

  // ---- stage 1: load attn-out (coalesced) + residual ----
  for(int idx=tid; idx<T*288; idx+=NT){
    int t = idx/288, r = idx%288;
    float v = g_O[(t0+t)*288 + r];
    int h = r/36, e = r%36;
    if (e < 32){ int ci=e>>4, a=e&15; SA[t*352 + a*20 + (h*2+ci)] = v; }
    else       { SA[t*352 + 320 + h*4 + (e-32)] = v; }
  }
  for(int idx=tid; idx<T*256; idx+=NT){
    int t = idx>>8, r = idx&255;
    SR[t*288 + r] = g_mv[(t0+t)*256 + r];
  }
  for(int idx=tid; idx<T*32; idx+=NT){
    int t = idx>>5, j = idx&31;
    SR[t*288 + 256 + j] = g_s[(t0+t)*32 + j];
  }
  __syncthreads();

  // ---- stage 2: out-projection equi + residual add into SR ----
  {
    int out = tid % 288, tp = tid / 288;   // tp in {0,1}
    if (out < 256){
      int o = out & 15, a = out >> 4;
      int kd = c_kdiag[a], pr = c_pair[a], ko = c_koff[a];
      u64 wd2[8], wp2[8], wsm2[16];
      load_wmv_row(ao_wmv, o, kd, ko, pr, wd2, wp2);
      if (a == 0){
        #pragma unroll
        for(int j=0;j<16;j++) wsm2[j] = pack2f(ao_wsm[o*32+2*j], ao_wsm[o*32+2*j+1]);
      }
      #pragma unroll
      for(int tt=0; tt<4; tt++){
        int t = tp + tt*4;
        float r0, r1;
        equi_mv_val2(SA + t*352, SA + (t+2)*352, a, pr, wd2, wp2, wsm2, r0, r1);
        SR[t*288 + o*16 + a] += r0;
        SR[(t+2)*288 + o*16 + a] += r1;
      }
    } else {
      int o = out - 256;
      u64 wss2[16], wms2[8];
      #pragma unroll
      for(int j=0;j<16;j++) wss2[j] = pack2f(ao_wss[o*32+2*j], ao_wss[o*32+2*j+1]);
      #pragma unroll
      for(int i=0;i<8;i++)  wms2[i] = pack2f(ao_wms[o*16+2*i], ao_wms[o*16+2*i+1]);
      #pragma unroll
      for(int tt=0; tt<4; tt++){
        int t = tp + tt*4;
        float r0, r1;
        equi_s_val2(SA + t*352, SA + (t+2)*352, wss2, wms2, r0, r1);
        SR[t*288 + 256 + o] += r0;
        SR[(t+2)*288 + 256 + o] += r1;
      }
    }
  }
  __syncthreads();

  // ---- stage 3: LN(SR) -> SX2 (blade-major; aliases SA) ----
  {
    int w = tid>>5, lane = tid&31;
    if (w < T){
      const float* R = SR + w*288;
      float ss = 0.f;
      #pragma unroll
      for(int r=0;r<8;r++){ int li = lane + 32*r; float v = R[li]; ss += v*v*c_inner[li&15]; }
      #pragma unroll
      for(int off=16;off;off>>=1) ss += __shfl_xor_sync(0xffffffffu, ss, off);
      float sc = rsqrtf(ss*0.0625f + 1e-6f);
      #pragma unroll
      for(int r=0;r<8;r++){
        int li = lane + 32*r; int o = li>>4, a = li&15;
        SX2[w*352 + a*20 + o] = R[li]*sc;
      }
      float v = R[256+lane];
      float s2 = v*v;
      #pragma unroll
      for(int off=16;off;off>>=1) s2 += __shfl_xor_sync(0xffffffffu, s2, off);
      SX2[w*352 + 320 + lane] = v * rsqrtf(s2*0.03125f + 1e-6f);
    }
  }
  __syncthreads();

  // ---- stage 4: mlp1 equi (32 mv ch + 64 s) -> SH ----
  if (tid < 512){
    int o = tid % 32, a = tid / 32;
    int kd = c_kdiag[a], pr = c_pair[a], ko = c_koff[a];
    u64 wd2[8], wp2[8], wsm2[16];
    load_wmv_row(m1_wmv, o, kd, ko, pr, wd2, wp2);
    if (a == 0){
      #pragma unroll
      for(int j=0;j<16;j++) wsm2[j] = pack2f(m1_wsm[o*32+2*j], m1_wsm[o*32+2*j+1]);
    }
    for(int t=0; t<T; t+=2){
      float r0, r1;
      equi_mv_val2(SX2 + t*352, SX2 + (t+1)*352, a, pr, wd2, wp2, wsm2, r0, r1);
      SH[t*608 + o*17 + a] = r0;
      SH[(t+1)*608 + o*17 + a] = r1;
    }
  } else {
    int o = tid - 512;  // 0..63
    u64 wss2[16], wms2[8];
    #pragma unroll
    for(int j=0;j<16;j++) wss2[j] = pack2f(m1_wss[o*32+2*j], m1_wss[o*32+2*j+1]);
    #pragma unroll
    for(int i=0;i<8;i++)  wms2[i] = pack2f(m1_wms[o*16+2*i], m1_wms[o*16+2*i+1]);
    for(int t=0; t<T; t+=2){
      float r0, r1;
      equi_s_val2(SX2 + t*352, SX2 + (t+1)*352, wss2, wms2, r0, r1);
      SH[t*608 + 544 + o] = r0;
      SH[(t+1)*608 + 544 + o] = r1;
    }
  }
  __syncthreads();

  // ---- stage 5: geometric product + gated gelu -> SX2 ----
  for(int idx=tid; idx<768; idx+=NT){
    if (idx < 256){
      int t = idx>>4, c = idx&15;
      const float* h1 = SH + t*608 + c*17;
      const float* h2 = SH + t*608 + (16+c)*17;
      float x[16], y[16], acc[16];
      #pragma unroll
      for(int i=0;i<16;i++){ x[i]=h1[i]; y[i]=h2[i]; acc[i]=0.f; }
      GP_ROW(0)  GP_ROW(1)  GP_ROW(2)  GP_ROW(3)
      GP_ROW(4)  GP_ROW(5)  GP_ROW(6)  GP_ROW(7)
      GP_ROW(8)  GP_ROW(9)  GP_ROW(10) GP_ROW(11)
      GP_ROW(12) GP_ROW(13) GP_ROW(14) GP_ROW(15)
      float g = gelu_f(acc[0]);
      #pragma unroll
      for(int a=0;a<16;a++) SX2[t*352 + a*20 + c] = acc[a]*g;
    } else {
      int r = idx - 256; int t = r>>5, j = r&31;
      const float* hs = SH + t*608 + 544;
      SX2[t*352 + 320 + j] = hs[j] * gelu_f(hs[32+j]);
    }
  }
  __syncthreads();

  // ---- stage 6: mlp2 equi + residual add into SR ----
  {
    int out = tid % 288, tp = tid / 288;
    if (out < 256){
      int o = out & 15, a = out >> 4;
      int kd = c_kdiag[a], pr = c_pair[a], ko = c_koff[a];
      u64 wd2[8], wp2[8], wsm2[16];
      load_wmv_row(m2_wmv, o, kd, ko, pr, wd2, wp2);
      if (a == 0){
        #pragma unroll
        for(int j=0;j<16;j++) wsm2[j] = pack2f(m2_wsm[o*32+2*j], m2_wsm[o*32+2*j+1]);
      }
      #pragma unroll
      for(int tt=0; tt<4; tt++){
        int t = tp + tt*4;
        float r0, r1;
        equi_mv_val2(SX2 + t*352, SX2 + (t+2)*352, a, pr, wd2, wp2, wsm2, r0, r1);
        SR[t*288 + o*16 + a] += r0;
        SR[(t+2)*288 + o*16 + a] += r1;
      }
    } else {
      int o = out - 256;
      u64 wss2[16], wms2[8];
      #pragma unroll
      for(int j=0;j<16;j++) wss2[j] = pack2f(m2_wss[o*32+2*j], m2_wss[o*32+2*j+1]);
      #pragma unroll
      for(int i=0;i<8;i++)  wms2[i] = pack2f(m2_wms[o*16+2*i], m2_wms[o*16+2*i+1]);
      #pragma unroll
      for(int tt=0; tt<4; tt++){
        int t = tp + tt*4;
        float r0, r1;
        equi_s_val2(SX2 + t*352, SX2 + (t+2)*352, wss2, wms2, r0, r1);
        SR[t*288 + 256 + o] += r0;
        SR[(t+2)*288 + 256 + o] += r1;
      }
    }
  }
  __syncthreads();

  // ---- stage 7: store residual (coalesced float4) ----
  for(int idx=tid; idx<T*64; idx+=NT){
    int t = idx>>6, r4 = idx&63;
    ((float4*)(g_mv + (t0+t)*256))[r4] = ((const float4*)(SR + t*288))[r4];
  }
  for(int idx=tid; idx<T*8; idx+=NT){
    int t = idx>>3, j4 = idx&7;
    ((float4*)(g_s + (t0+t)*32))[j4] = ((const float4*)(SR + t*288 + 256))[j4];
  }
}

// ---------------- final projection + mean ----------------
__global__ void final_kernel(const float* __restrict__ wout_mv,
                             const float* __restrict__ wout_sm,
                             float* __restrict__ out){
  int b = blockIdx.x, tid = threadIdx.x;
  __shared__ float red[256];
  float acc = 0.f;
  for(int n=tid; n<NSEQ; n+=256){
    size_t t = (size_t)b*NSEQ + n;
    const float* M = g_mv + t*256;
    const float* S = g_s + t*32;
    float v = 0.f;
    #pragma unroll
    for(int i=0;i<16;i++) v += wout_mv[i*9] * M[i*16];
    #pragma unroll
    for(int j=0;j<32;j++) v += wout_sm[j] * S[j];
    acc += v;
  }
  red[tid] = acc; __syncthreads();
  for(int s=128; s; s>>=1){ if (tid < s) red[tid] += red[tid+s]; __syncthreads(); }
  if (tid == 0) out[b] = red[0] * (1.f/NSEQ);
}

// ---------------- host ----------------
extern "C" void kernel_launch(void* const* d_in, const int* in_sizes, int n_in,
                              void* d_out, int out_size) {
  const float* inputs    = (const float*)d_in[0];
  const float* win_mv    = (const float*)d_in[1];
  const float* win_bs    = (const float*)d_in[3];
  const float* qkv_wmv   = (const float*)d_in[4];
  const float* qkv_wsm   = (const float*)d_in[5];
  const float* qkv_wms   = (const float*)d_in[6];
  const float* qkv_wss   = (const float*)d_in[7];
  const float* aout_wmv  = (const float*)d_in[8];
  const float* aout_wsm  = (const float*)d_in[9];
  const float* aout_wms  = (const float*)d_in[10];
  const float* aout_wss  = (const float*)d_in[11];
  const float* m1_wmv    = (const float*)d_in[12];
  const float* m1_wsm    = (const float*)d_in[13];
  const float* m1_wms    = (const float*)d_in[14];
  const float* m1_wss    = (const float*)d_in[15];
  const float* m2_wmv    = (const float*)d_in[16];
  const float* m2_wsm    = (const float*)d_in[17];
  const float* m2_wms    = (const float*)d_in[18];
  const float* m2_wss    = (const float*)d_in[19];
  const float* wout_mv   = (const float*)d_in[20];
  const float* wout_sm   = (const float*)d_in[21];

  const int smem_qkv  = (16*352 + 16*864) * 4;             // 77824
  const int smem_blk  = (16*352 + 16*288 + 16*608) * 4;    // 79872
  const int smem_attn = (2*640 + 2*1152) * 16;             // 57344
  cudaFuncSetAttribute((const void*)qkv_kernel,
                       cudaFuncAttributeMaxDynamicSharedMemorySize, smem_qkv);
  cudaFuncSetAttribute((const void*)block2_kernel,
                       cudaFuncAttributeMaxDynamicSharedMemorySize, smem_blk);
  cudaFuncSetAttribute((const void*)attn_kernel,
                       cudaFuncAttributeMaxDynamicSharedMemorySize, smem_attn);

  embed_kernel<<<(NTOK*48 + 255)/256, 256>>>(inputs, win_mv, win_bs);

  for (int l = 0; l < 8; l++){
    qkv_kernel<<<NTOK/16, 864, smem_qkv>>>(
        qkv_wmv + (size_t)l*48*16*9, qkv_wsm + (size_t)l*48*32,
        qkv_wms + (size_t)l*96*16,   qkv_wss + (size_t)l*96*32);
    attn_kernel<<<dim3(64, NSEQ/256), 128, smem_attn>>>();
    block2_kernel<<<NTOK/16, 576, smem_blk>>>(
        aout_wmv + (size_t)l*16*16*9, aout_wsm + (size_t)l*16*32,
        aout_wms + (size_t)l*32*16,   aout_wss + (size_t)l*32*32,
        m1_wmv  + (size_t)l*32*16*9,  m1_wsm  + (size_t)l*32*32,
        m1_wms  + (size_t)l*64*16,    m1_wss  + (size_t)l*64*32,
        m2_wmv  + (size_t)l*16*16*9,  m2_wsm  + (size_t)l*16*32,
        m2_wms  + (size_t)l*32*16,    m2_wss  + (size_t)l*32*32);
  }

  final_kernel<<<NBAT, 256>>>(wout_mv, wout_sm, (float*)d_out);
}

// round 9
// speedup vs baseline: 1.4347x; 1.0112x over previous
#include <cuda_runtime.h>
#include <math.h>

#define NTOK 8192
#define NSEQ 1024
#define NBAT 8

typedef unsigned long long u64;

// ---------------- f32x2 packed helpers (Blackwell) ----------------
__device__ __forceinline__ u64 pack2f(float lo, float hi){
  u64 r; asm("mov.b64 %0, {%1, %2};" : "=l"(r) : "f"(lo), "f"(hi)); return r;
}
__device__ __forceinline__ u64 ffma2(u64 a, u64 b, u64 c){
  u64 d; asm("fma.rn.f32x2 %0, %1, %2, %3;" : "=l"(d) : "l"(a), "l"(b), "l"(c)); return d;
}
__device__ __forceinline__ u64 fmul2(u64 a, u64 b){
  u64 d; asm("mul.rn.f32x2 %0, %1, %2;" : "=l"(d) : "l"(a), "l"(b)); return d;
}
__device__ __forceinline__ u64 fadd2(u64 a, u64 b){
  u64 d; asm("add.rn.f32x2 %0, %1, %2;" : "=l"(d) : "l"(a), "l"(b)); return d;
}
__device__ __forceinline__ float hadd2(u64 v){
  float a,b; asm("mov.b64 {%0, %1}, %2;" : "=f"(a), "=f"(b) : "l"(v)); return a+b;
}
// ---------------- cp.async helpers ----------------
__device__ __forceinline__ void cpa16(void* s, const void* g){
  unsigned sa = (unsigned)__cvta_generic_to_shared(s);
  asm volatile("cp.async.cg.shared.global [%0], [%1], 16;" :: "r"(sa), "l"(g));
}
__device__ __forceinline__ void cpa_commit(){ asm volatile("cp.async.commit_group;"); }
__device__ __forceinline__ void cpa_wait0(){ asm volatile("cp.async.wait_group 0;"); }

// ---------------- device scratch ----------------
__device__ float g_mv [NTOK*256];
__device__ float g_s  [NTOK*32];
__device__ float g_Q[(size_t)64*NSEQ*20];
__device__ float g_K[(size_t)64*NSEQ*20];
__device__ float g_V[(size_t)64*NSEQ*36];
__device__ float g_O[(size_t)NTOK*288];              // token-major: [tok][h][36]
__device__ float g_Osp[(size_t)64*NSEQ*2*38];        // [bh][n][split][36 acc + m + l]

// ---------------- blade tables ----------------
__constant__ int   c_kdiag[16] = {0,1,1,1,1,2,2,2,2,2,2,3,3,3,3,4};
__constant__ int   c_pair [16] = {-1,0,-1,-1,-1,2,3,4,-1,-1,-1,8,9,10,-1,14};
__constant__ int   c_koff [16] = {0,5,0,0,0,6,6,6,0,0,0,7,7,7,0,8};
__constant__ float c_inner[16] = {1,0,1,1,1,0,0,0,1,1,1,0,0,0,1,0};
__constant__ int   c_iblades[8]= {0,2,3,4,8,9,10,14};

// compile-time blade algebra (geometric product)
__host__ __device__ constexpr int blade_mask(int i){
  return i==0?0: i==1?1: i==2?2: i==3?4: i==4?8: i==5?3: i==6?5: i==7?9:
         i==8?6: i==9?10: i==10?12: i==11?7: i==12?11: i==13?13: i==14?14: 15;
}
__host__ __device__ constexpr int mask_idx(int m){
  return m==0?0: m==1?1: m==2?2: m==3?5: m==4?3: m==5?6: m==6?8: m==7?11:
         m==8?4: m==9?7: m==10?9: m==11?12: m==12?10: m==13?13: m==14?14: 15;
}
__host__ __device__ constexpr int pc4(int v){ return (v&1)+((v>>1)&1)+((v>>2)&1)+((v>>3)&1); }
__host__ __device__ constexpr int gp_par(int ma,int mb){
  return ( ((mb&1)?pc4(ma>>1):0) + (((mb>>1)&1)?pc4(ma>>2):0) + (((mb>>2)&1)?pc4(ma>>3):0) ) & 1;
}
template<int I,int J>
__device__ __forceinline__ void gp_term(float (&acc)[16], const float* x, const float* y){
  constexpr int ma = blade_mask(I);
  constexpr int mb = blade_mask(J);
  if constexpr (!(ma & mb & 1)) {
    constexpr int k  = mask_idx(ma ^ mb);
    constexpr int sg = gp_par(ma, mb);
    float p = x[I]*y[J];
    if constexpr (sg) acc[k] -= p; else acc[k] += p;
  }
}
#define GP_ROW(I) \
  gp_term<I,0>(acc,x,y);  gp_term<I,1>(acc,x,y);  gp_term<I,2>(acc,x,y);  gp_term<I,3>(acc,x,y); \
  gp_term<I,4>(acc,x,y);  gp_term<I,5>(acc,x,y);  gp_term<I,6>(acc,x,y);  gp_term<I,7>(acc,x,y); \
  gp_term<I,8>(acc,x,y);  gp_term<I,9>(acc,x,y);  gp_term<I,10>(acc,x,y); gp_term<I,11>(acc,x,y);\
  gp_term<I,12>(acc,x,y); gp_term<I,13>(acc,x,y); gp_term<I,14>(acc,x,y); gp_term<I,15>(acc,x,y);

__device__ __forceinline__ float gelu_f(float v){
  float v3 = v*v*v;
  return 0.5f*v*(1.f + tanhf(0.7978845608028654f*(v + 0.044715f*v3)));
}

// ---- equi building blocks: TWO tokens per call (8-way ILP) ----
__device__ __forceinline__ void load_wmv_row(const float* wmv, int o, int kd, int ko, int pr,
                                             u64* wd2, u64* wp2){
  #pragma unroll
  for(int i=0;i<8;i++)
    wd2[i] = pack2f(wmv[o*144 + (2*i)*9 + kd], wmv[o*144 + (2*i+1)*9 + kd]);
  if (pr >= 0){
    #pragma unroll
    for(int i=0;i<8;i++)
      wp2[i] = pack2f(wmv[o*144 + (2*i)*9 + ko], wmv[o*144 + (2*i+1)*9 + ko]);
  }
}
__device__ __forceinline__ void equi_mv_val2(const float* X0, const float* X1, int a, int pr,
    const u64* wd2, const u64* wp2, const u64* wsm2, float& r0, float& r1){
  const u64* A0 = (const u64*)(X0 + a*20);
  const u64* A1 = (const u64*)(X1 + a*20);
  u64 p0 = fmul2(wd2[0], A0[0]), p1 = fmul2(wd2[1], A0[1]);
  u64 q0 = fmul2(wd2[0], A1[0]), q1 = fmul2(wd2[1], A1[1]);
  #pragma unroll
  for(int c=2;c<8;c+=2){
    p0 = ffma2(wd2[c],A0[c],p0); p1 = ffma2(wd2[c+1],A0[c+1],p1);
    q0 = ffma2(wd2[c],A1[c],q0); q1 = ffma2(wd2[c+1],A1[c+1],q1);
  }
  if (pr >= 0){
    const u64* B0 = (const u64*)(X0 + pr*20);
    const u64* B1 = (const u64*)(X1 + pr*20);
    #pragma unroll
    for(int c=0;c<8;c+=2){
      p0 = ffma2(wp2[c],B0[c],p0); p1 = ffma2(wp2[c+1],B0[c+1],p1);
      q0 = ffma2(wp2[c],B1[c],q0); q1 = ffma2(wp2[c+1],B1[c+1],q1);
    }
  }
  if (a == 0){
    const u64* S0 = (const u64*)(X0 + 320);
    const u64* S1 = (const u64*)(X1 + 320);
    #pragma unroll
    for(int c=0;c<16;c+=2){
      p0 = ffma2(wsm2[c],S0[c],p0); p1 = ffma2(wsm2[c+1],S0[c+1],p1);
      q0 = ffma2(wsm2[c],S1[c],q0); q1 = ffma2(wsm2[c+1],S1[c+1],q1);
    }
  }
  r0 = hadd2(fadd2(p0, p1));
  r1 = hadd2(fadd2(q0, q1));
}
__device__ __forceinline__ void equi_s_val2(const float* X0, const float* X1,
    const u64* wss2, const u64* wms2, float& r0, float& r1){
  const u64* S0 = (const u64*)(X0 + 320);
  const u64* S1 = (const u64*)(X1 + 320);
  u64 p0 = fmul2(wss2[0], S0[0]), p1 = fmul2(wss2[1], S0[1]);
  u64 q0 = fmul2(wss2[0], S1[0]), q1 = fmul2(wss2[1], S1[1]);
  #pragma unroll
  for(int c=2;c<16;c+=2){
    p0 = ffma2(wss2[c],S0[c],p0); p1 = ffma2(wss2[c+1],S0[c+1],p1);
    q0 = ffma2(wss2[c],S1[c],q0); q1 = ffma2(wss2[c+1],S1[c+1],q1);
  }
  const u64* Z0 = (const u64*)(X0);
  const u64* Z1 = (const u64*)(X1);
  #pragma unroll
  for(int c=0;c<8;c+=2){
    p0 = ffma2(wms2[c],Z0[c],p0); p1 = ffma2(wms2[c+1],Z0[c+1],p1);
    q0 = ffma2(wms2[c],Z1[c],q0); q1 = ffma2(wms2[c+1],Z1[c+1],q1);
  }
  r0 = hadd2(fadd2(p0, p1));
  r1 = hadd2(fadd2(q0, q1));
}

// ---------------- embed ----------------
__global__ void embed_kernel(const float* __restrict__ inp,
                             const float* __restrict__ win_mv,
                             const float* __restrict__ win_bs){
  int idx = blockIdx.x*blockDim.x + threadIdx.x;
  if (idx < NTOK*16){
    int t = idx>>4, o = idx&15;
    float x = inp[t*3+0], y = inp[t*3+1], z = inp[t*3+2];
    float w3 = win_mv[o*9+3], w8 = win_mv[o*9+8];
    float* M = g_mv + (size_t)t*256 + o*16;
    #pragma unroll
    for(int a=0;a<16;a++) M[a]=0.f;
    M[11] = -z*w3;  M[12] = y*w3;  M[13] = -x*w3;  M[14] = w3;  M[15] = w8;
  } else if (idx < NTOK*16 + NTOK*32){
    int r = idx - NTOK*16; int t = r>>5, j = r&31;
    g_s[t*32+j] = win_bs[j];
  }
}

// ---------------- LN + QKV equi, staged coalesced pack ----------------
__global__ void __launch_bounds__(864) qkv_kernel(
    const float* __restrict__ wmv, const float* __restrict__ wsm,
    const float* __restrict__ wms, const float* __restrict__ wss)
{
  constexpr int T = 16, NT = 864;
  extern __shared__ float sm[];
  float* SX = sm;            // T*352
  float* SY = sm + T*352;    // T*864
  const int tid = threadIdx.x;
  const size_t t0 = (size_t)blockIdx.x * T;
  const int b = (int)(t0 >> 10), n0 = (int)(t0 & 1023);

  for(int idx=tid; idx<T*256; idx+=NT){
    int t = idx>>8, r = idx&255, i = r>>4, a = r&15;
    SX[t*352 + a*20 + i] = g_mv[(t0+t)*256 + r];
  }
  for(int idx=tid; idx<T*32; idx+=NT){
    int t = idx>>5, j = idx&31;
    SX[t*352 + 320 + j] = g_s[(t0+t)*32 + j];
  }
  __syncthreads();

  { // LN: warp w -> token w
    int w = tid>>5, lane = tid&31;
    if (w < T){
      float* X = SX + w*352;
      int a = lane>>1;
      int base = a*20 + (lane&1)*8;
      float msk = c_inner[a];
      float ss = 0.f;
      #pragma unroll
      for(int r=0;r<8;r++){ float v = X[base+r]; ss += v*v*msk; }
      #pragma unroll
      for(int off=16;off;off>>=1) ss += __shfl_xor_sync(0xffffffffu, ss, off);
      float sc = rsqrtf(ss*0.0625f + 1e-6f);
      #pragma unroll
      for(int r=0;r<8;r++) X[base+r] *= sc;
      float v = X[320+lane];
      float s2 = v*v;
      #pragma unroll
      for(int off=16;off;off>>=1) s2 += __shfl_xor_sync(0xffffffffu, s2, off);
      X[320+lane] = v * rsqrtf(s2*0.03125f + 1e-6f);
    }
  }
  __syncthreads();

  if (tid < 768){
    int o = tid % 48, a = tid / 48;
    int kd = c_kdiag[a], pr = c_pair[a], ko = c_koff[a];
    u64 wd2[8], wp2[8], wsm2[16];
    load_wmv_row(wmv, o, kd, ko, pr, wd2, wp2);
    if (a == 0){
      #pragma unroll
      for(int j=0;j<16;j++) wsm2[j] = pack2f(wsm[o*32+2*j], wsm[o*32+2*j+1]);
    }
    for(int t=0; t<T; t+=2){
      float r0, r1;
      equi_mv_val2(SX + t*352, SX + (t+1)*352, a, pr, wd2, wp2, wsm2, r0, r1);
      SY[t*864 + a*48 + o] = r0;
      SY[(t+1)*864 + a*48 + o] = r1;
    }
  } else {
    int o = tid - 768;  // 0..95
    u64 wss2[16], wms2[8];
    #pragma unroll
    for(int j=0;j<16;j++) wss2[j] = pack2f(wss[o*32+2*j], wss[o*32+2*j+1]);
    #pragma unroll
    for(int i=0;i<8;i++)  wms2[i] = pack2f(wms[o*16+2*i], wms[o*16+2*i+1]);
    for(int t=0; t<T; t+=2){
      float r0, r1;
      equi_s_val2(SX + t*352, SX + (t+1)*352, wss2, wms2, r0, r1);
      SY[t*864 + 768 + o] = r0;
      SY[(t+1)*864 + 768 + o] = r1;
    }
  }
  __syncthreads();

  for(int idx=tid; idx<8*T*20; idx+=NT){           // Q
    int h = idx/(T*20), rem = idx%(T*20), t = rem/20, e = rem%20;
    float v;
    if (e < 16){ int ci=e>>3, ib=e&7, a=c_iblades[ib]; v = SY[t*864 + a*48 + (h*2+ci)]; }
    else       { v = SY[t*864 + 768 + h*4 + (e-16)]; }
    g_Q[((size_t)(b*8+h)*NSEQ + n0 + t)*20 + e] = v;
  }
  for(int idx=tid; idx<8*T*20; idx+=NT){           // K
    int h = idx/(T*20), rem = idx%(T*20), t = rem/20, e = rem%20;
    float v;
    if (e < 16){ int ci=e>>3, ib=e&7, a=c_iblades[ib]; v = SY[t*864 + a*48 + (16 + h*2+ci)]; }
    else       { v = SY[t*864 + 768 + 32 + h*4 + (e-16)]; }
    g_K[((size_t)(b*8+h)*NSEQ + n0 + t)*20 + e] = v;
  }
  for(int idx=tid; idx<8*T*36; idx+=NT){           // V
    int h = idx/(T*36), rem = idx%(T*36), t = rem/36, e = rem%36;
    float v;
    if (e < 32){ int ci=e>>4, a=e&15; v = SY[t*864 + a*48 + (32 + h*2+ci)]; }
    else       { v = SY[t*864 + 768 + 64 + h*4 + (e-32)]; }
    g_V[((size_t)(b*8+h)*NSEQ + n0 + t)*36 + e] = v;
  }
}

// ---------------- attention (split-KV x2, 2 q/thread, f32x2) ----------------
__global__ void __launch_bounds__(128) attn_kernel(){
  const int bh = blockIdx.x, qt = blockIdx.y, z = blockIdx.z, tid = threadIdx.x;
  const int qi0 = qt*256 + tid;
  const float SCALE = 0.22360679774997896f;  // 1/sqrt(20)

  extern __shared__ float4 dyn4[];
  float4* sk4 = dyn4;            // 2 x 640
  float4* sv4 = dyn4 + 1280;     // 2 x 1152

  u64 q0[10], q1[10];
  {
    const float* qp0 = g_Q + ((size_t)bh*NSEQ + qi0)*20;
    const float* qp1 = qp0 + 128*20;
    #pragma unroll
    for(int c=0;c<10;c++){
      q0[c] = pack2f(qp0[2*c]*SCALE, qp0[2*c+1]*SCALE);
      q1[c] = pack2f(qp1[2*c]*SCALE, qp1[2*c+1]*SCALE);
    }
  }
  float m0=-1e30f, l0=0.f, m1=-1e30f, l1=0.f;
  u64 a0[18], a1[18];
  #pragma unroll
  for(int c=0;c<18;c++){ a0[c]=0ull; a1[c]=0ull; }

  const int kt0 = z*4;
  const float4* kp = (const float4*)(g_K + (size_t)bh*NSEQ*20) + kt0*128*5;
  const float4* vp = (const float4*)(g_V + (size_t)bh*NSEQ*36) + kt0*128*9;

  // preload tile 0
  #pragma unroll
  for(int i=0;i<5;i++) cpa16(&sk4[tid + 128*i], &kp[tid + 128*i]);
  #pragma unroll
  for(int i=0;i<9;i++) cpa16(&sv4[tid + 128*i], &vp[tid + 128*i]);
  cpa_commit();
  cpa_wait0();
  __syncthreads();

  for(int ki=0; ki<4; ki++){
    const int cur = ki & 1, nxt = cur ^ 1;
    if (ki < 3){
      const float4* kpn = kp + (ki+1)*128*5;
      const float4* vpn = vp + (ki+1)*128*9;
      #pragma unroll
      for(int i=0;i<5;i++) cpa16(&sk4[nxt*640 + tid + 128*i], &kpn[tid + 128*i]);
      #pragma unroll
      for(int i=0;i<9;i++) cpa16(&sv4[nxt*1152 + tid + 128*i], &vpn[tid + 128*i]);
      cpa_commit();
    }
    const float4* skc = sk4 + cur*640;
    const float4* svc = sv4 + cur*1152;

    for(int j=0; j<128; j++){
      const u64* kk = (const u64*)(skc + j*5);
      const u64* vv = (const u64*)(svc + j*9);
      u64 t0a = fmul2(q0[0], kk[0]), t0b = fmul2(q0[1], kk[1]);
      u64 t1a = fmul2(q1[0], kk[0]), t1b = fmul2(q1[1], kk[1]);
      #pragma unroll
      for(int c=2;c<10;c+=2){
        t0a = ffma2(q0[c], kk[c], t0a);  t0b = ffma2(q0[c+1], kk[c+1], t0b);
        t1a = ffma2(q1[c], kk[c], t1a);  t1b = ffma2(q1[c+1], kk[c+1], t1b);
      }
      float s0 = hadd2(fadd2(t0a, t0b));
      float s1 = hadd2(fadd2(t1a, t1b));
      float p0, p1;
      if (s0 > m0){
        float cc = __expf(m0 - s0); m0 = s0; l0 = l0*cc + 1.f;
        u64 cp = pack2f(cc, cc);
        #pragma unroll
        for(int c=0;c<18;c++) a0[c] = fmul2(a0[c], cp);
        p0 = 1.f;
      } else { p0 = __expf(s0 - m0); l0 += p0; }
      if (s1 > m1){
        float cc = __expf(m1 - s1); m1 = s1; l1 = l1*cc + 1.f;
        u64 cp = pack2f(cc, cc);
        #pragma unroll
        for(int c=0;c<18;c++) a1[c] = fmul2(a1[c], cp);
        p1 = 1.f;
      } else { p1 = __expf(s1 - m1); l1 += p1; }
      u64 pp0 = pack2f(p0, p0), pp1 = pack2f(p1, p1);
      #pragma unroll
      for(int c=0;c<18;c++){
        a0[c] = ffma2(pp0, vv[c], a0[c]);
        a1[c] = ffma2(pp1, vv[c], a1[c]);
      }
    }
    if (ki < 3){
      cpa_wait0();
      __syncthreads();
    }
  }
  // store unnormalized partials + (m, l)
  float* op0 = g_Osp + ((size_t)(bh*NSEQ + qi0)*2 + z)*38;
  float* op1 = g_Osp + ((size_t)(bh*NSEQ + qi0 + 128)*2 + z)*38;
  #pragma unroll
  for(int c=0;c<18;c++){
    ((u64*)op0)[c] = a0[c];
    ((u64*)op1)[c] = a1[c];
  }
  op0[36] = m0; op0[37] = l0;
  op1[36] = m1; op1[37] = l1;
}

// ---------------- split-KV merge: g_Osp -> g_O (token-major) ----------------
__global__ void __launch_bounds__(256) merge_kernel(){
  int qh = blockIdx.x*256 + threadIdx.x;     // bh*1024 + n
  if (qh >= 64*NSEQ) return;
  const float* p0 = g_Osp + (size_t)qh*76;
  const float* p1 = p0 + 38;
  float m0 = p0[36], l0 = p0[37], m1 = p1[36], l1 = p1[37];
  float mm = fmaxf(m0, m1);
  float w0 = __expf(m0 - mm), w1 = __expf(m1 - mm);
  float inv = 1.f/(l0*w0 + l1*w1);
  u64 w02 = pack2f(w0*inv, w0*inv), w12 = pack2f(w1*inv, w1*inv);
  int bh = qh>>10, n = qh&1023, b = bh>>3, h = bh&7;
  u64* o = (u64*)(g_O + (((size_t)(b*NSEQ+n))*8 + h)*36);
  #pragma unroll
  for(int c=0;c<18;c++)
    o[c] = fadd2(fmul2(((const u64*)p0)[c], w02), fmul2(((const u64*)p1)[c], w12));
}

// ---------------- fused: out-proj + res + LN + mlp1 + GP + mlp2 + res ----
// SR token layout: mv at [o*17 + a] (odd stride -> conflict-free), scalars at 272.
__global__ void __launch_bounds__(576) block2_kernel(
    const float* __restrict__ ao_wmv, const float* __restrict__ ao_wsm,
    const float* __restrict__ ao_wms, const float* __restrict__ ao_wss,
    const float* __restrict__ m1_wmv, const float* __restrict__ m1_wsm,
    const float* __restrict__ m1_wms, const float* __restrict__ m1_wss,
    const float* __restrict__ m2_wmv, const float* __restrict__ m2_wsm,
    const float* __restrict__ m2_wms, const float* __restrict__ m2_wss)
{
  constexpr int T = 16, NT = 576, SRS = 304;
  extern __shared__ float sm[];
  float* SA  = sm;             // T*352  attn-out (blade-major); later reused as SX2
  float* SR  = SA + T*352;     // T*304  residual [o*17+a], scalars at 272
  float* SH  = SR + T*SRS;     // T*608  mlp1 hidden
  float* SX2 = SA;             // alias: SA dead after stage 2
  const int tid = threadIdx.x;
  const size_t t0 = (size_t)blockIdx.x * T;

  // ---- stage 1: load attn-out (coalesced) + residual ----
  for(int idx=tid; idx<T*288; idx+=NT){
    int t = idx/288, r = idx%288;
    float v = g_O[(t0+t)*288 + r];
    int h = r/36, e = r%36;
    if (e < 32){ int ci=e>>4, a=e&15; SA[t*352 + a*20 + (h*2+ci)] = v; }
    else       { SA[t*352 + 320 + h*4 + (e-32)] = v; }
  }
  for(int idx=tid; idx<T*256; idx+=NT){
    int t = idx>>8, r = idx&255;
    SR[t*SRS + (r>>4)*17 + (r&15)] = g_mv[(t0+t)*256 + r];
  }
  for(int idx=tid; idx<T*32; idx+=NT){
    int t = idx>>5, j = idx&31;
    SR[t*SRS + 272 + j] = g_s[(t0+t)*32 + j];
  }
  __syncthreads();

  // ---- stage 2: out-projection equi + residual add into SR ----
  {
    int out = tid % 288, tp = tid / 288;   // tp in {0,1}
    if (out < 256){
      int o = out & 15, a = out >> 4;
      int kd = c_kdiag[a], pr = c_pair[a], ko = c_koff[a];
      u64 wd2[8], wp2[8], wsm2[16];
      load_wmv_row(ao_wmv, o, kd, ko, pr, wd2, wp2);
      if (a == 0){
        #pragma unroll
        for(int j=0;j<16;j++) wsm2[j] = pack2f(ao_wsm[o*32+2*j], ao_wsm[o*32+2*j+1]);
      }
      #pragma unroll
      for(int tt=0; tt<4; tt++){
        int t = tp + tt*4;
        float r0, r1;
        equi_mv_val2(SA + t*352, SA + (t+2)*352, a, pr, wd2, wp2, wsm2, r0, r1);
        SR[t*SRS + o*17 + a] += r0;
        SR[(t+2)*SRS + o*17 + a] += r1;
      }
    } else {
      int o = out - 256;
      u64 wss2[16], wms2[8];
      #pragma unroll
      for(int j=0;j<16;j++) wss2[j] = pack2f(ao_wss[o*32+2*j], ao_wss[o*32+2*j+1]);
      #pragma unroll
      for(int i=0;i<8;i++)  wms2[i] = pack2f(ao_wms[o*16+2*i], ao_wms[o*16+2*i+1]);
      #pragma unroll
      for(int tt=0; tt<4; tt++){
        int t = tp + tt*4;
        float r0, r1;
        equi_s_val2(SA + t*352, SA + (t+2)*352, wss2, wms2, r0, r1);
        SR[t*SRS + 272 + o] += r0;
        SR[(t+2)*SRS + 272 + o] += r1;
      }
    }
  }
  __syncthreads();

  // ---- stage 3: LN(SR) -> SX2 (blade-major; aliases SA) ----
  {
    int w = tid>>5, lane = tid&31;
    if (w < T){
      const float* R = SR + w*SRS;
      float ss = 0.f;
      #pragma unroll
      for(int r=0;r<8;r++){
        int li = lane + 32*r; int o = li>>4, a = li&15;
        float v = R[o*17 + a]; ss += v*v*c_inner[a];
      }
      #pragma unroll
      for(int off=16;off;off>>=1) ss += __shfl_xor_sync(0xffffffffu, ss, off);
      float sc = rsqrtf(ss*0.0625f + 1e-6f);
      #pragma unroll
      for(int r=0;r<8;r++){
        int li = lane + 32*r; int o = li>>4, a = li&15;
        SX2[w*352 + a*20 + o] = R[o*17 + a]*sc;
      }
      float v = R[272+lane];
      float s2 = v*v;
      #pragma unroll
      for(int off=16;off;off>>=1) s2 += __shfl_xor_sync(0xffffffffu, s2, off);
      SX2[w*352 + 320 + lane] = v * rsqrtf(s2*0.03125f + 1e-6f);
    }
  }
  __syncthreads();

  // ---- stage 4: mlp1 equi (32 mv ch + 64 s) -> SH ----
  if (tid < 512){
    int o = tid % 32, a = tid / 32;
    int kd = c_kdiag[a], pr = c_pair[a], ko = c_koff[a];
    u64 wd2[8], wp2[8], wsm2[16];
    load_wmv_row(m1_wmv, o, kd, ko, pr, wd2, wp2);
    if (a == 0){
      #pragma unroll
      for(int j=0;j<16;j++) wsm2[j] = pack2f(m1_wsm[o*32+2*j], m1_wsm[o*32+2*j+1]);
    }
    for(int t=0; t<T; t+=2){
      float r0, r1;
      equi_mv_val2(SX2 + t*352, SX2 + (t+1)*352, a, pr, wd2, wp2, wsm2, r0, r1);
      SH[t*608 + o*17 + a] = r0;
      SH[(t+1)*608 + o*17 + a] = r1;
    }
  } else {
    int o = tid - 512;  // 0..63
    u64 wss2[16], wms2[8];
    #pragma unroll
    for(int j=0;j<16;j++) wss2[j] = pack2f(m1_wss[o*32+2*j], m1_wss[o*32+2*j+1]);
    #pragma unroll
    for(int i=0;i<8;i++)  wms2[i] = pack2f(m1_wms[o*16+2*i], m1_wms[o*16+2*i+1]);
    for(int t=0; t<T; t+=2){
      float r0, r1;
      equi_s_val2(SX2 + t*352, SX2 + (t+1)*352, wss2, wms2, r0, r1);
      SH[t*608 + 544 + o] = r0;
      SH[(t+1)*608 + 544 + o] = r1;
    }
  }
  __syncthreads();

  // ---- stage 5: geometric product + gated gelu -> SX2 ----
  for(int idx=tid; idx<768; idx+=NT){
    if (idx < 256){
      int t = idx>>4, c = idx&15;
      const float* h1 = SH + t*608 + c*17;
      const float* h2 = SH + t*608 + (16+c)*17;
      float x[16], y[16], acc[16];
      #pragma unroll
      for(int i=0;i<16;i++){ x[i]=h1[i]; y[i]=h2[i]; acc[i]=0.f; }
      GP_ROW(0)  GP_ROW(1)  GP_ROW(2)  GP_ROW(3)
      GP_ROW(4)  GP_ROW(5)  GP_ROW(6)  GP_ROW(7)
      GP_ROW(8)  GP_ROW(9)  GP_ROW(10) GP_ROW(11)
      GP_ROW(12) GP_ROW(13) GP_ROW(14) GP_ROW(15)
      float g = gelu_f(acc[0]);
      #pragma unroll
      for(int a=0;a<16;a++) SX2[t*352 + a*20 + c] = acc[a]*g;
    } else {
      int r = idx - 256; int t = r>>5, j = r&31;
      const float* hs = SH + t*608 + 544;
      SX2[t*352 + 320 + j] = hs[j] * gelu_f(hs[32+j]);
    }
  }
  __syncthreads();

  // ---- stage 6: mlp2 equi + residual add into SR ----
  {
    int out = tid % 288, tp = tid / 288;
    if (out < 256){
      int o = out & 15, a = out >> 4;
      int kd = c_kdiag[a], pr = c_pair[a], ko = c_koff[a];
      u64 wd2[8], wp2[8], wsm2[16];
      load_wmv_row(m2_wmv, o, kd, ko, pr, wd2, wp2);
      if (a == 0){
        #pragma unroll
        for(int j=0;j<16;j++) wsm2[j] = pack2f(m2_wsm[o*32+2*j], m2_wsm[o*32+2*j+1]);
      }
      #pragma unroll
      for(int tt=0; tt<4; tt++){
        int t = tp + tt*4;
        float r0, r1;
        equi_mv_val2(SX2 + t*352, SX2 + (t+2)*352, a, pr, wd2, wp2, wsm2, r0, r1);
        SR[t*SRS + o*17 + a] += r0;
        SR[(t+2)*SRS + o*17 + a] += r1;
      }
    } else {
      int o = out - 256;
      u64 wss2[16], wms2[8];
      #pragma unroll
      for(int j=0;j<16;j++) wss2[j] = pack2f(m2_wss[o*32+2*j], m2_wss[o*32+2*j+1]);
      #pragma unroll
      for(int i=0;i<8;i++)  wms2[i] = pack2f(m2_wms[o*16+2*i], m2_wms[o*16+2*i+1]);
      #pragma unroll
      for(int tt=0; tt<4; tt++){
        int t = tp + tt*4;
        float r0, r1;
        equi_s_val2(SX2 + t*352, SX2 + (t+2)*352, wss2, wms2, r0, r1);
        SR[t*SRS + 272 + o] += r0;
        SR[(t+2)*SRS + 272 + o] += r1;
      }
    }
  }
  __syncthreads();

  // ---- stage 7: store residual (conflict-free read, coalesced write) ----
  for(int idx=tid; idx<T*256; idx+=NT){
    int t = idx>>8, r = idx&255;
    g_mv[(t0+t)*256 + r] = SR[t*SRS + (r>>4)*17 + (r&15)];
  }
  for(int idx=tid; idx<T*32; idx+=NT){
    int t = idx>>5, j = idx&31;
    g_s[(t0+t)*32 + j] = SR[t*SRS + 272 + j];
  }
}

// ---------------- final projection + mean ----------------
__global__ void final_kernel(const float* __restrict__ wout_mv,
                             const float* __restrict__ wout_sm,
                             float* __restrict__ out){
  int b = blockIdx.x, tid = threadIdx.x;
  __shared__ float red[256];
  float acc = 0.f;
  for(int n=tid; n<NSEQ; n+=256){
    size_t t = (size_t)b*NSEQ + n;
    const float* M = g_mv + t*256;
    const float* S = g_s + t*32;
    float v = 0.f;
    #pragma unroll
    for(int i=0;i<16;i++) v += wout_mv[i*9] * M[i*16];
    #pragma unroll
    for(int j=0;j<32;j++) v += wout_sm[j] * S[j];
    acc += v;
  }
  red[tid] = acc; __syncthreads();
  for(int s=128; s; s>>=1){ if (tid < s) red[tid] += red[tid+s]; __syncthreads(); }
  if (tid == 0) out[b] = red[0] * (1.f/NSEQ);
}

// ---------------- host ----------------
extern "C" void kernel_launch(void* const* d_in, const int* in_sizes, int n_in,
                              void* d_out, int out_size) {
  const float* inputs    = (const float*)d_in[0];
  const float* win_mv    = (const float*)d_in[1];
  const float* win_bs    = (const float*)d_in[3];
  const float* qkv_wmv   = (const float*)d_in[4];
  const float* qkv_wsm   = (const float*)d_in[5];
  const float* qkv_wms   = (const float*)d_in[6];
  const float* qkv_wss   = (const float*)d_in[7];
  const float* aout_wmv  = (const float*)d_in[8];
  const float* aout_wsm  = (const float*)d_in[9];
  const float* aout_wms  = (const float*)d_in[10];
  const float* aout_wss  = (const float*)d_in[11];
  const float* m1_wmv    = (const float*)d_in[12];
  const float* m1_wsm    = (const float*)d_in[13];
  const float* m1_wms    = (const float*)d_in[14];
  const float* m1_wss    = (const float*)d_in[15];
  const float* m2_wmv    = (const float*)d_in[16];
  const float* m2_wsm    = (const float*)d_in[17];
  const float* m2_wms    = (const float*)d_in[18];
  const float* m2_wss    = (const float*)d_in[19];
  const float* wout_mv   = (const float*)d_in[20];
  const float* wout_sm   = (const float*)d_in[21];

  const int smem_qkv  = (16*352 + 16*864) * 4;             // 77824
  const int smem_blk  = (16*352 + 16*304 + 16*608) * 4;    // 80896
  const int smem_attn = (2*640 + 2*1152) * 16;             // 57344
  cudaFuncSetAttribute((const void*)qkv_kernel,
                       cudaFuncAttributeMaxDynamicSharedMemorySize, smem_qkv);
  cudaFuncSetAttribute((const void*)block2_kernel,
                       cudaFuncAttributeMaxDynamicSharedMemorySize, smem_blk);
  cudaFuncSetAttribute((const void*)attn_kernel,
                       cudaFuncAttributeMaxDynamicSharedMemorySize, smem_attn);

  embed_kernel<<<(NTOK*48 + 255)/256, 256>>>(inputs, win_mv, win_bs);

  for (int l = 0; l < 8; l++){
    qkv_kernel<<<NTOK/16, 864, smem_qkv>>>(
        qkv_wmv + (size_t)l*48*16*9, qkv_wsm + (size_t)l*48*32,
        qkv_wms + (size_t)l*96*16,   qkv_wss + (size_t)l*96*32);
    attn_kernel<<<dim3(64, NSEQ/256, 2), 128, smem_attn>>>();
    merge_kernel<<<64*NSEQ/256, 256>>>();
    block2_kernel<<<NTOK/16, 576, smem_blk>>>(
        aout_wmv + (size_t)l*16*16*9, aout_wsm + (size_t)l*16*32,
        aout_wms + (size_t)l*32*16,   aout_wss + (size_t)l*32*32,
        m1_wmv  + (size_t)l*32*16*9,  m1_wsm  + (size_t)l*32*32,
        m1_wms  + (size_t)l*64*16,    m1_wss  + (size_t)l*64*32,
        m2_wmv  + (size_t)l*16*16*9,  m2_wsm  + (size_t)l*16*32,
        m2_wms  + (size_t)l*32*16,    m2_wss  + (size_t)l*32*32);
  }

  final_kernel<<<NBAT, 256>>>(wout_mv, wout_sm, (float*)d_out);
}

// round 10
// speedup vs baseline: 1.4966x; 1.0431x over previous
#include <cuda_runtime.h>
#include <math.h>

#define NTOK 8192
#define NSEQ 1024
#define NBAT 8
#define NSPLIT 4

typedef unsigned long long u64;

// ---------------- f32x2 packed helpers (Blackwell) ----------------
__device__ __forceinline__ u64 pack2f(float lo, float hi){
  u64 r; asm("mov.b64 %0, {%1, %2};" : "=l"(r) : "f"(lo), "f"(hi)); return r;
}
__device__ __forceinline__ u64 ffma2(u64 a, u64 b, u64 c){
  u64 d; asm("fma.rn.f32x2 %0, %1, %2, %3;" : "=l"(d) : "l"(a), "l"(b), "l"(c)); return d;
}
__device__ __forceinline__ u64 fmul2(u64 a, u64 b){
  u64 d; asm("mul.rn.f32x2 %0, %1, %2;" : "=l"(d) : "l"(a), "l"(b)); return d;
}
__device__ __forceinline__ u64 fadd2(u64 a, u64 b){
  u64 d; asm("add.rn.f32x2 %0, %1, %2;" : "=l"(d) : "l"(a), "l"(b)); return d;
}
__device__ __forceinline__ float hadd2(u64 v){
  float a,b; asm("mov.b64 {%0, %1}, %2;" : "=f"(a), "=f"(b) : "l"(v)); return a+b;
}
// ---------------- cp.async helpers ----------------
__device__ __forceinline__ void cpa16(void* s, const void* g){
  unsigned sa = (unsigned)__cvta_generic_to_shared(s);
  asm volatile("cp.async.cg.shared.global [%0], [%1], 16;" :: "r"(sa), "l"(g));
}
__device__ __forceinline__ void cpa_commit(){ asm volatile("cp.async.commit_group;"); }
__device__ __forceinline__ void cpa_wait0(){ asm volatile("cp.async.wait_group 0;"); }

// ---------------- device scratch ----------------
__device__ float g_mv [NTOK*256];
__device__ float g_s  [NTOK*32];
__device__ float g_Q[(size_t)64*NSEQ*20];
__device__ float g_K[(size_t)64*NSEQ*20];
__device__ float g_V[(size_t)64*NSEQ*36];
__device__ float g_Osp[(size_t)64*NSEQ*NSPLIT*38];   // [bh][n][split][36 acc + m + l]

// ---------------- blade tables ----------------
__constant__ int   c_kdiag[16] = {0,1,1,1,1,2,2,2,2,2,2,3,3,3,3,4};
__constant__ int   c_pair [16] = {-1,0,-1,-1,-1,2,3,4,-1,-1,-1,8,9,10,-1,14};
__constant__ int   c_koff [16] = {0,5,0,0,0,6,6,6,0,0,0,7,7,7,0,8};
__constant__ float c_inner[16] = {1,0,1,1,1,0,0,0,1,1,1,0,0,0,1,0};
__constant__ int   c_iblades[8]= {0,2,3,4,8,9,10,14};

// compile-time blade algebra (geometric product)
__host__ __device__ constexpr int blade_mask(int i){
  return i==0?0: i==1?1: i==2?2: i==3?4: i==4?8: i==5?3: i==6?5: i==7?9:
         i==8?6: i==9?10: i==10?12: i==11?7: i==12?11: i==13?13: i==14?14: 15;
}
__host__ __device__ constexpr int mask_idx(int m){
  return m==0?0: m==1?1: m==2?2: m==3?5: m==4?3: m==5?6: m==6?8: m==7?11:
         m==8?4: m==9?7: m==10?9: m==11?12: m==12?10: m==13?13: m==14?14: 15;
}
__host__ __device__ constexpr int pc4(int v){ return (v&1)+((v>>1)&1)+((v>>2)&1)+((v>>3)&1); }
__host__ __device__ constexpr int gp_par(int ma,int mb){
  return ( ((mb&1)?pc4(ma>>1):0) + (((mb>>1)&1)?pc4(ma>>2):0) + (((mb>>2)&1)?pc4(ma>>3):0) ) & 1;
}
template<int I,int J>
__device__ __forceinline__ void gp_term(float (&acc)[16], const float* x, const float* y){
  constexpr int ma = blade_mask(I);
  constexpr int mb = blade_mask(J);
  if constexpr (!(ma & mb & 1)) {
    constexpr int k  = mask_idx(ma ^ mb);
    constexpr int sg = gp_par(ma, mb);
    float p = x[I]*y[J];
    if constexpr (sg) acc[k] -= p; else acc[k] += p;
  }
}
#define GP_ROW(I) \
  gp_term<I,0>(acc,x,y);  gp_term<I,1>(acc,x,y);  gp_term<I,2>(acc,x,y);  gp_term<I,3>(acc,x,y); \
  gp_term<I,4>(acc,x,y);  gp_term<I,5>(acc,x,y);  gp_term<I,6>(acc,x,y);  gp_term<I,7>(acc,x,y); \
  gp_term<I,8>(acc,x,y);  gp_term<I,9>(acc,x,y);  gp_term<I,10>(acc,x,y); gp_term<I,11>(acc,x,y);\
  gp_term<I,12>(acc,x,y); gp_term<I,13>(acc,x,y); gp_term<I,14>(acc,x,y); gp_term<I,15>(acc,x,y);

__device__ __forceinline__ float gelu_f(float v){
  float v3 = v*v*v;
  return 0.5f*v*(1.f + tanhf(0.7978845608028654f*(v + 0.044715f*v3)));
}

// ---- equi building blocks: TWO tokens per call (8-way ILP) ----
__device__ __forceinline__ void load_wmv_row(const float* wmv, int o, int kd, int ko, int pr,
                                             u64* wd2, u64* wp2){
  #pragma unroll
  for(int i=0;i<8;i++)
    wd2[i] = pack2f(wmv[o*144 + (2*i)*9 + kd], wmv[o*144 + (2*i+1)*9 + kd]);
  if (pr >= 0){
    #pragma unroll
    for(int i=0;i<8;i++)
      wp2[i] = pack2f(wmv[o*144 + (2*i)*9 + ko], wmv[o*144 + (2*i+1)*9 + ko]);
  }
}
__device__ __forceinline__ void equi_mv_val2(const float* X0, const float* X1, int a, int pr,
    const u64* wd2, const u64* wp2, const u64* wsm2, float& r0, float& r1){
  const u64* A0 = (const u64*)(X0 + a*20);
  const u64* A1 = (const u64*)(X1 + a*20);
  u64 p0 = fmul2(wd2[0], A0[0]), p1 = fmul2(wd2[1], A0[1]);
  u64 q0 = fmul2(wd2[0], A1[0]), q1 = fmul2(wd2[1], A1[1]);
  #pragma unroll
  for(int c=2;c<8;c+=2){
    p0 = ffma2(wd2[c],A0[c],p0); p1 = ffma2(wd2[c+1],A0[c+1],p1);
    q0 = ffma2(wd2[c],A1[c],q0); q1 = ffma2(wd2[c+1],A1[c+1],q1);
  }
  if (pr >= 0){
    const u64* B0 = (const u64*)(X0 + pr*20);
    const u64* B1 = (const u64*)(X1 + pr*20);
    #pragma unroll
    for(int c=0;c<8;c+=2){
      p0 = ffma2(wp2[c],B0[c],p0); p1 = ffma2(wp2[c+1],B0[c+1],p1);
      q0 = ffma2(wp2[c],B1[c],q0); q1 = ffma2(wp2[c+1],B1[c+1],q1);
    }
  }
  if (a == 0){
    const u64* S0 = (const u64*)(X0 + 320);
    const u64* S1 = (const u64*)(X1 + 320);
    #pragma unroll
    for(int c=0;c<16;c+=2){
      p0 = ffma2(wsm2[c],S0[c],p0); p1 = ffma2(wsm2[c+1],S0[c+1],p1);
      q0 = ffma2(wsm2[c],S1[c],q0); q1 = ffma2(wsm2[c+1],S1[c+1],q1);
    }
  }
  r0 = hadd2(fadd2(p0, p1));
  r1 = hadd2(fadd2(q0, q1));
}
__device__ __forceinline__ void equi_s_val2(const float* X0, const float* X1,
    const u64* wss2, const u64* wms2, float& r0, float& r1){
  const u64* S0 = (const u64*)(X0 + 320);
  const u64* S1 = (const u64*)(X1 + 320);
  u64 p0 = fmul2(wss2[0], S0[0]), p1 = fmul2(wss2[1], S0[1]);
  u64 q0 = fmul2(wss2[0], S1[0]), q1 = fmul2(wss2[1], S1[1]);
  #pragma unroll
  for(int c=2;c<16;c+=2){
    p0 = ffma2(wss2[c],S0[c],p0); p1 = ffma2(wss2[c+1],S0[c+1],p1);
    q0 = ffma2(wss2[c],S1[c],q0); q1 = ffma2(wss2[c+1],S1[c+1],q1);
  }
  const u64* Z0 = (const u64*)(X0);
  const u64* Z1 = (const u64*)(X1);
  #pragma unroll
  for(int c=0;c<8;c+=2){
    p0 = ffma2(wms2[c],Z0[c],p0); p1 = ffma2(wms2[c+1],Z0[c+1],p1);
    q0 = ffma2(wms2[c],Z1[c],q0); q1 = ffma2(wms2[c+1],Z1[c+1],q1);
  }
  r0 = hadd2(fadd2(p0, p1));
  r1 = hadd2(fadd2(q0, q1));
}

// ---------------- embed ----------------
__global__ void embed_kernel(const float* __restrict__ inp,
                             const float* __restrict__ win_mv,
                             const float* __restrict__ win_bs){
  int idx = blockIdx.x*blockDim.x + threadIdx.x;
  if (idx < NTOK*16){
    int t = idx>>4, o = idx&15;
    float x = inp[t*3+0], y = inp[t*3+1], z = inp[t*3+2];
    float w3 = win_mv[o*9+3], w8 = win_mv[o*9+8];
    float* M = g_mv + (size_t)t*256 + o*16;
    #pragma unroll
    for(int a=0;a<16;a++) M[a]=0.f;
    M[11] = -z*w3;  M[12] = y*w3;  M[13] = -x*w3;  M[14] = w3;  M[15] = w8;
  } else if (idx < NTOK*16 + NTOK*32){
    int r = idx - NTOK*16; int t = r>>5, j = r&31;
    g_s[t*32+j] = win_bs[j];
  }
}

// ---------------- LN + QKV equi, staged coalesced pack ----------------
__global__ void __launch_bounds__(864) qkv_kernel(
    const float* __restrict__ wmv, const float* __restrict__ wsm,
    const float* __restrict__ wms, const float* __restrict__ wss)
{
  constexpr int T = 16, NT = 864;
  extern __shared__ float sm[];
  float* SX = sm;            // T*352
  float* SY = sm + T*352;    // T*864
  const int tid = threadIdx.x;
  const size_t t0 = (size_t)blockIdx.x * T;
  const int b = (int)(t0 >> 10), n0 = (int)(t0 & 1023);

  for(int idx=tid; idx<T*256; idx+=NT){
    int t = idx>>8, r = idx&255, i = r>>4, a = r&15;
    SX[t*352 + a*20 + i] = g_mv[(t0+t)*256 + r];
  }
  for(int idx=tid; idx<T*32; idx+=NT){
    int t = idx>>5, j = idx&31;
    SX[t*352 + 320 + j] = g_s[(t0+t)*32 + j];
  }
  __syncthreads();

  { // LN: warp w -> token w
    int w = tid>>5, lane = tid&31;
    if (w < T){
      float* X = SX + w*352;
      int a = lane>>1;
      int base = a*20 + (lane&1)*8;
      float msk = c_inner[a];
      float ss = 0.f;
      #pragma unroll
      for(int r=0;r<8;r++){ float v = X[base+r]; ss += v*v*msk; }
      #pragma unroll
      for(int off=16;off;off>>=1) ss += __shfl_xor_sync(0xffffffffu, ss, off);
      float sc = rsqrtf(ss*0.0625f + 1e-6f);
      #pragma unroll
      for(int r=0;r<8;r++) X[base+r] *= sc;
      float v = X[320+lane];
      float s2 = v*v;
      #pragma unroll
      for(int off=16;off;off>>=1) s2 += __shfl_xor_sync(0xffffffffu, s2, off);
      X[320+lane] = v * rsqrtf(s2*0.03125f + 1e-6f);
    }
  }
  __syncthreads();

  if (tid < 768){
    int o = tid % 48, a = tid / 48;
    int kd = c_kdiag[a], pr = c_pair[a], ko = c_koff[a];
    u64 wd2[8], wp2[8], wsm2[16];
    load_wmv_row(wmv, o, kd, ko, pr, wd2, wp2);
    if (a == 0){
      #pragma unroll
      for(int j=0;j<16;j++) wsm2[j] = pack2f(wsm[o*32+2*j], wsm[o*32+2*j+1]);
    }
    for(int t=0; t<T; t+=2){
      float r0, r1;
      equi_mv_val2(SX + t*352, SX + (t+1)*352, a, pr, wd2, wp2, wsm2, r0, r1);
      SY[t*864 + a*48 + o] = r0;
      SY[(t+1)*864 + a*48 + o] = r1;
    }
  } else {
    int o = tid - 768;  // 0..95
    u64 wss2[16], wms2[8];
    #pragma unroll
    for(int j=0;j<16;j++) wss2[j] = pack2f(wss[o*32+2*j], wss[o*32+2*j+1]);
    #pragma unroll
    for(int i=0;i<8;i++)  wms2[i] = pack2f(wms[o*16+2*i], wms[o*16+2*i+1]);
    for(int t=0; t<T; t+=2){
      float r0, r1;
      equi_s_val2(SX + t*352, SX + (t+1)*352, wss2, wms2, r0, r1);
      SY[t*864 + 768 + o] = r0;
      SY[(t+1)*864 + 768 + o] = r1;
    }
  }
  __syncthreads();

  for(int idx=tid; idx<8*T*20; idx+=NT){           // Q
    int h = idx/(T*20), rem = idx%(T*20), t = rem/20, e = rem%20;
    float v;
    if (e < 16){ int ci=e>>3, ib=e&7, a=c_iblades[ib]; v = SY[t*864 + a*48 + (h*2+ci)]; }
    else       { v = SY[t*864 + 768 + h*4 + (e-16)]; }
    g_Q[((size_t)(b*8+h)*NSEQ + n0 + t)*20 + e] = v;
  }
  for(int idx=tid; idx<8*T*20; idx+=NT){           // K
    int h = idx/(T*20), rem = idx%(T*20), t = rem/20, e = rem%20;
    float v;
    if (e < 16){ int ci=e>>3, ib=e&7, a=c_iblades[ib]; v = SY[t*864 + a*48 + (16 + h*2+ci)]; }
    else       { v = SY[t*864 + 768 + 32 + h*4 + (e-16)]; }
    g_K[((size_t)(b*8+h)*NSEQ + n0 + t)*20 + e] = v;
  }
  for(int idx=tid; idx<8*T*36; idx+=NT){           // V
    int h = idx/(T*36), rem = idx%(T*36), t = rem/36, e = rem%36;
    float v;
    if (e < 32){ int ci=e>>4, a=e&15; v = SY[t*864 + a*48 + (32 + h*2+ci)]; }
    else       { v = SY[t*864 + 768 + 64 + h*4 + (e-32)]; }
    g_V[((size_t)(b*8+h)*NSEQ + n0 + t)*36 + e] = v;
  }
}

// ---------------- attention (split-KV x4, 2 q/thread, f32x2) ----------------
__global__ void __launch_bounds__(128) attn_kernel(){
  const int bh = blockIdx.x, qt = blockIdx.y, z = blockIdx.z, tid = threadIdx.x;
  const int qi0 = qt*256 + tid;
  const float SCALE = 0.22360679774997896f;  // 1/sqrt(20)

  extern __shared__ float4 dyn4[];
  float4* sk4 = dyn4;            // 2 x 640
  float4* sv4 = dyn4 + 1280;     // 2 x 1152

  u64 q0[10], q1[10];
  {
    const float* qp0 = g_Q + ((size_t)bh*NSEQ + qi0)*20;
    const float* qp1 = qp0 + 128*20;
    #pragma unroll
    for(int c=0;c<10;c++){
      q0[c] = pack2f(qp0[2*c]*SCALE, qp0[2*c+1]*SCALE);
      q1[c] = pack2f(qp1[2*c]*SCALE, qp1[2*c+1]*SCALE);
    }
  }
  float m0=-1e30f, l0=0.f, m1=-1e30f, l1=0.f;
  u64 a0[18], a1[18];
  #pragma unroll
  for(int c=0;c<18;c++){ a0[c]=0ull; a1[c]=0ull; }

  const int kt0 = z*2;
  const float4* kp = (const float4*)(g_K + (size_t)bh*NSEQ*20) + kt0*128*5;
  const float4* vp = (const float4*)(g_V + (size_t)bh*NSEQ*36) + kt0*128*9;

  // preload tile 0
  #pragma unroll
  for(int i=0;i<5;i++) cpa16(&sk4[tid + 128*i], &kp[tid + 128*i]);
  #pragma unroll
  for(int i=0;i<9;i++) cpa16(&sv4[tid + 128*i], &vp[tid + 128*i]);
  cpa_commit();
  cpa_wait0();
  __syncthreads();

  for(int ki=0; ki<2; ki++){
    const int cur = ki & 1, nxt = cur ^ 1;
    if (ki < 1){
      const float4* kpn = kp + 128*5;
      const float4* vpn = vp + 128*9;
      #pragma unroll
      for(int i=0;i<5;i++) cpa16(&sk4[nxt*640 + tid + 128*i], &kpn[tid + 128*i]);
      #pragma unroll
      for(int i=0;i<9;i++) cpa16(&sv4[nxt*1152 + tid + 128*i], &vpn[tid + 128*i]);
      cpa_commit();
    }
    const float4* skc = sk4 + cur*640;
    const float4* svc = sv4 + cur*1152;

    for(int j=0; j<128; j++){
      const u64* kk = (const u64*)(skc + j*5);
      const u64* vv = (const u64*)(svc + j*9);
      u64 t0a = fmul2(q0[0], kk[0]), t0b = fmul2(q0[1], kk[1]);
      u64 t1a = fmul2(q1[0], kk[0]), t1b = fmul2(q1[1], kk[1]);
      #pragma unroll
      for(int c=2;c<10;c+=2){
        t0a = ffma2(q0[c], kk[c], t0a);  t0b = ffma2(q0[c+1], kk[c+1], t0b);
        t1a = ffma2(q1[c], kk[c], t1a);  t1b = ffma2(q1[c+1], kk[c+1], t1b);
      }
      float s0 = hadd2(fadd2(t0a, t0b));
      float s1 = hadd2(fadd2(t1a, t1b));
      float p0, p1;
      if (s0 > m0){
        float cc = __expf(m0 - s0); m0 = s0; l0 = l0*cc + 1.f;
        u64 cp = pack2f(cc, cc);
        #pragma unroll
        for(int c=0;c<18;c++) a0[c] = fmul2(a0[c], cp);
        p0 = 1.f;
      } else { p0 = __expf(s0 - m0); l0 += p0; }
      if (s1 > m1){
        float cc = __expf(m1 - s1); m1 = s1; l1 = l1*cc + 1.f;
        u64 cp = pack2f(cc, cc);
        #pragma unroll
        for(int c=0;c<18;c++) a1[c] = fmul2(a1[c], cp);
        p1 = 1.f;
      } else { p1 = __expf(s1 - m1); l1 += p1; }
      u64 pp0 = pack2f(p0, p0), pp1 = pack2f(p1, p1);
      #pragma unroll
      for(int c=0;c<18;c++){
        a0[c] = ffma2(pp0, vv[c], a0[c]);
        a1[c] = ffma2(pp1, vv[c], a1[c]);
      }
    }
    if (ki < 1){
      cpa_wait0();
      __syncthreads();
    }
  }
  // store unnormalized partials + (m, l)
  float* op0 = g_Osp + ((size_t)(bh*NSEQ + qi0)*NSPLIT + z)*38;
  float* op1 = g_Osp + ((size_t)(bh*NSEQ + qi0 + 128)*NSPLIT + z)*38;
  #pragma unroll
  for(int c=0;c<18;c++){
    ((u64*)op0)[c] = a0[c];
    ((u64*)op1)[c] = a1[c];
  }
  op0[36] = m0; op0[37] = l0;
  op1[36] = m1; op1[37] = l1;
}

// ---------------- fused: merge + out-proj + res + LN + mlp1 + GP + mlp2 + res
// T=8 tokens/block, NT=288, 2 blocks/SM.
__global__ void __launch_bounds__(288, 2) block2_kernel(
    const float* __restrict__ ao_wmv, const float* __restrict__ ao_wsm,
    const float* __restrict__ ao_wms, const float* __restrict__ ao_wss,
    const float* __restrict__ m1_wmv, const float* __restrict__ m1_wsm,
    const float* __restrict__ m1_wms, const float* __restrict__ m1_wss,
    const float* __restrict__ m2_wmv, const float* __restrict__ m2_wsm,
    const float* __restrict__ m2_wms, const float* __restrict__ m2_wss)
{
  constexpr int T = 8, NT = 288, SRS = 304;
  extern __shared__ float sm[];
  float* SA  = sm;             // T*352  attn-out (blade-major); later reused as SX2
  float* SR  = SA + T*352;     // T*304  residual [o*17+a], scalars at 272
  float* SH  = SR + T*SRS;     // T*608  mlp1 hidden
  float* SW  = SH + T*608;     // T*8*NSPLIT merge weights
  float* SX2 = SA;             // alias: SA dead after stage 2
  const int tid = threadIdx.x;
  const size_t t0 = (size_t)blockIdx.x * T;
  const int b = (int)(t0 >> 10), n0 = (int)(t0 & 1023);

  // ---- stage 0: merge weights + residual loads ----
  if (tid < T*8){
    int t = tid>>3, h = tid&7;
    const float* p = g_Osp + (((size_t)(b*8+h)*NSEQ + n0 + t)*NSPLIT)*38;
    float m[NSPLIT], l[NSPLIT];
    float mm = -1e30f;
    #pragma unroll
    for(int z=0;z<NSPLIT;z++){ m[z]=p[z*38+36]; l[z]=p[z*38+37]; mm = fmaxf(mm, m[z]); }
    float den = 0.f, w[NSPLIT];
    #pragma unroll
    for(int z=0;z<NSPLIT;z++){ w[z] = __expf(m[z]-mm); den += l[z]*w[z]; }
    float inv = 1.f/den;
    #pragma unroll
    for(int z=0;z<NSPLIT;z++) SW[tid*NSPLIT + z] = w[z]*inv;
  }
  for(int idx=tid; idx<T*256; idx+=NT){
    int t = idx>>8, r = idx&255;
    SR[t*SRS + (r>>4)*17 + (r&15)] = g_mv[(t0+t)*256 + r];
  }
  for(int idx=tid; idx<T*32; idx+=NT){
    int t = idx>>5, j = idx&31;
    SR[t*SRS + 272 + j] = g_s[(t0+t)*32 + j];
  }
  __syncthreads();

  // ---- stage 1: merged attn-out -> SA (blade-major) ----
  for(int idx=tid; idx<T*288; idx+=NT){
    int t = idx/288, r = idx%288;
    int h = r/36, e = r%36;
    const float* p = g_Osp + (((size_t)(b*8+h)*NSEQ + n0 + t)*NSPLIT)*38;
    const float* wv = SW + (t*8+h)*NSPLIT;
    float v = 0.f;
    #pragma unroll
    for(int z=0;z<NSPLIT;z++) v += p[z*38 + e] * wv[z];
    if (e < 32){ int ci=e>>4, a=e&15; SA[t*352 + a*20 + (h*2+ci)] = v; }
    else       { SA[t*352 + 320 + h*4 + (e-32)] = v; }
  }
  __syncthreads();

  // ---- stage 2: out-projection equi + residual add into SR ----
  {
    int out = tid;
    if (out < 256){
      int o = out & 15, a = out >> 4;
      int kd = c_kdiag[a], pr = c_pair[a], ko = c_koff[a];
      u64 wd2[8], wp2[8], wsm2[16];
      load_wmv_row(ao_wmv, o, kd, ko, pr, wd2, wp2);
      if (a == 0){
        #pragma unroll
        for(int j=0;j<16;j++) wsm2[j] = pack2f(ao_wsm[o*32+2*j], ao_wsm[o*32+2*j+1]);
      }
      #pragma unroll
      for(int tt=0; tt<T; tt+=2){
        float r0, r1;
        equi_mv_val2(SA + tt*352, SA + (tt+1)*352, a, pr, wd2, wp2, wsm2, r0, r1);
        SR[tt*SRS + o*17 + a] += r0;
        SR[(tt+1)*SRS + o*17 + a] += r1;
      }
    } else {
      int o = out - 256;
      u64 wss2[16], wms2[8];
      #pragma unroll
      for(int j=0;j<16;j++) wss2[j] = pack2f(ao_wss[o*32+2*j], ao_wss[o*32+2*j+1]);
      #pragma unroll
      for(int i=0;i<8;i++)  wms2[i] = pack2f(ao_wms[o*16+2*i], ao_wms[o*16+2*i+1]);
      #pragma unroll
      for(int tt=0; tt<T; tt+=2){
        float r0, r1;
        equi_s_val2(SA + tt*352, SA + (tt+1)*352, wss2, wms2, r0, r1);
        SR[tt*SRS + 272 + o] += r0;
        SR[(tt+1)*SRS + 272 + o] += r1;
      }
    }
  }
  __syncthreads();

  // ---- stage 3: LN(SR) -> SX2 (blade-major; aliases SA) ----
  {
    int w = tid>>5, lane = tid&31;
    if (w < T){
      const float* R = SR + w*SRS;
      float ss = 0.f;
      #pragma unroll
      for(int r=0;r<8;r++){
        int li = lane + 32*r; int o = li>>4, a = li&15;
        float v = R[o*17 + a]; ss += v*v*c_inner[a];
      }
      #pragma unroll
      for(int off=16;off;off>>=1) ss += __shfl_xor_sync(0xffffffffu, ss, off);
      float sc = rsqrtf(ss*0.0625f + 1e-6f);
      #pragma unroll
      for(int r=0;r<8;r++){
        int li = lane + 32*r; int o = li>>4, a = li&15;
        SX2[w*352 + a*20 + o] = R[o*17 + a]*sc;
      }
      float v = R[272+lane];
      float s2 = v*v;
      #pragma unroll
      for(int off=16;off;off>>=1) s2 += __shfl_xor_sync(0xffffffffu, s2, off);
      SX2[w*352 + 320 + lane] = v * rsqrtf(s2*0.03125f + 1e-6f);
    }
  }
  __syncthreads();

  // ---- stage 4: mlp1 equi (512 mv outs + 64 s outs over 288 threads) ----
  for(int half=0; half<2; half++){
    int out = tid + half*NT;
    if (out < 512){
      int o = out % 32, a = out / 32;
      int kd = c_kdiag[a], pr = c_pair[a], ko = c_koff[a];
      u64 wd2[8], wp2[8], wsm2[16];
      load_wmv_row(m1_wmv, o, kd, ko, pr, wd2, wp2);
      if (a == 0){
        #pragma unroll
        for(int j=0;j<16;j++) wsm2[j] = pack2f(m1_wsm[o*32+2*j], m1_wsm[o*32+2*j+1]);
      }
      #pragma unroll
      for(int t=0; t<T; t+=2){
        float r0, r1;
        equi_mv_val2(SX2 + t*352, SX2 + (t+1)*352, a, pr, wd2, wp2, wsm2, r0, r1);
        SH[t*608 + o*17 + a] = r0;
        SH[(t+1)*608 + o*17 + a] = r1;
      }
    } else if (out < 576){
      int o = out - 512;  // 0..63
      u64 wss2[16], wms2[8];
      #pragma unroll
      for(int j=0;j<16;j++) wss2[j] = pack2f(m1_wss[o*32+2*j], m1_wss[o*32+2*j+1]);
      #pragma unroll
      for(int i=0;i<8;i++)  wms2[i] = pack2f(m1_wms[o*16+2*i], m1_wms[o*16+2*i+1]);
      #pragma unroll
      for(int t=0; t<T; t+=2){
        float r0, r1;
        equi_s_val2(SX2 + t*352, SX2 + (t+1)*352, wss2, wms2, r0, r1);
        SH[t*608 + 544 + o] = r0;
        SH[(t+1)*608 + 544 + o] = r1;
      }
    }
  }
  __syncthreads();

  // ---- stage 5: geometric product + gated gelu -> SX2 ----
  for(int idx=tid; idx<T*48; idx+=NT){
    if (idx < T*16){
      int t = idx>>4, c = idx&15;
      const float* h1 = SH + t*608 + c*17;
      const float* h2 = SH + t*608 + (16+c)*17;
      float x[16], y[16], acc[16];
      #pragma unroll
      for(int i=0;i<16;i++){ x[i]=h1[i]; y[i]=h2[i]; acc[i]=0.f; }
      GP_ROW(0)  GP_ROW(1)  GP_ROW(2)  GP_ROW(3)
      GP_ROW(4)  GP_ROW(5)  GP_ROW(6)  GP_ROW(7)
      GP_ROW(8)  GP_ROW(9)  GP_ROW(10) GP_ROW(11)
      GP_ROW(12) GP_ROW(13) GP_ROW(14) GP_ROW(15)
      float g = gelu_f(acc[0]);
      #pragma unroll
      for(int a=0;a<16;a++) SX2[t*352 + a*20 + c] = acc[a]*g;
    } else {
      int r = idx - T*16; int t = r>>5, j = r&31;
      const float* hs = SH + t*608 + 544;
      SX2[t*352 + 320 + j] = hs[j] * gelu_f(hs[32+j]);
    }
  }
  __syncthreads();

  // ---- stage 6: mlp2 equi + residual add into SR ----
  {
    int out = tid;
    if (out < 256){
      int o = out & 15, a = out >> 4;
      int kd = c_kdiag[a], pr = c_pair[a], ko = c_koff[a];
      u64 wd2[8], wp2[8], wsm2[16];
      load_wmv_row(m2_wmv, o, kd, ko, pr, wd2, wp2);
      if (a == 0){
        #pragma unroll
        for(int j=0;j<16;j++) wsm2[j] = pack2f(m2_wsm[o*32+2*j], m2_wsm[o*32+2*j+1]);
      }
      #pragma unroll
      for(int tt=0; tt<T; tt+=2){
        float r0, r1;
        equi_mv_val2(SX2 + tt*352, SX2 + (tt+1)*352, a, pr, wd2, wp2, wsm2, r0, r1);
        SR[tt*SRS + o*17 + a] += r0;
        SR[(tt+1)*SRS + o*17 + a] += r1;
      }
    } else {
      int o = out - 256;
      u64 wss2[16], wms2[8];
      #pragma unroll
      for(int j=0;j<16;j++) wss2[j] = pack2f(m2_wss[o*32+2*j], m2_wss[o*32+2*j+1]);
      #pragma unroll
      for(int i=0;i<8;i++)  wms2[i] = pack2f(m2_wms[o*16+2*i], m2_wms[o*16+2*i+1]);
      #pragma unroll
      for(int tt=0; tt<T; tt+=2){
        float r0, r1;
        equi_s_val2(SX2 + tt*352, SX2 + (tt+1)*352, wss2, wms2, r0, r1);
        SR[tt*SRS + 272 + o] += r0;
        SR[(tt+1)*SRS + 272 + o] += r1;
      }
    }
  }
  __syncthreads();

  // ---- stage 7: store residual ----
  for(int idx=tid; idx<T*256; idx+=NT){
    int t = idx>>8, r = idx&255;
    g_mv[(t0+t)*256 + r] = SR[t*SRS + (r>>4)*17 + (r&15)];
  }
  for(int idx=tid; idx<T*32; idx+=NT){
    int t = idx>>5, j = idx&31;
    g_s[(t0+t)*32 + j] = SR[t*SRS + 272 + j];
  }
}

// ---------------- final projection + mean ----------------
__global__ void final_kernel(const float* __restrict__ wout_mv,
                             const float* __restrict__ wout_sm,
                             float* __restrict__ out){
  int b = blockIdx.x, tid = threadIdx.x;
  __shared__ float red[256];
  float acc = 0.f;
  for(int n=tid; n<NSEQ; n+=256){
    size_t t = (size_t)b*NSEQ + n;
    const float* M = g_mv + t*256;
    const float* S = g_s + t*32;
    float v = 0.f;
    #pragma unroll
    for(int i=0;i<16;i++) v += wout_mv[i*9] * M[i*16];
    #pragma unroll
    for(int j=0;j<32;j++) v += wout_sm[j] * S[j];
    acc += v;
  }
  red[tid] = acc; __syncthreads();
  for(int s=128; s; s>>=1){ if (tid < s) red[tid] += red[tid+s]; __syncthreads(); }
  if (tid == 0) out[b] = red[0] * (1.f/NSEQ);
}

// ---------------- host ----------------
extern "C" void kernel_launch(void* const* d_in, const int* in_sizes, int n_in,
                              void* d_out, int out_size) {
  const float* inputs    = (const float*)d_in[0];
  const float* win_mv    = (const float*)d_in[1];
  const float* win_bs    = (const float*)d_in[3];
  const float* qkv_wmv   = (const float*)d_in[4];
  const float* qkv_wsm   = (const float*)d_in[5];
  const float* qkv_wms   = (const float*)d_in[6];
  const float* qkv_wss   = (const float*)d_in[7];
  const float* aout_wmv  = (const float*)d_in[8];
  const float* aout_wsm  = (const float*)d_in[9];
  const float* aout_wms  = (const float*)d_in[10];
  const float* aout_wss  = (const float*)d_in[11];
  const float* m1_wmv    = (const float*)d_in[12];
  const float* m1_wsm    = (const float*)d_in[13];
  const float* m1_wms    = (const float*)d_in[14];
  const float* m1_wss    = (const float*)d_in[15];
  const float* m2_wmv    = (const float*)d_in[16];
  const float* m2_wsm    = (const float*)d_in[17];
  const float* m2_wms    = (const float*)d_in[18];
  const float* m2_wss    = (const float*)d_in[19];
  const float* wout_mv   = (const float*)d_in[20];
  const float* wout_sm   = (const float*)d_in[21];

  const int smem_qkv  = (16*352 + 16*864) * 4;                       // 77824
  const int smem_blk  = (8*352 + 8*304 + 8*608 + 8*8*NSPLIT) * 4;    // 41472
  const int smem_attn = (2*640 + 2*1152) * 16;                       // 57344
  cudaFuncSetAttribute((const void*)qkv_kernel,
                       cudaFuncAttributeMaxDynamicSharedMemorySize, smem_qkv);
  cudaFuncSetAttribute((const void*)block2_kernel,
                       cudaFuncAttributeMaxDynamicSharedMemorySize, smem_blk);
  cudaFuncSetAttribute((const void*)attn_kernel,
                       cudaFuncAttributeMaxDynamicSharedMemorySize, smem_attn);

  embed_kernel<<<(NTOK*48 + 255)/256, 256>>>(inputs, win_mv, win_bs);

  for (int l = 0; l < 8; l++){
    qkv_kernel<<<NTOK/16, 864, smem_qkv>>>(
        qkv_wmv + (size_t)l*48*16*9, qkv_wsm + (size_t)l*48*32,
        qkv_wms + (size_t)l*96*16,   qkv_wss + (size_t)l*96*32);
    attn_kernel<<<dim3(64, NSEQ/256, NSPLIT), 128, smem_attn>>>();
    block2_kernel<<<NTOK/8, 288, smem_blk>>>(
        aout_wmv + (size_t)l*16*16*9, aout_wsm + (size_t)l*16*32,
        aout_wms + (size_t)l*32*16,   aout_wss + (size_t)l*32*32,
        m1_wmv  + (size_t)l*32*16*9,  m1_wsm  + (size_t)l*32*32,
        m1_wms  + (size_t)l*64*16,    m1_wss  + (size_t)l*64*32,
        m2_wmv  + (size_t)l*16*16*9,  m2_wsm  + (size_t)l*16*32,
        m2_wms  + (size_t)l*32*16,    m2_wss  + (size_t)l*32*32);
  }

  final_kernel<<<NBAT, 256>>>(wout_mv, wout_sm, (float*)d_out);
}

// round 11
// speedup vs baseline: 1.5951x; 1.0658x over previous
#include <cuda_runtime.h>
#include <math.h>

#define NTOK 8192
#define NSEQ 1024
#define NBAT 8
#define NSPLIT 4

typedef unsigned long long u64;

// ---------------- f32x2 packed helpers (Blackwell) ----------------
__device__ __forceinline__ u64 pack2f(float lo, float hi){
  u64 r; asm("mov.b64 %0, {%1, %2};" : "=l"(r) : "f"(lo), "f"(hi)); return r;
}
__device__ __forceinline__ u64 ffma2(u64 a, u64 b, u64 c){
  u64 d; asm("fma.rn.f32x2 %0, %1, %2, %3;" : "=l"(d) : "l"(a), "l"(b), "l"(c)); return d;
}
__device__ __forceinline__ u64 fmul2(u64 a, u64 b){
  u64 d; asm("mul.rn.f32x2 %0, %1, %2;" : "=l"(d) : "l"(a), "l"(b)); return d;
}
__device__ __forceinline__ u64 fadd2(u64 a, u64 b){
  u64 d; asm("add.rn.f32x2 %0, %1, %2;" : "=l"(d) : "l"(a), "l"(b)); return d;
}
__device__ __forceinline__ float hadd2(u64 v){
  float a,b; asm("mov.b64 {%0, %1}, %2;" : "=f"(a), "=f"(b) : "l"(v)); return a+b;
}
// ---------------- cp.async helpers ----------------
__device__ __forceinline__ void cpa16(void* s, const void* g){
  unsigned sa = (unsigned)__cvta_generic_to_shared(s);
  asm volatile("cp.async.cg.shared.global [%0], [%1], 16;" :: "r"(sa), "l"(g));
}
__device__ __forceinline__ void cpa_commit(){ asm volatile("cp.async.commit_group;"); }
__device__ __forceinline__ void cpa_wait0(){ asm volatile("cp.async.wait_group 0;"); }

// ---------------- device scratch ----------------
__device__ float g_mv [NTOK*256];
__device__ float g_s  [NTOK*32];
__device__ float g_Q[(size_t)64*NSEQ*20];
__device__ float g_K[(size_t)64*NSEQ*20];
__device__ float g_V[(size_t)64*NSEQ*36];
__device__ float g_Osp[(size_t)64*NSEQ*NSPLIT*38];   // [bh][n][split][36 acc + m + l]

// ---------------- blade tables ----------------
__constant__ int   c_kdiag[16] = {0,1,1,1,1,2,2,2,2,2,2,3,3,3,3,4};
__constant__ int   c_pair [16] = {-1,0,-1,-1,-1,2,3,4,-1,-1,-1,8,9,10,-1,14};
__constant__ int   c_koff [16] = {0,5,0,0,0,6,6,6,0,0,0,7,7,7,0,8};
__constant__ float c_inner[16] = {1,0,1,1,1,0,0,0,1,1,1,0,0,0,1,0};
__constant__ int   c_iblades[8]= {0,2,3,4,8,9,10,14};

// compile-time blade algebra (geometric product)
__host__ __device__ constexpr int blade_mask(int i){
  return i==0?0: i==1?1: i==2?2: i==3?4: i==4?8: i==5?3: i==6?5: i==7?9:
         i==8?6: i==9?10: i==10?12: i==11?7: i==12?11: i==13?13: i==14?14: 15;
}
__host__ __device__ constexpr int mask_idx(int m){
  return m==0?0: m==1?1: m==2?2: m==3?5: m==4?3: m==5?6: m==6?8: m==7?11:
         m==8?4: m==9?7: m==10?9: m==11?12: m==12?10: m==13?13: m==14?14: 15;
}
__host__ __device__ constexpr int pc4(int v){ return (v&1)+((v>>1)&1)+((v>>2)&1)+((v>>3)&1); }
__host__ __device__ constexpr int gp_par(int ma,int mb){
  return ( ((mb&1)?pc4(ma>>1):0) + (((mb>>1)&1)?pc4(ma>>2):0) + (((mb>>2)&1)?pc4(ma>>3):0) ) & 1;
}
template<int I,int J>
__device__ __forceinline__ void gp_term(float (&acc)[16], const float* x, const float* y){
  constexpr int ma = blade_mask(I);
  constexpr int mb = blade_mask(J);
  if constexpr (!(ma & mb & 1)) {
    constexpr int k  = mask_idx(ma ^ mb);
    constexpr int sg = gp_par(ma, mb);
    float p = x[I]*y[J];
    if constexpr (sg) acc[k] -= p; else acc[k] += p;
  }
}
#define GP_ROW(I) \
  gp_term<I,0>(acc,x,y);  gp_term<I,1>(acc,x,y);  gp_term<I,2>(acc,x,y);  gp_term<I,3>(acc,x,y); \
  gp_term<I,4>(acc,x,y);  gp_term<I,5>(acc,x,y);  gp_term<I,6>(acc,x,y);  gp_term<I,7>(acc,x,y); \
  gp_term<I,8>(acc,x,y);  gp_term<I,9>(acc,x,y);  gp_term<I,10>(acc,x,y); gp_term<I,11>(acc,x,y);\
  gp_term<I,12>(acc,x,y); gp_term<I,13>(acc,x,y); gp_term<I,14>(acc,x,y); gp_term<I,15>(acc,x,y);

__device__ __forceinline__ float gelu_f(float v){
  float v3 = v*v*v;
  return 0.5f*v*(1.f + tanhf(0.7978845608028654f*(v + 0.044715f*v3)));
}

// ---- equi building blocks: TWO tokens per call (8-way ILP) ----
__device__ __forceinline__ void load_wmv_row(const float* wmv, int o, int kd, int ko, int pr,
                                             u64* wd2, u64* wp2){
  #pragma unroll
  for(int i=0;i<8;i++)
    wd2[i] = pack2f(wmv[o*144 + (2*i)*9 + kd], wmv[o*144 + (2*i+1)*9 + kd]);
  if (pr >= 0){
    #pragma unroll
    for(int i=0;i<8;i++)
      wp2[i] = pack2f(wmv[o*144 + (2*i)*9 + ko], wmv[o*144 + (2*i+1)*9 + ko]);
  }
}
__device__ __forceinline__ void equi_mv_val2(const float* X0, const float* X1, int a, int pr,
    const u64* wd2, const u64* wp2, const u64* wsm2, float& r0, float& r1){
  const u64* A0 = (const u64*)(X0 + a*20);
  const u64* A1 = (const u64*)(X1 + a*20);
  u64 p0 = fmul2(wd2[0], A0[0]), p1 = fmul2(wd2[1], A0[1]);
  u64 q0 = fmul2(wd2[0], A1[0]), q1 = fmul2(wd2[1], A1[1]);
  #pragma unroll
  for(int c=2;c<8;c+=2){
    p0 = ffma2(wd2[c],A0[c],p0); p1 = ffma2(wd2[c+1],A0[c+1],p1);
    q0 = ffma2(wd2[c],A1[c],q0); q1 = ffma2(wd2[c+1],A1[c+1],q1);
  }
  if (pr >= 0){
    const u64* B0 = (const u64*)(X0 + pr*20);
    const u64* B1 = (const u64*)(X1 + pr*20);
    #pragma unroll
    for(int c=0;c<8;c+=2){
      p0 = ffma2(wp2[c],B0[c],p0); p1 = ffma2(wp2[c+1],B0[c+1],p1);
      q0 = ffma2(wp2[c],B1[c],q0); q1 = ffma2(wp2[c+1],B1[c+1],q1);
    }
  }
  if (a == 0){
    const u64* S0 = (const u64*)(X0 + 320);
    const u64* S1 = (const u64*)(X1 + 320);
    #pragma unroll
    for(int c=0;c<16;c+=2){
      p0 = ffma2(wsm2[c],S0[c],p0); p1 = ffma2(wsm2[c+1],S0[c+1],p1);
      q0 = ffma2(wsm2[c],S1[c],q0); q1 = ffma2(wsm2[c+1],S1[c+1],q1);
    }
  }
  r0 = hadd2(fadd2(p0, p1));
  r1 = hadd2(fadd2(q0, q1));
}
__device__ __forceinline__ void equi_s_val2(const float* X0, const float* X1,
    const u64* wss2, const u64* wms2, float& r0, float& r1){
  const u64* S0 = (const u64*)(X0 + 320);
  const u64* S1 = (const u64*)(X1 + 320);
  u64 p0 = fmul2(wss2[0], S0[0]), p1 = fmul2(wss2[1], S0[1]);
  u64 q0 = fmul2(wss2[0], S1[0]), q1 = fmul2(wss2[1], S1[1]);
  #pragma unroll
  for(int c=2;c<16;c+=2){
    p0 = ffma2(wss2[c],S0[c],p0); p1 = ffma2(wss2[c+1],S0[c+1],p1);
    q0 = ffma2(wss2[c],S1[c],q0); q1 = ffma2(wss2[c+1],S1[c+1],q1);
  }
  const u64* Z0 = (const u64*)(X0);
  const u64* Z1 = (const u64*)(X1);
  #pragma unroll
  for(int c=0;c<8;c+=2){
    p0 = ffma2(wms2[c],Z0[c],p0); p1 = ffma2(wms2[c+1],Z0[c+1],p1);
    q0 = ffma2(wms2[c],Z1[c],q0); q1 = ffma2(wms2[c+1],Z1[c+1],q1);
  }
  r0 = hadd2(fadd2(p0, p1));
  r1 = hadd2(fadd2(q0, q1));
}

// ---------------- embed ----------------
__global__ void embed_kernel(const float* __restrict__ inp,
                             const float* __restrict__ win_mv,
                             const float* __restrict__ win_bs){
  int idx = blockIdx.x*blockDim.x + threadIdx.x;
  if (idx < NTOK*16){
    int t = idx>>4, o = idx&15;
    float x = inp[t*3+0], y = inp[t*3+1], z = inp[t*3+2];
    float w3 = win_mv[o*9+3], w8 = win_mv[o*9+8];
    float* M = g_mv + (size_t)t*256 + o*16;
    #pragma unroll
    for(int a=0;a<16;a++) M[a]=0.f;
    M[11] = -z*w3;  M[12] = y*w3;  M[13] = -x*w3;  M[14] = w3;  M[15] = w8;
  } else if (idx < NTOK*16 + NTOK*32){
    int r = idx - NTOK*16; int t = r>>5, j = r&31;
    g_s[t*32+j] = win_bs[j];
  }
}

// ---------------- LN + QKV equi, staged coalesced pack (layer 0 only) ------
__global__ void __launch_bounds__(864) qkv_kernel(
    const float* __restrict__ wmv, const float* __restrict__ wsm,
    const float* __restrict__ wms, const float* __restrict__ wss)
{
  constexpr int T = 16, NT = 864;
  extern __shared__ float sm[];
  float* SX = sm;            // T*352
  float* SY = sm + T*352;    // T*864
  const int tid = threadIdx.x;
  const size_t t0 = (size_t)blockIdx.x * T;
  const int b = (int)(t0 >> 10), n0 = (int)(t0 & 1023);

  for(int idx=tid; idx<T*256; idx+=NT){
    int t = idx>>8, r = idx&255, i = r>>4, a = r&15;
    SX[t*352 + a*20 + i] = g_mv[(t0+t)*256 + r];
  }
  for(int idx=tid; idx<T*32; idx+=NT){
    int t = idx>>5, j = idx&31;
    SX[t*352 + 320 + j] = g_s[(t0+t)*32 + j];
  }
  __syncthreads();

  { // LN: warp w -> token w
    int w = tid>>5, lane = tid&31;
    if (w < T){
      float* X = SX + w*352;
      int a = lane>>1;
      int base = a*20 + (lane&1)*8;
      float msk = c_inner[a];
      float ss = 0.f;
      #pragma unroll
      for(int r=0;r<8;r++){ float v = X[base+r]; ss += v*v*msk; }
      #pragma unroll
      for(int off=16;off;off>>=1) ss += __shfl_xor_sync(0xffffffffu, ss, off);
      float sc = rsqrtf(ss*0.0625f + 1e-6f);
      #pragma unroll
      for(int r=0;r<8;r++) X[base+r] *= sc;
      float v = X[320+lane];
      float s2 = v*v;
      #pragma unroll
      for(int off=16;off;off>>=1) s2 += __shfl_xor_sync(0xffffffffu, s2, off);
      X[320+lane] = v * rsqrtf(s2*0.03125f + 1e-6f);
    }
  }
  __syncthreads();

  if (tid < 768){
    int o = tid % 48, a = tid / 48;
    int kd = c_kdiag[a], pr = c_pair[a], ko = c_koff[a];
    u64 wd2[8], wp2[8], wsm2[16];
    load_wmv_row(wmv, o, kd, ko, pr, wd2, wp2);
    if (a == 0){
      #pragma unroll
      for(int j=0;j<16;j++) wsm2[j] = pack2f(wsm[o*32+2*j], wsm[o*32+2*j+1]);
    }
    for(int t=0; t<T; t+=2){
      float r0, r1;
      equi_mv_val2(SX + t*352, SX + (t+1)*352, a, pr, wd2, wp2, wsm2, r0, r1);
      SY[t*864 + a*48 + o] = r0;
      SY[(t+1)*864 + a*48 + o] = r1;
    }
  } else {
    int o = tid - 768;  // 0..95
    u64 wss2[16], wms2[8];
    #pragma unroll
    for(int j=0;j<16;j++) wss2[j] = pack2f(wss[o*32+2*j], wss[o*32+2*j+1]);
    #pragma unroll
    for(int i=0;i<8;i++)  wms2[i] = pack2f(wms[o*16+2*i], wms[o*16+2*i+1]);
    for(int t=0; t<T; t+=2){
      float r0, r1;
      equi_s_val2(SX + t*352, SX + (t+1)*352, wss2, wms2, r0, r1);
      SY[t*864 + 768 + o] = r0;
      SY[(t+1)*864 + 768 + o] = r1;
    }
  }
  __syncthreads();

  for(int idx=tid; idx<8*T*20; idx+=NT){           // Q
    int h = idx/(T*20), rem = idx%(T*20), t = rem/20, e = rem%20;
    float v;
    if (e < 16){ int ci=e>>3, ib=e&7, a=c_iblades[ib]; v = SY[t*864 + a*48 + (h*2+ci)]; }
    else       { v = SY[t*864 + 768 + h*4 + (e-16)]; }
    g_Q[((size_t)(b*8+h)*NSEQ + n0 + t)*20 + e] = v;
  }
  for(int idx=tid; idx<8*T*20; idx+=NT){           // K
    int h = idx/(T*20), rem = idx%(T*20), t = rem/20, e = rem%20;
    float v;
    if (e < 16){ int ci=e>>3, ib=e&7, a=c_iblades[ib]; v = SY[t*864 + a*48 + (16 + h*2+ci)]; }
    else       { v = SY[t*864 + 768 + 32 + h*4 + (e-16)]; }
    g_K[((size_t)(b*8+h)*NSEQ + n0 + t)*20 + e] = v;
  }
  for(int idx=tid; idx<8*T*36; idx+=NT){           // V
    int h = idx/(T*36), rem = idx%(T*36), t = rem/36, e = rem%36;
    float v;
    if (e < 32){ int ci=e>>4, a=e&15; v = SY[t*864 + a*48 + (32 + h*2+ci)]; }
    else       { v = SY[t*864 + 768 + 64 + h*4 + (e-32)]; }
    g_V[((size_t)(b*8+h)*NSEQ + n0 + t)*36 + e] = v;
  }
}

// ---------------- attention (split-KV x4, 2 q/thread, f32x2) ----------------
__global__ void __launch_bounds__(128) attn_kernel(){
  const int bh = blockIdx.x, qt = blockIdx.y, z = blockIdx.z, tid = threadIdx.x;
  const int qi0 = qt*256 + tid;
  const float SCALE = 0.22360679774997896f;  // 1/sqrt(20)

  extern __shared__ float4 dyn4[];
  float4* sk4 = dyn4;            // 2 x 640
  float4* sv4 = dyn4 + 1280;     // 2 x 1152

  u64 q0[10], q1[10];
  {
    const float* qp0 = g_Q + ((size_t)bh*NSEQ + qi0)*20;
    const float* qp1 = qp0 + 128*20;
    #pragma unroll
    for(int c=0;c<10;c++){
      q0[c] = pack2f(qp0[2*c]*SCALE, qp0[2*c+1]*SCALE);
      q1[c] = pack2f(qp1[2*c]*SCALE, qp1[2*c+1]*SCALE);
    }
  }
  float m0=-1e30f, l0=0.f, m1=-1e30f, l1=0.f;
  u64 a0[18], a1[18];
  #pragma unroll
  for(int c=0;c<18;c++){ a0[c]=0ull; a1[c]=0ull; }

  const int kt0 = z*2;
  const float4* kp = (const float4*)(g_K + (size_t)bh*NSEQ*20) + kt0*128*5;
  const float4* vp = (const float4*)(g_V + (size_t)bh*NSEQ*36) + kt0*128*9;

  #pragma unroll
  for(int i=0;i<5;i++) cpa16(&sk4[tid + 128*i], &kp[tid + 128*i]);
  #pragma unroll
  for(int i=0;i<9;i++) cpa16(&sv4[tid + 128*i], &vp[tid + 128*i]);
  cpa_commit();
  cpa_wait0();
  __syncthreads();

  for(int ki=0; ki<2; ki++){
    const int cur = ki & 1, nxt = cur ^ 1;
    if (ki < 1){
      const float4* kpn = kp + 128*5;
      const float4* vpn = vp + 128*9;
      #pragma unroll
      for(int i=0;i<5;i++) cpa16(&sk4[nxt*640 + tid + 128*i], &kpn[tid + 128*i]);
      #pragma unroll
      for(int i=0;i<9;i++) cpa16(&sv4[nxt*1152 + tid + 128*i], &vpn[tid + 128*i]);
      cpa_commit();
    }
    const float4* skc = sk4 + cur*640;
    const float4* svc = sv4 + cur*1152;

    for(int j=0; j<128; j++){
      const u64* kk = (const u64*)(skc + j*5);
      const u64* vv = (const u64*)(svc + j*9);
      u64 t0a = fmul2(q0[0], kk[0]), t0b = fmul2(q0[1], kk[1]);
      u64 t1a = fmul2(q1[0], kk[0]), t1b = fmul2(q1[1], kk[1]);
      #pragma unroll
      for(int c=2;c<10;c+=2){
        t0a = ffma2(q0[c], kk[c], t0a);  t0b = ffma2(q0[c+1], kk[c+1], t0b);
        t1a = ffma2(q1[c], kk[c], t1a);  t1b = ffma2(q1[c+1], kk[c+1], t1b);
      }
      float s0 = hadd2(fadd2(t0a, t0b));
      float s1 = hadd2(fadd2(t1a, t1b));
      float p0, p1;
      if (s0 > m0){
        float cc = __expf(m0 - s0); m0 = s0; l0 = l0*cc + 1.f;
        u64 cp = pack2f(cc, cc);
        #pragma unroll
        for(int c=0;c<18;c++) a0[c] = fmul2(a0[c], cp);
        p0 = 1.f;
      } else { p0 = __expf(s0 - m0); l0 += p0; }
      if (s1 > m1){
        float cc = __expf(m1 - s1); m1 = s1; l1 = l1*cc + 1.f;
        u64 cp = pack2f(cc, cc);
        #pragma unroll
        for(int c=0;c<18;c++) a1[c] = fmul2(a1[c], cp);
        p1 = 1.f;
      } else { p1 = __expf(s1 - m1); l1 += p1; }
      u64 pp0 = pack2f(p0, p0), pp1 = pack2f(p1, p1);
      #pragma unroll
      for(int c=0;c<18;c++){
        a0[c] = ffma2(pp0, vv[c], a0[c]);
        a1[c] = ffma2(pp1, vv[c], a1[c]);
      }
    }
    if (ki < 1){
      cpa_wait0();
      __syncthreads();
    }
  }
  float* op0 = g_Osp + ((size_t)(bh*NSEQ + qi0)*NSPLIT + z)*38;
  float* op1 = g_Osp + ((size_t)(bh*NSEQ + qi0 + 128)*NSPLIT + z)*38;
  #pragma unroll
  for(int c=0;c<18;c++){
    ((u64*)op0)[c] = a0[c];
    ((u64*)op1)[c] = a1[c];
  }
  op0[36] = m0; op0[37] = l0;
  op1[36] = m1; op1[37] = l1;
}

// ---- fused: merge + out-proj + res + LN + mlp1 + GP + mlp2 + res (+ next QKV)
// T=16 tokens/block, NT=576 threads. FQ: also produce next layer's Q/K/V.
template<bool FQ>
__global__ void __launch_bounds__(576) block2_kernel(
    const float* __restrict__ ao_wmv, const float* __restrict__ ao_wsm,
    const float* __restrict__ ao_wms, const float* __restrict__ ao_wss,
    const float* __restrict__ m1_wmv, const float* __restrict__ m1_wsm,
    const float* __restrict__ m1_wms, const float* __restrict__ m1_wss,
    const float* __restrict__ m2_wmv, const float* __restrict__ m2_wsm,
    const float* __restrict__ m2_wms, const float* __restrict__ m2_wss,
    const float* __restrict__ nq_wmv, const float* __restrict__ nq_wsm,
    const float* __restrict__ nq_wms, const float* __restrict__ nq_wss)
{
  constexpr int T = 16, NT = 576, SRS = 304;
  extern __shared__ float sm[];
  float* SA  = sm;                 // T*352  attn-out (blade-major); later SX2
  float* SR  = SA + T*352;         // T*304  residual [o*17+a], scalars at 272
  float* SW  = SR + T*SRS;         // T*8*NSPLIT merge weights
  float* SH  = SW + T*8*NSPLIT;    // T*864 region: mlp1 hidden (stride 608) / qkv SY (stride 864)
  float* SX2 = SA;
  const int tid = threadIdx.x;
  const size_t t0 = (size_t)blockIdx.x * T;
  const int b = (int)(t0 >> 10), n0 = (int)(t0 & 1023);

  // ---- stage 0: merge weights + residual loads ----
  if (tid < T*8){
    int t = tid>>3, h = tid&7;
    const float* p = g_Osp + (((size_t)(b*8+h)*NSEQ + n0 + t)*NSPLIT)*38;
    float m[NSPLIT], l[NSPLIT];
    float mm = -1e30f;
    #pragma unroll
    for(int z=0;z<NSPLIT;z++){ m[z]=p[z*38+36]; l[z]=p[z*38+37]; mm = fmaxf(mm, m[z]); }
    float den = 0.f, w[NSPLIT];
    #pragma unroll
    for(int z=0;z<NSPLIT;z++){ w[z] = __expf(m[z]-mm); den += l[z]*w[z]; }
    float inv = 1.f/den;
    #pragma unroll
    for(int z=0;z<NSPLIT;z++) SW[tid*NSPLIT + z] = w[z]*inv;
  }
  for(int idx=tid; idx<T*256; idx+=NT){
    int t = idx>>8, r = idx&255;
    SR[t*SRS + (r>>4)*17 + (r&15)] = g_mv[(t0+t)*256 + r];
  }
  for(int idx=tid; idx<T*32; idx+=NT){
    int t = idx>>5, j = idx&31;
    SR[t*SRS + 272 + j] = g_s[(t0+t)*32 + j];
  }
  __syncthreads();

  // ---- stage 1: merged attn-out -> SA (blade-major) ----
  for(int idx=tid; idx<T*288; idx+=NT){
    int t = idx/288, r = idx%288;
    int h = r/36, e = r%36;
    const float* p = g_Osp + (((size_t)(b*8+h)*NSEQ + n0 + t)*NSPLIT)*38;
    const float* wv = SW + (t*8+h)*NSPLIT;
    float v = 0.f;
    #pragma unroll
    for(int z=0;z<NSPLIT;z++) v += p[z*38 + e] * wv[z];
    if (e < 32){ int ci=e>>4, a=e&15; SA[t*352 + a*20 + (h*2+ci)] = v; }
    else       { SA[t*352 + 320 + h*4 + (e-32)] = v; }
  }
  __syncthreads();

  // ---- stage 2: out-projection equi + residual add into SR ----
  {
    int out = tid % 288, tp = tid / 288;   // tp in {0,1}
    if (out < 256){
      int o = out & 15, a = out >> 4;
      int kd = c_kdiag[a], pr = c_pair[a], ko = c_koff[a];
      u64 wd2[8], wp2[8], wsm2[16];
      load_wmv_row(ao_wmv, o, kd, ko, pr, wd2, wp2);
      if (a == 0){
        #pragma unroll
        for(int j=0;j<16;j++) wsm2[j] = pack2f(ao_wsm[o*32+2*j], ao_wsm[o*32+2*j+1]);
      }
      #pragma unroll
      for(int tt=0; tt<4; tt++){
        int t = tp + tt*4;
        float r0, r1;
        equi_mv_val2(SA + t*352, SA + (t+2)*352, a, pr, wd2, wp2, wsm2, r0, r1);
        SR[t*SRS + o*17 + a] += r0;
        SR[(t+2)*SRS + o*17 + a] += r1;
      }
    } else {
      int o = out - 256;
      u64 wss2[16], wms2[8];
      #pragma unroll
      for(int j=0;j<16;j++) wss2[j] = pack2f(ao_wss[o*32+2*j], ao_wss[o*32+2*j+1]);
      #pragma unroll
      for(int i=0;i<8;i++)  wms2[i] = pack2f(ao_wms[o*16+2*i], ao_wms[o*16+2*i+1]);
      #pragma unroll
      for(int tt=0; tt<4; tt++){
        int t = tp + tt*4;
        float r0, r1;
        equi_s_val2(SA + t*352, SA + (t+2)*352, wss2, wms2, r0, r1);
        SR[t*SRS + 272 + o] += r0;
        SR[(t+2)*SRS + 272 + o] += r1;
      }
    }
  }
  __syncthreads();

  // ---- stage 3: LN(SR) -> SX2 ----
  {
    int w = tid>>5, lane = tid&31;
    if (w < T){
      const float* R = SR + w*SRS;
      float ss = 0.f;
      #pragma unroll
      for(int r=0;r<8;r++){
        int li = lane + 32*r; int o = li>>4, a = li&15;
        float v = R[o*17 + a]; ss += v*v*c_inner[a];
      }
      #pragma unroll
      for(int off=16;off;off>>=1) ss += __shfl_xor_sync(0xffffffffu, ss, off);
      float sc = rsqrtf(ss*0.0625f + 1e-6f);
      #pragma unroll
      for(int r=0;r<8;r++){
        int li = lane + 32*r; int o = li>>4, a = li&15;
        SX2[w*352 + a*20 + o] = R[o*17 + a]*sc;
      }
      float v = R[272+lane];
      float s2 = v*v;
      #pragma unroll
      for(int off=16;off;off>>=1) s2 += __shfl_xor_sync(0xffffffffu, s2, off);
      SX2[w*352 + 320 + lane] = v * rsqrtf(s2*0.03125f + 1e-6f);
    }
  }
  __syncthreads();

  // ---- stage 4: mlp1 equi (512 mv outs + 64 s outs) -> SH (stride 608) ----
  if (tid < 512){
    int o = tid % 32, a = tid / 32;
    int kd = c_kdiag[a], pr = c_pair[a], ko = c_koff[a];
    u64 wd2[8], wp2[8], wsm2[16];
    load_wmv_row(m1_wmv, o, kd, ko, pr, wd2, wp2);
    if (a == 0){
      #pragma unroll
      for(int j=0;j<16;j++) wsm2[j] = pack2f(m1_wsm[o*32+2*j], m1_wsm[o*32+2*j+1]);
    }
    for(int t=0; t<T; t+=2){
      float r0, r1;
      equi_mv_val2(SX2 + t*352, SX2 + (t+1)*352, a, pr, wd2, wp2, wsm2, r0, r1);
      SH[t*608 + o*17 + a] = r0;
      SH[(t+1)*608 + o*17 + a] = r1;
    }
  } else {
    int o = tid - 512;  // 0..63
    u64 wss2[16], wms2[8];
    #pragma unroll
    for(int j=0;j<16;j++) wss2[j] = pack2f(m1_wss[o*32+2*j], m1_wss[o*32+2*j+1]);
    #pragma unroll
    for(int i=0;i<8;i++)  wms2[i] = pack2f(m1_wms[o*16+2*i], m1_wms[o*16+2*i+1]);
    for(int t=0; t<T; t+=2){
      float r0, r1;
      equi_s_val2(SX2 + t*352, SX2 + (t+1)*352, wss2, wms2, r0, r1);
      SH[t*608 + 544 + o] = r0;
      SH[(t+1)*608 + 544 + o] = r1;
    }
  }
  __syncthreads();

  // ---- stage 5: geometric product + gated gelu -> SX2 ----
  for(int idx=tid; idx<T*48; idx+=NT){
    if (idx < T*16){
      int t = idx>>4, c = idx&15;
      const float* h1 = SH + t*608 + c*17;
      const float* h2 = SH + t*608 + (16+c)*17;
      float x[16], y[16], acc[16];
      #pragma unroll
      for(int i=0;i<16;i++){ x[i]=h1[i]; y[i]=h2[i]; acc[i]=0.f; }
      GP_ROW(0)  GP_ROW(1)  GP_ROW(2)  GP_ROW(3)
      GP_ROW(4)  GP_ROW(5)  GP_ROW(6)  GP_ROW(7)
      GP_ROW(8)  GP_ROW(9)  GP_ROW(10) GP_ROW(11)
      GP_ROW(12) GP_ROW(13) GP_ROW(14) GP_ROW(15)
      float g = gelu_f(acc[0]);
      #pragma unroll
      for(int a=0;a<16;a++) SX2[t*352 + a*20 + c] = acc[a]*g;
    } else {
      int r = idx - T*16; int t = r>>5, j = r&31;
      const float* hs = SH + t*608 + 544;
      SX2[t*352 + 320 + j] = hs[j] * gelu_f(hs[32+j]);
    }
  }
  __syncthreads();

  // ---- stage 6: mlp2 equi + residual add into SR ----
  {
    int out = tid % 288, tp = tid / 288;
    if (out < 256){
      int o = out & 15, a = out >> 4;
      int kd = c_kdiag[a], pr = c_pair[a], ko = c_koff[a];
      u64 wd2[8], wp2[8], wsm2[16];
      load_wmv_row(m2_wmv, o, kd, ko, pr, wd2, wp2);
      if (a == 0){
        #pragma unroll
        for(int j=0;j<16;j++) wsm2[j] = pack2f(m2_wsm[o*32+2*j], m2_wsm[o*32+2*j+1]);
      }
      #pragma unroll
      for(int tt=0; tt<4; tt++){
        int t = tp + tt*4;
        float r0, r1;
        equi_mv_val2(SX2 + t*352, SX2 + (t+2)*352, a, pr, wd2, wp2, wsm2, r0, r1);
        SR[t*SRS + o*17 + a] += r0;
        SR[(t+2)*SRS + o*17 + a] += r1;
      }
    } else {
      int o = out - 256;
      u64 wss2[16], wms2[8];
      #pragma unroll
      for(int j=0;j<16;j++) wss2[j] = pack2f(m2_wss[o*32+2*j], m2_wss[o*32+2*j+1]);
      #pragma unroll
      for(int i=0;i<8;i++)  wms2[i] = pack2f(m2_wms[o*16+2*i], m2_wms[o*16+2*i+1]);
      #pragma unroll
      for(int tt=0; tt<4; tt++){
        int t = tp + tt*4;
        float r0, r1;
        equi_s_val2(SX2 + t*352, SX2 + (t+2)*352, wss2, wms2, r0, r1);
        SR[t*SRS + 272 + o] += r0;
        SR[(t+2)*SRS + 272 + o] += r1;
      }
    }
  }
  __syncthreads();

  // ---- stage 7: store residual to global ----
  for(int idx=tid; idx<T*256; idx+=NT){
    int t = idx>>8, r = idx&255;
    g_mv[(t0+t)*256 + r] = SR[t*SRS + (r>>4)*17 + (r&15)];
  }
  for(int idx=tid; idx<T*32; idx+=NT){
    int t = idx>>5, j = idx&31;
    g_s[(t0+t)*32 + j] = SR[t*SRS + 272 + j];
  }

  if (!FQ) return;

  // ---- stage 8: LN(SR) -> SX2 (for next layer's QKV) ----
  {
    int w = tid>>5, lane = tid&31;
    if (w < T){
      const float* R = SR + w*SRS;
      float ss = 0.f;
      #pragma unroll
      for(int r=0;r<8;r++){
        int li = lane + 32*r; int o = li>>4, a = li&15;
        float v = R[o*17 + a]; ss += v*v*c_inner[a];
      }
      #pragma unroll
      for(int off=16;off;off>>=1) ss += __shfl_xor_sync(0xffffffffu, ss, off);
      float sc = rsqrtf(ss*0.0625f + 1e-6f);
      #pragma unroll
      for(int r=0;r<8;r++){
        int li = lane + 32*r; int o = li>>4, a = li&15;
        SX2[w*352 + a*20 + o] = R[o*17 + a]*sc;
      }
      float v = R[272+lane];
      float s2 = v*v;
      #pragma unroll
      for(int off=16;off;off>>=1) s2 += __shfl_xor_sync(0xffffffffu, s2, off);
      SX2[w*352 + 320 + lane] = v * rsqrtf(s2*0.03125f + 1e-6f);
    }
  }
  __syncthreads();

  // ---- stage 9: next-layer QKV equi -> SH as SY (stride 864) ----
  for(int out = tid; out < 864; out += NT){
    if (out < 768){
      int o = out % 48, a = out / 48;
      int kd = c_kdiag[a], pr = c_pair[a], ko = c_koff[a];
      u64 wd2[8], wp2[8], wsm2[16];
      load_wmv_row(nq_wmv, o, kd, ko, pr, wd2, wp2);
      if (a == 0){
        #pragma unroll
        for(int j=0;j<16;j++) wsm2[j] = pack2f(nq_wsm[o*32+2*j], nq_wsm[o*32+2*j+1]);
      }
      for(int t=0; t<T; t+=2){
        float r0, r1;
        equi_mv_val2(SX2 + t*352, SX2 + (t+1)*352, a, pr, wd2, wp2, wsm2, r0, r1);
        SH[t*864 + a*48 + o] = r0;
        SH[(t+1)*864 + a*48 + o] = r1;
      }
    } else {
      int o = out - 768;  // 0..95
      u64 wss2[16], wms2[8];
      #pragma unroll
      for(int j=0;j<16;j++) wss2[j] = pack2f(nq_wss[o*32+2*j], nq_wss[o*32+2*j+1]);
      #pragma unroll
      for(int i=0;i<8;i++)  wms2[i] = pack2f(nq_wms[o*16+2*i], nq_wms[o*16+2*i+1]);
      for(int t=0; t<T; t+=2){
        float r0, r1;
        equi_s_val2(SX2 + t*352, SX2 + (t+1)*352, wss2, wms2, r0, r1);
        SH[t*864 + 768 + o] = r0;
        SH[(t+1)*864 + 768 + o] = r1;
      }
    }
  }
  __syncthreads();

  // ---- stage 10: pack Q/K/V ----
  for(int idx=tid; idx<8*T*20; idx+=NT){           // Q
    int h = idx/(T*20), rem = idx%(T*20), t = rem/20, e = rem%20;
    float v;
    if (e < 16){ int ci=e>>3, ib=e&7, a=c_iblades[ib]; v = SH[t*864 + a*48 + (h*2+ci)]; }
    else       { v = SH[t*864 + 768 + h*4 + (e-16)]; }
    g_Q[((size_t)(b*8+h)*NSEQ + n0 + t)*20 + e] = v;
  }
  for(int idx=tid; idx<8*T*20; idx+=NT){           // K
    int h = idx/(T*20), rem = idx%(T*20), t = rem/20, e = rem%20;
    float v;
    if (e < 16){ int ci=e>>3, ib=e&7, a=c_iblades[ib]; v = SH[t*864 + a*48 + (16 + h*2+ci)]; }
    else       { v = SH[t*864 + 768 + 32 + h*4 + (e-16)]; }
    g_K[((size_t)(b*8+h)*NSEQ + n0 + t)*20 + e] = v;
  }
  for(int idx=tid; idx<8*T*36; idx+=NT){           // V
    int h = idx/(T*36), rem = idx%(T*36), t = rem/36, e = rem%36;
    float v;
    if (e < 32){ int ci=e>>4, a=e&15; v = SH[t*864 + a*48 + (32 + h*2+ci)]; }
    else       { v = SH[t*864 + 768 + 64 + h*4 + (e-32)]; }
    g_V[((size_t)(b*8+h)*NSEQ + n0 + t)*36 + e] = v;
  }
}

// ---------------- final projection + mean ----------------
__global__ void final_kernel(const float* __restrict__ wout_mv,
                             const float* __restrict__ wout_sm,
                             float* __restrict__ out){
  int b = blockIdx.x, tid = threadIdx.x;
  __shared__ float red[256];
  float acc = 0.f;
  for(int n=tid; n<NSEQ; n+=256){
    size_t t = (size_t)b*NSEQ + n;
    const float* M = g_mv + t*256;
    const float* S = g_s + t*32;
    float v = 0.f;
    #pragma unroll
    for(int i=0;i<16;i++) v += wout_mv[i*9] * M[i*16];
    #pragma unroll
    for(int j=0;j<32;j++) v += wout_sm[j] * S[j];
    acc += v;
  }
  red[tid] = acc; __syncthreads();
  for(int s=128; s; s>>=1){ if (tid < s) red[tid] += red[tid+s]; __syncthreads(); }
  if (tid == 0) out[b] = red[0] * (1.f/NSEQ);
}

// ---------------- host ----------------
extern "C" void kernel_launch(void* const* d_in, const int* in_sizes, int n_in,
                              void* d_out, int out_size) {
  const float* inputs    = (const float*)d_in[0];
  const float* win_mv    = (const float*)d_in[1];
  const float* win_bs    = (const float*)d_in[3];
  const float* qkv_wmv   = (const float*)d_in[4];
  const float* qkv_wsm   = (const float*)d_in[5];
  const float* qkv_wms   = (const float*)d_in[6];
  const float* qkv_wss   = (const float*)d_in[7];
  const float* aout_wmv  = (const float*)d_in[8];
  const float* aout_wsm  = (const float*)d_in[9];
  const float* aout_wms  = (const float*)d_in[10];
  const float* aout_wss  = (const float*)d_in[11];
  const float* m1_wmv    = (const float*)d_in[12];
  const float* m1_wsm    = (const float*)d_in[13];
  const float* m1_wms    = (const float*)d_in[14];
  const float* m1_wss    = (const float*)d_in[15];
  const float* m2_wmv    = (const float*)d_in[16];
  const float* m2_wsm    = (const float*)d_in[17];
  const float* m2_wms    = (const float*)d_in[18];
  const float* m2_wss    = (const float*)d_in[19];
  const float* wout_mv   = (const float*)d_in[20];
  const float* wout_sm   = (const float*)d_in[21];

  const int smem_qkv  = (16*352 + 16*864) * 4;                        // 77824
  const int smem_blk  = (16*352 + 16*304 + 16*8*NSPLIT + 16*864) * 4; // 99328
  const int smem_attn = (2*640 + 2*1152) * 16;                        // 57344
  cudaFuncSetAttribute((const void*)qkv_kernel,
                       cudaFuncAttributeMaxDynamicSharedMemorySize, smem_qkv);
  cudaFuncSetAttribute((const void*)block2_kernel<true>,
                       cudaFuncAttributeMaxDynamicSharedMemorySize, smem_blk);
  cudaFuncSetAttribute((const void*)block2_kernel<false>,
                       cudaFuncAttributeMaxDynamicSharedMemorySize, smem_blk);
  cudaFuncSetAttribute((const void*)attn_kernel,
                       cudaFuncAttributeMaxDynamicSharedMemorySize, smem_attn);

  embed_kernel<<<(NTOK*48 + 255)/256, 256>>>(inputs, win_mv, win_bs);

  qkv_kernel<<<NTOK/16, 864, smem_qkv>>>(
      qkv_wmv, qkv_wsm, qkv_wms, qkv_wss);

  for (int l = 0; l < 8; l++){
    attn_kernel<<<dim3(64, NSEQ/256, NSPLIT), 128, smem_attn>>>();
    if (l < 7){
      int ln = l + 1;
      block2_kernel<true><<<NTOK/16, 576, smem_blk>>>(
          aout_wmv + (size_t)l*16*16*9, aout_wsm + (size_t)l*16*32,
          aout_wms + (size_t)l*32*16,   aout_wss + (size_t)l*32*32,
          m1_wmv  + (size_t)l*32*16*9,  m1_wsm  + (size_t)l*32*32,
          m1_wms  + (size_t)l*64*16,    m1_wss  + (size_t)l*64*32,
          m2_wmv  + (size_t)l*16*16*9,  m2_wsm  + (size_t)l*16*32,
          m2_wms  + (size_t)l*32*16,    m2_wss  + (size_t)l*32*32,
          qkv_wmv + (size_t)ln*48*16*9, qkv_wsm + (size_t)ln*48*32,
          qkv_wms + (size_t)ln*96*16,   qkv_wss + (size_t)ln*96*32);
    } else {
      block2_kernel<false><<<NTOK/16, 576, smem_blk>>>(
          aout_wmv + (size_t)l*16*16*9, aout_wsm + (size_t)l*16*32,
          aout_wms + (size_t)l*32*16,   aout_wss + (size_t)l*32*32,
          m1_wmv  + (size_t)l*32*16*9,  m1_wsm  + (size_t)l*32*32,
          m1_wms  + (size_t)l*64*16,    m1_wss  + (size_t)l*64*32,
          m2_wmv  + (size_t)l*16*16*9,  m2_wsm  + (size_t)l*16*32,
          m2_wms  + (size_t)l*32*16,    m2_wss  + (size_t)l*32*32,
          qkv_wmv, qkv_wsm, qkv_wms, qkv_wss);
    }
  }

  final_kernel<<<NBAT, 256>>>(wout_mv, wout_sm, (float*)d_out);
}

// round 12
// speedup vs baseline: 1.5973x; 1.0013x over previous
#include <cuda_runtime.h>
#include <math.h>

#define NTOK 8192
#define NSEQ 1024
#define NBAT 8
#define NSPLIT 4

typedef unsigned long long u64;

// ---------------- f32x2 packed helpers (Blackwell) ----------------
__device__ __forceinline__ u64 pack2f(float lo, float hi){
  u64 r; asm("mov.b64 %0, {%1, %2};" : "=l"(r) : "f"(lo), "f"(hi)); return r;
}
__device__ __forceinline__ u64 ffma2(u64 a, u64 b, u64 c){
  u64 d; asm("fma.rn.f32x2 %0, %1, %2, %3;" : "=l"(d) : "l"(a), "l"(b), "l"(c)); return d;
}
__device__ __forceinline__ u64 fmul2(u64 a, u64 b){
  u64 d; asm("mul.rn.f32x2 %0, %1, %2;" : "=l"(d) : "l"(a), "l"(b)); return d;
}
__device__ __forceinline__ u64 fadd2(u64 a, u64 b){
  u64 d; asm("add.rn.f32x2 %0, %1, %2;" : "=l"(d) : "l"(a), "l"(b)); return d;
}
__device__ __forceinline__ float hadd2(u64 v){
  float a,b; asm("mov.b64 {%0, %1}, %2;" : "=f"(a), "=f"(b) : "l"(v)); return a+b;
}
__device__ __forceinline__ u64 lo2(float4 v){ return pack2f(v.x, v.y); }
__device__ __forceinline__ u64 hi2(float4 v){ return pack2f(v.z, v.w); }
// ---------------- cp.async helpers ----------------
__device__ __forceinline__ void cpa16(void* s, const void* g){
  unsigned sa = (unsigned)__cvta_generic_to_shared(s);
  asm volatile("cp.async.cg.shared.global [%0], [%1], 16;" :: "r"(sa), "l"(g));
}
__device__ __forceinline__ void cpa_commit(){ asm volatile("cp.async.commit_group;"); }
__device__ __forceinline__ void cpa_wait0(){ asm volatile("cp.async.wait_group 0;"); }

// ---------------- device scratch ----------------
__device__ float g_mv [NTOK*256];
__device__ float g_s  [NTOK*32];
__device__ float g_Q[(size_t)64*NSEQ*20];
__device__ float g_K[(size_t)64*NSEQ*20];
__device__ float g_V[(size_t)64*NSEQ*36];
__device__ float g_Osp[(size_t)64*NSEQ*NSPLIT*38];   // [bh][n][split][36 acc + m + l]

// ---------------- blade tables ----------------
__constant__ int   c_kdiag[16] = {0,1,1,1,1,2,2,2,2,2,2,3,3,3,3,4};
__constant__ int   c_pair [16] = {-1,0,-1,-1,-1,2,3,4,-1,-1,-1,8,9,10,-1,14};
__constant__ int   c_koff [16] = {0,5,0,0,0,6,6,6,0,0,0,7,7,7,0,8};
__constant__ float c_inner[16] = {1,0,1,1,1,0,0,0,1,1,1,0,0,0,1,0};
__constant__ int   c_iblades[8]= {0,2,3,4,8,9,10,14};

// compile-time blade algebra (geometric product)
__host__ __device__ constexpr int blade_mask(int i){
  return i==0?0: i==1?1: i==2?2: i==3?4: i==4?8: i==5?3: i==6?5: i==7?9:
         i==8?6: i==9?10: i==10?12: i==11?7: i==12?11: i==13?13: i==14?14: 15;
}
__host__ __device__ constexpr int mask_idx(int m){
  return m==0?0: m==1?1: m==2?2: m==3?5: m==4?3: m==5?6: m==6?8: m==7?11:
         m==8?4: m==9?7: m==10?9: m==11?12: m==12?10: m==13?13: m==14?14: 15;
}
__host__ __device__ constexpr int pc4(int v){ return (v&1)+((v>>1)&1)+((v>>2)&1)+((v>>3)&1); }
__host__ __device__ constexpr int gp_par(int ma,int mb){
  return ( ((mb&1)?pc4(ma>>1):0) + (((mb>>1)&1)?pc4(ma>>2):0) + (((mb>>2)&1)?pc4(ma>>3):0) ) & 1;
}
template<int I,int J>
__device__ __forceinline__ void gp_term(float (&acc)[16], const float* x, const float* y){
  constexpr int ma = blade_mask(I);
  constexpr int mb = blade_mask(J);
  if constexpr (!(ma & mb & 1)) {
    constexpr int k  = mask_idx(ma ^ mb);
    constexpr int sg = gp_par(ma, mb);
    float p = x[I]*y[J];
    if constexpr (sg) acc[k] -= p; else acc[k] += p;
  }
}
#define GP_ROW(I) \
  gp_term<I,0>(acc,x,y);  gp_term<I,1>(acc,x,y);  gp_term<I,2>(acc,x,y);  gp_term<I,3>(acc,x,y); \
  gp_term<I,4>(acc,x,y);  gp_term<I,5>(acc,x,y);  gp_term<I,6>(acc,x,y);  gp_term<I,7>(acc,x,y); \
  gp_term<I,8>(acc,x,y);  gp_term<I,9>(acc,x,y);  gp_term<I,10>(acc,x,y); gp_term<I,11>(acc,x,y);\
  gp_term<I,12>(acc,x,y); gp_term<I,13>(acc,x,y); gp_term<I,14>(acc,x,y); gp_term<I,15>(acc,x,y);

__device__ __forceinline__ float gelu_f(float v){
  float v3 = v*v*v;
  return 0.5f*v*(1.f + tanhf(0.7978845608028654f*(v + 0.044715f*v3)));
}

// ---- equi building blocks: TWO tokens per call, float4 (LDS.128) loads ----
__device__ __forceinline__ void load_wmv_row(const float* wmv, int o, int kd, int ko, int pr,
                                             u64* wd2, u64* wp2){
  #pragma unroll
  for(int i=0;i<8;i++)
    wd2[i] = pack2f(wmv[o*144 + (2*i)*9 + kd], wmv[o*144 + (2*i+1)*9 + kd]);
  if (pr >= 0){
    #pragma unroll
    for(int i=0;i<8;i++)
      wp2[i] = pack2f(wmv[o*144 + (2*i)*9 + ko], wmv[o*144 + (2*i+1)*9 + ko]);
  }
}
__device__ __forceinline__ void equi_mv_val2(const float* X0, const float* X1, int a, int pr,
    const u64* wd2, const u64* wp2, const u64* wsm2, float& r0, float& r1){
  const float4* A0 = (const float4*)(X0 + a*20);
  const float4* A1 = (const float4*)(X1 + a*20);
  u64 p0, p1, q0, q1;
  {
    float4 f0 = A0[0], f1 = A0[1], g0 = A1[0], g1 = A1[1];
    p0 = fmul2(wd2[0], lo2(f0)); p1 = fmul2(wd2[1], hi2(f0));
    q0 = fmul2(wd2[0], lo2(g0)); q1 = fmul2(wd2[1], hi2(g0));
    p0 = ffma2(wd2[2], lo2(f1), p0); p1 = ffma2(wd2[3], hi2(f1), p1);
    q0 = ffma2(wd2[2], lo2(g1), q0); q1 = ffma2(wd2[3], hi2(g1), q1);
    float4 f2 = A0[2], f3 = A0[3], g2 = A1[2], g3 = A1[3];
    p0 = ffma2(wd2[4], lo2(f2), p0); p1 = ffma2(wd2[5], hi2(f2), p1);
    q0 = ffma2(wd2[4], lo2(g2), q0); q1 = ffma2(wd2[5], hi2(g2), q1);
    p0 = ffma2(wd2[6], lo2(f3), p0); p1 = ffma2(wd2[7], hi2(f3), p1);
    q0 = ffma2(wd2[6], lo2(g3), q0); q1 = ffma2(wd2[7], hi2(g3), q1);
  }
  if (pr >= 0){
    const float4* B0 = (const float4*)(X0 + pr*20);
    const float4* B1 = (const float4*)(X1 + pr*20);
    float4 f0 = B0[0], f1 = B0[1], g0 = B1[0], g1 = B1[1];
    p0 = ffma2(wp2[0], lo2(f0), p0); p1 = ffma2(wp2[1], hi2(f0), p1);
    q0 = ffma2(wp2[0], lo2(g0), q0); q1 = ffma2(wp2[1], hi2(g0), q1);
    p0 = ffma2(wp2[2], lo2(f1), p0); p1 = ffma2(wp2[3], hi2(f1), p1);
    q0 = ffma2(wp2[2], lo2(g1), q0); q1 = ffma2(wp2[3], hi2(g1), q1);
    float4 f2 = B0[2], f3 = B0[3], g2 = B1[2], g3 = B1[3];
    p0 = ffma2(wp2[4], lo2(f2), p0); p1 = ffma2(wp2[5], hi2(f2), p1);
    q0 = ffma2(wp2[4], lo2(g2), q0); q1 = ffma2(wp2[5], hi2(g2), q1);
    p0 = ffma2(wp2[6], lo2(f3), p0); p1 = ffma2(wp2[7], hi2(f3), p1);
    q0 = ffma2(wp2[6], lo2(g3), q0); q1 = ffma2(wp2[7], hi2(g3), q1);
  }
  if (a == 0){
    const float4* S0 = (const float4*)(X0 + 320);
    const float4* S1 = (const float4*)(X1 + 320);
    #pragma unroll
    for(int c=0;c<8;c++){
      float4 f = S0[c], g = S1[c];
      p0 = ffma2(wsm2[2*c], lo2(f), p0); p1 = ffma2(wsm2[2*c+1], hi2(f), p1);
      q0 = ffma2(wsm2[2*c], lo2(g), q0); q1 = ffma2(wsm2[2*c+1], hi2(g), q1);
    }
  }
  r0 = hadd2(fadd2(p0, p1));
  r1 = hadd2(fadd2(q0, q1));
}
__device__ __forceinline__ void equi_s_val2(const float* X0, const float* X1,
    const u64* wss2, const u64* wms2, float& r0, float& r1){
  const float4* S0 = (const float4*)(X0 + 320);
  const float4* S1 = (const float4*)(X1 + 320);
  u64 p0, p1, q0, q1;
  {
    float4 f = S0[0], g = S1[0];
    p0 = fmul2(wss2[0], lo2(f)); p1 = fmul2(wss2[1], hi2(f));
    q0 = fmul2(wss2[0], lo2(g)); q1 = fmul2(wss2[1], hi2(g));
  }
  #pragma unroll
  for(int c=1;c<8;c++){
    float4 f = S0[c], g = S1[c];
    p0 = ffma2(wss2[2*c], lo2(f), p0); p1 = ffma2(wss2[2*c+1], hi2(f), p1);
    q0 = ffma2(wss2[2*c], lo2(g), q0); q1 = ffma2(wss2[2*c+1], hi2(g), q1);
  }
  const float4* Z0 = (const float4*)(X0);
  const float4* Z1 = (const float4*)(X1);
  #pragma unroll
  for(int c=0;c<4;c++){
    float4 f = Z0[c], g = Z1[c];
    p0 = ffma2(wms2[2*c], lo2(f), p0); p1 = ffma2(wms2[2*c+1], hi2(f), p1);
    q0 = ffma2(wms2[2*c], lo2(g), q0); q1 = ffma2(wms2[2*c+1], hi2(g), q1);
  }
  r0 = hadd2(fadd2(p0, p1));
  r1 = hadd2(fadd2(q0, q1));
}

// ---------------- embed ----------------
__global__ void embed_kernel(const float* __restrict__ inp,
                             const float* __restrict__ win_mv,
                             const float* __restrict__ win_bs){
  int idx = blockIdx.x*blockDim.x + threadIdx.x;
  if (idx < NTOK*16){
    int t = idx>>4, o = idx&15;
    float x = inp[t*3+0], y = inp[t*3+1], z = inp[t*3+2];
    float w3 = win_mv[o*9+3], w8 = win_mv[o*9+8];
    float* M = g_mv + (size_t)t*256 + o*16;
    #pragma unroll
    for(int a=0;a<16;a++) M[a]=0.f;
    M[11] = -z*w3;  M[12] = y*w3;  M[13] = -x*w3;  M[14] = w3;  M[15] = w8;
  } else if (idx < NTOK*16 + NTOK*32){
    int r = idx - NTOK*16; int t = r>>5, j = r&31;
    g_s[t*32+j] = win_bs[j];
  }
}

// ---------------- LN + QKV equi, staged coalesced pack (layer 0 only) ------
__global__ void __launch_bounds__(864) qkv_kernel(
    const float* __restrict__ wmv, const float* __restrict__ wsm,
    const float* __restrict__ wms, const float* __restrict__ wss)
{
  constexpr int T = 16, NT = 864;
  extern __shared__ float sm[];
  float* SX = sm;            // T*352
  float* SY = sm + T*352;    // T*864
  const int tid = threadIdx.x;
  const size_t t0 = (size_t)blockIdx.x * T;
  const int b = (int)(t0 >> 10), n0 = (int)(t0 & 1023);

  for(int idx=tid; idx<T*256; idx+=NT){
    int t = idx>>8, r = idx&255, i = r>>4, a = r&15;
    SX[t*352 + a*20 + i] = g_mv[(t0+t)*256 + r];
  }
  for(int idx=tid; idx<T*32; idx+=NT){
    int t = idx>>5, j = idx&31;
    SX[t*352 + 320 + j] = g_s[(t0+t)*32 + j];
  }
  __syncthreads();

  { // LN: warp w -> token w
    int w = tid>>5, lane = tid&31;
    if (w < T){
      float* X = SX + w*352;
      int a = lane>>1;
      int base = a*20 + (lane&1)*8;
      float msk = c_inner[a];
      float ss = 0.f;
      #pragma unroll
      for(int r=0;r<8;r++){ float v = X[base+r]; ss += v*v*msk; }
      #pragma unroll
      for(int off=16;off;off>>=1) ss += __shfl_xor_sync(0xffffffffu, ss, off);
      float sc = rsqrtf(ss*0.0625f + 1e-6f);
      #pragma unroll
      for(int r=0;r<8;r++) X[base+r] *= sc;
      float v = X[320+lane];
      float s2 = v*v;
      #pragma unroll
      for(int off=16;off;off>>=1) s2 += __shfl_xor_sync(0xffffffffu, s2, off);
      X[320+lane] = v * rsqrtf(s2*0.03125f + 1e-6f);
    }
  }
  __syncthreads();

  if (tid < 768){
    int o = tid % 48, a = tid / 48;
    int kd = c_kdiag[a], pr = c_pair[a], ko = c_koff[a];
    u64 wd2[8], wp2[8], wsm2[16];
    load_wmv_row(wmv, o, kd, ko, pr, wd2, wp2);
    if (a == 0){
      #pragma unroll
      for(int j=0;j<16;j++) wsm2[j] = pack2f(wsm[o*32+2*j], wsm[o*32+2*j+1]);
    }
    for(int t=0; t<T; t+=2){
      float r0, r1;
      equi_mv_val2(SX + t*352, SX + (t+1)*352, a, pr, wd2, wp2, wsm2, r0, r1);
      SY[t*864 + a*48 + o] = r0;
      SY[(t+1)*864 + a*48 + o] = r1;
    }
  } else {
    int o = tid - 768;  // 0..95
    u64 wss2[16], wms2[8];
    #pragma unroll
    for(int j=0;j<16;j++) wss2[j] = pack2f(wss[o*32+2*j], wss[o*32+2*j+1]);
    #pragma unroll
    for(int i=0;i<8;i++)  wms2[i] = pack2f(wms[o*16+2*i], wms[o*16+2*i+1]);
    for(int t=0; t<T; t+=2){
      float r0, r1;
      equi_s_val2(SX + t*352, SX + (t+1)*352, wss2, wms2, r0, r1);
      SY[t*864 + 768 + o] = r0;
      SY[(t+1)*864 + 768 + o] = r1;
    }
  }
  __syncthreads();

  for(int idx=tid; idx<8*T*20; idx+=NT){           // Q
    int h = idx/(T*20), rem = idx%(T*20), t = rem/20, e = rem%20;
    float v;
    if (e < 16){ int ci=e>>3, ib=e&7, a=c_iblades[ib]; v = SY[t*864 + a*48 + (h*2+ci)]; }
    else       { v = SY[t*864 + 768 + h*4 + (e-16)]; }
    g_Q[((size_t)(b*8+h)*NSEQ + n0 + t)*20 + e] = v;
  }
  for(int idx=tid; idx<8*T*20; idx+=NT){           // K
    int h = idx/(T*20), rem = idx%(T*20), t = rem/20, e = rem%20;
    float v;
    if (e < 16){ int ci=e>>3, ib=e&7, a=c_iblades[ib]; v = SY[t*864 + a*48 + (16 + h*2+ci)]; }
    else       { v = SY[t*864 + 768 + 32 + h*4 + (e-16)]; }
    g_K[((size_t)(b*8+h)*NSEQ + n0 + t)*20 + e] = v;
  }
  for(int idx=tid; idx<8*T*36; idx+=NT){           // V
    int h = idx/(T*36), rem = idx%(T*36), t = rem/36, e = rem%36;
    float v;
    if (e < 32){ int ci=e>>4, a=e&15; v = SY[t*864 + a*48 + (32 + h*2+ci)]; }
    else       { v = SY[t*864 + 768 + 64 + h*4 + (e-32)]; }
    g_V[((size_t)(b*8+h)*NSEQ + n0 + t)*36 + e] = v;
  }
}

// ---------------- attention (split-KV x4, 2 q/thread, float4 LDS) ----------
__global__ void __launch_bounds__(128) attn_kernel(){
  const int bh = blockIdx.x, qt = blockIdx.y, z = blockIdx.z, tid = threadIdx.x;
  const int qi0 = qt*256 + tid;
  const float SCALE = 0.22360679774997896f;  // 1/sqrt(20)

  extern __shared__ float4 dyn4[];
  float4* sk4 = dyn4;            // 2 x 640
  float4* sv4 = dyn4 + 1280;     // 2 x 1152

  u64 q0[10], q1[10];
  {
    const float* qp0 = g_Q + ((size_t)bh*NSEQ + qi0)*20;
    const float* qp1 = qp0 + 128*20;
    #pragma unroll
    for(int c=0;c<10;c++){
      q0[c] = pack2f(qp0[2*c]*SCALE, qp0[2*c+1]*SCALE);
      q1[c] = pack2f(qp1[2*c]*SCALE, qp1[2*c+1]*SCALE);
    }
  }
  float m0=-1e30f, l0=0.f, m1=-1e30f, l1=0.f;
  u64 a0[18], a1[18];
  #pragma unroll
  for(int c=0;c<18;c++){ a0[c]=0ull; a1[c]=0ull; }

  const int kt0 = z*2;
  const float4* kp = (const float4*)(g_K + (size_t)bh*NSEQ*20) + kt0*128*5;
  const float4* vp = (const float4*)(g_V + (size_t)bh*NSEQ*36) + kt0*128*9;

  #pragma unroll
  for(int i=0;i<5;i++) cpa16(&sk4[tid + 128*i], &kp[tid + 128*i]);
  #pragma unroll
  for(int i=0;i<9;i++) cpa16(&sv4[tid + 128*i], &vp[tid + 128*i]);
  cpa_commit();
  cpa_wait0();
  __syncthreads();

  for(int ki=0; ki<2; ki++){
    const int cur = ki & 1, nxt = cur ^ 1;
    if (ki < 1){
      const float4* kpn = kp + 128*5;
      const float4* vpn = vp + 128*9;
      #pragma unroll
      for(int i=0;i<5;i++) cpa16(&sk4[nxt*640 + tid + 128*i], &kpn[tid + 128*i]);
      #pragma unroll
      for(int i=0;i<9;i++) cpa16(&sv4[nxt*1152 + tid + 128*i], &vpn[tid + 128*i]);
      cpa_commit();
    }
    const float4* skc = sk4 + cur*640;
    const float4* svc = sv4 + cur*1152;

    for(int j=0; j<128; j++){
      const float4* kk4 = skc + j*5;
      float4 k0 = kk4[0], k1 = kk4[1], k2 = kk4[2], k3 = kk4[3], k4 = kk4[4];
      u64 t0a = fmul2(q0[0], lo2(k0)), t0b = fmul2(q0[1], hi2(k0));
      u64 t1a = fmul2(q1[0], lo2(k0)), t1b = fmul2(q1[1], hi2(k0));
      t0a = ffma2(q0[2], lo2(k1), t0a); t0b = ffma2(q0[3], hi2(k1), t0b);
      t1a = ffma2(q1[2], lo2(k1), t1a); t1b = ffma2(q1[3], hi2(k1), t1b);
      t0a = ffma2(q0[4], lo2(k2), t0a); t0b = ffma2(q0[5], hi2(k2), t0b);
      t1a = ffma2(q1[4], lo2(k2), t1a); t1b = ffma2(q1[5], hi2(k2), t1b);
      t0a = ffma2(q0[6], lo2(k3), t0a); t0b = ffma2(q0[7], hi2(k3), t0b);
      t1a = ffma2(q1[6], lo2(k3), t1a); t1b = ffma2(q1[7], hi2(k3), t1b);
      t0a = ffma2(q0[8], lo2(k4), t0a); t0b = ffma2(q0[9], hi2(k4), t0b);
      t1a = ffma2(q1[8], lo2(k4), t1a); t1b = ffma2(q1[9], hi2(k4), t1b);
      float s0 = hadd2(fadd2(t0a, t0b));
      float s1 = hadd2(fadd2(t1a, t1b));
      float p0, p1;
      if (s0 > m0){
        float cc = __expf(m0 - s0); m0 = s0; l0 = l0*cc + 1.f;
        u64 cp = pack2f(cc, cc);
        #pragma unroll
        for(int c=0;c<18;c++) a0[c] = fmul2(a0[c], cp);
        p0 = 1.f;
      } else { p0 = __expf(s0 - m0); l0 += p0; }
      if (s1 > m1){
        float cc = __expf(m1 - s1); m1 = s1; l1 = l1*cc + 1.f;
        u64 cp = pack2f(cc, cc);
        #pragma unroll
        for(int c=0;c<18;c++) a1[c] = fmul2(a1[c], cp);
        p1 = 1.f;
      } else { p1 = __expf(s1 - m1); l1 += p1; }
      u64 pp0 = pack2f(p0, p0), pp1 = pack2f(p1, p1);
      const float4* vv4 = svc + j*9;
      #pragma unroll
      for(int i=0;i<9;i++){
        float4 v4 = vv4[i];
        u64 vl = lo2(v4), vh = hi2(v4);
        a0[2*i]   = ffma2(pp0, vl, a0[2*i]);
        a0[2*i+1] = ffma2(pp0, vh, a0[2*i+1]);
        a1[2*i]   = ffma2(pp1, vl, a1[2*i]);
        a1[2*i+1] = ffma2(pp1, vh, a1[2*i+1]);
      }
    }
    if (ki < 1){
      cpa_wait0();
      __syncthreads();
    }
  }
  float* op0 = g_Osp + ((size_t)(bh*NSEQ + qi0)*NSPLIT + z)*38;
  float* op1 = g_Osp + ((size_t)(bh*NSEQ + qi0 + 128)*NSPLIT + z)*38;
  #pragma unroll
  for(int c=0;c<18;c++){
    ((u64*)op0)[c] = a0[c];
    ((u64*)op1)[c] = a1[c];
  }
  op0[36] = m0; op0[37] = l0;
  op1[36] = m1; op1[37] = l1;
}

// ---- fused: merge + out-proj + res + LN + mlp1 + GP + mlp2 + res (+ next QKV)
template<bool FQ>
__global__ void __launch_bounds__(576) block2_kernel(
    const float* __restrict__ ao_wmv, const float* __restrict__ ao_wsm,
    const float* __restrict__ ao_wms, const float* __restrict__ ao_wss,
    const float* __restrict__ m1_wmv, const float* __restrict__ m1_wsm,
    const float* __restrict__ m1_wms, const float* __restrict__ m1_wss,
    const float* __restrict__ m2_wmv, const float* __restrict__ m2_wsm,
    const float* __restrict__ m2_wms, const float* __restrict__ m2_wss,
    const float* __restrict__ nq_wmv, const float* __restrict__ nq_wsm,
    const float* __restrict__ nq_wms, const float* __restrict__ nq_wss)
{
  constexpr int T = 16, NT = 576, SRS = 304;
  extern __shared__ float sm[];
  float* SA  = sm;                 // T*352  attn-out (blade-major); later SX2
  float* SR  = SA + T*352;         // T*304  residual [o*17+a], scalars at 272
  float* SW  = SR + T*SRS;         // T*8*NSPLIT merge weights
  float* SH  = SW + T*8*NSPLIT;    // T*864 region: mlp1 hidden (608) / qkv SY (864)
  float* SX2 = SA;
  const int tid = threadIdx.x;
  const size_t t0 = (size_t)blockIdx.x * T;
  const int b = (int)(t0 >> 10), n0 = (int)(t0 & 1023);

  // ---- stage 0: merge weights + residual loads ----
  if (tid < T*8){
    int t = tid>>3, h = tid&7;
    const float* p = g_Osp + (((size_t)(b*8+h)*NSEQ + n0 + t)*NSPLIT)*38;
    float m[NSPLIT], l[NSPLIT];
    float mm = -1e30f;
    #pragma unroll
    for(int z=0;z<NSPLIT;z++){ m[z]=p[z*38+36]; l[z]=p[z*38+37]; mm = fmaxf(mm, m[z]); }
    float den = 0.f, w[NSPLIT];
    #pragma unroll
    for(int z=0;z<NSPLIT;z++){ w[z] = __expf(m[z]-mm); den += l[z]*w[z]; }
    float inv = 1.f/den;
    #pragma unroll
    for(int z=0;z<NSPLIT;z++) SW[tid*NSPLIT + z] = w[z]*inv;
  }
  for(int idx=tid; idx<T*256; idx+=NT){
    int t = idx>>8, r = idx&255;
    SR[t*SRS + (r>>4)*17 + (r&15)] = g_mv[(t0+t)*256 + r];
  }
  for(int idx=tid; idx<T*32; idx+=NT){
    int t = idx>>5, j = idx&31;
    SR[t*SRS + 272 + j] = g_s[(t0+t)*32 + j];
  }
  __syncthreads();

  // ---- stage 1: merged attn-out -> SA (blade-major) ----
  for(int idx=tid; idx<T*288; idx+=NT){
    int t = idx/288, r = idx%288;
    int h = r/36, e = r%36;
    const float* p = g_Osp + (((size_t)(b*8+h)*NSEQ + n0 + t)*NSPLIT)*38;
    const float* wv = SW + (t*8+h)*NSPLIT;
    float v = 0.f;
    #pragma unroll
    for(int z=0;z<NSPLIT;z++) v += p[z*38 + e] * wv[z];
    if (e < 32){ int ci=e>>4, a=e&15; SA[t*352 + a*20 + (h*2+ci)] = v; }
    else       { SA[t*352 + 320 + h*4 + (e-32)] = v; }
  }
  __syncthreads();

  // ---- stage 2: out-projection equi + residual add into SR ----
  {
    int out = tid % 288, tp = tid / 288;   // tp in {0,1}
    if (out < 256){
      int o = out & 15, a = out >> 4;
      int kd = c_kdiag[a], pr = c_pair[a], ko = c_koff[a];
      u64 wd2[8], wp2[8], wsm2[16];
      load_wmv_row(ao_wmv, o, kd, ko, pr, wd2, wp2);
      if (a == 0){
        #pragma unroll
        for(int j=0;j<16;j++) wsm2[j] = pack2f(ao_wsm[o*32+2*j], ao_wsm[o*32+2*j+1]);
      }
      #pragma unroll
      for(int tt=0; tt<4; tt++){
        int t = tp + tt*4;
        float r0, r1;
        equi_mv_val2(SA + t*352, SA + (t+2)*352, a, pr, wd2, wp2, wsm2, r0, r1);
        SR[t*SRS + o*17 + a] += r0;
        SR[(t+2)*SRS + o*17 + a] += r1;
      }
    } else {
      int o = out - 256;
      u64 wss2[16], wms2[8];
      #pragma unroll
      for(int j=0;j<16;j++) wss2[j] = pack2f(ao_wss[o*32+2*j], ao_wss[o*32+2*j+1]);
      #pragma unroll
      for(int i=0;i<8;i++)  wms2[i] = pack2f(ao_wms[o*16+2*i], ao_wms[o*16+2*i+1]);
      #pragma unroll
      for(int tt=0; tt<4; tt++){
        int t = tp + tt*4;
        float r0, r1;
        equi_s_val2(SA + t*352, SA + (t+2)*352, wss2, wms2, r0, r1);
        SR[t*SRS + 272 + o] += r0;
        SR[(t+2)*SRS + 272 + o] += r1;
      }
    }
  }
  __syncthreads();

  // ---- stage 3: LN(SR) -> SX2 ----
  {
    int w = tid>>5, lane = tid&31;
    if (w < T){
      const float* R = SR + w*SRS;
      float ss = 0.f;
      #pragma unroll
      for(int r=0;r<8;r++){
        int li = lane + 32*r; int o = li>>4, a = li&15;
        float v = R[o*17 + a]; ss += v*v*c_inner[a];
      }
      #pragma unroll
      for(int off=16;off;off>>=1) ss += __shfl_xor_sync(0xffffffffu, ss, off);
      float sc = rsqrtf(ss*0.0625f + 1e-6f);
      #pragma unroll
      for(int r=0;r<8;r++){
        int li = lane + 32*r; int o = li>>4, a = li&15;
        SX2[w*352 + a*20 + o] = R[o*17 + a]*sc;
      }
      float v = R[272+lane];
      float s2 = v*v;
      #pragma unroll
      for(int off=16;off;off>>=1) s2 += __shfl_xor_sync(0xffffffffu, s2, off);
      SX2[w*352 + 320 + lane] = v * rsqrtf(s2*0.03125f + 1e-6f);
    }
  }
  __syncthreads();

  // ---- stage 4: mlp1 equi (512 mv outs + 64 s outs) -> SH (stride 608) ----
  if (tid < 512){
    int o = tid % 32, a = tid / 32;
    int kd = c_kdiag[a], pr = c_pair[a], ko = c_koff[a];
    u64 wd2[8], wp2[8], wsm2[16];
    load_wmv_row(m1_wmv, o, kd, ko, pr, wd2, wp2);
    if (a == 0){
      #pragma unroll
      for(int j=0;j<16;j++) wsm2[j] = pack2f(m1_wsm[o*32+2*j], m1_wsm[o*32+2*j+1]);
    }
    for(int t=0; t<T; t+=2){
      float r0, r1;
      equi_mv_val2(SX2 + t*352, SX2 + (t+1)*352, a, pr, wd2, wp2, wsm2, r0, r1);
      SH[t*608 + o*17 + a] = r0;
      SH[(t+1)*608 + o*17 + a] = r1;
    }
  } else {
    int o = tid - 512;  // 0..63
    u64 wss2[16], wms2[8];
    #pragma unroll
    for(int j=0;j<16;j++) wss2[j] = pack2f(m1_wss[o*32+2*j], m1_wss[o*32+2*j+1]);
    #pragma unroll
    for(int i=0;i<8;i++)  wms2[i] = pack2f(m1_wms[o*16+2*i], m1_wms[o*16+2*i+1]);
    for(int t=0; t<T; t+=2){
      float r0, r1;
      equi_s_val2(SX2 + t*352, SX2 + (t+1)*352, wss2, wms2, r0, r1);
      SH[t*608 + 544 + o] = r0;
      SH[(t+1)*608 + 544 + o] = r1;
    }
  }
  __syncthreads();

  // ---- stage 5: geometric product + gated gelu -> SX2 ----
  for(int idx=tid; idx<T*48; idx+=NT){
    if (idx < T*16){
      int t = idx>>4, c = idx&15;
      const float* h1 = SH + t*608 + c*17;
      const float* h2 = SH + t*608 + (16+c)*17;
      float x[16], y[16], acc[16];
      #pragma unroll
      for(int i=0;i<16;i++){ x[i]=h1[i]; y[i]=h2[i]; acc[i]=0.f; }
      GP_ROW(0)  GP_ROW(1)  GP_ROW(2)  GP_ROW(3)
      GP_ROW(4)  GP_ROW(5)  GP_ROW(6)  GP_ROW(7)
      GP_ROW(8)  GP_ROW(9)  GP_ROW(10) GP_ROW(11)
      GP_ROW(12) GP_ROW(13) GP_ROW(14) GP_ROW(15)
      float g = gelu_f(acc[0]);
      #pragma unroll
      for(int a=0;a<16;a++) SX2[t*352 + a*20 + c] = acc[a]*g;
    } else {
      int r = idx - T*16; int t = r>>5, j = r&31;
      const float* hs = SH + t*608 + 544;
      SX2[t*352 + 320 + j] = hs[j] * gelu_f(hs[32+j]);
    }
  }
  __syncthreads();

  // ---- stage 6: mlp2 equi + residual add into SR ----
  {
    int out = tid % 288, tp = tid / 288;
    if (out < 256){
      int o = out & 15, a = out >> 4;
      int kd = c_kdiag[a], pr = c_pair[a], ko = c_koff[a];
      u64 wd2[8], wp2[8], wsm2[16];
      load_wmv_row(m2_wmv, o, kd, ko, pr, wd2, wp2);
      if (a == 0){
        #pragma unroll
        for(int j=0;j<16;j++) wsm2[j] = pack2f(m2_wsm[o*32+2*j], m2_wsm[o*32+2*j+1]);
      }
      #pragma unroll
      for(int tt=0; tt<4; tt++){
        int t = tp + tt*4;
        float r0, r1;
        equi_mv_val2(SX2 + t*352, SX2 + (t+2)*352, a, pr, wd2, wp2, wsm2, r0, r1);
        SR[t*SRS + o*17 + a] += r0;
        SR[(t+2)*SRS + o*17 + a] += r1;
      }
    } else {
      int o = out - 256;
      u64 wss2[16], wms2[8];
      #pragma unroll
      for(int j=0;j<16;j++) wss2[j] = pack2f(m2_wss[o*32+2*j], m2_wss[o*32+2*j+1]);
      #pragma unroll
      for(int i=0;i<8;i++)  wms2[i] = pack2f(m2_wms[o*16+2*i], m2_wms[o*16+2*i+1]);
      #pragma unroll
      for(int tt=0; tt<4; tt++){
        int t = tp + tt*4;
        float r0, r1;
        equi_s_val2(SX2 + t*352, SX2 + (t+2)*352, wss2, wms2, r0, r1);
        SR[t*SRS + 272 + o] += r0;
        SR[(t+2)*SRS + 272 + o] += r1;
      }
    }
  }
  __syncthreads();

  // ---- stage 7: store residual to global ----
  for(int idx=tid; idx<T*256; idx+=NT){
    int t = idx>>8, r = idx&255;
    g_mv[(t0+t)*256 + r] = SR[t*SRS + (r>>4)*17 + (r&15)];
  }
  for(int idx=tid; idx<T*32; idx+=NT){
    int t = idx>>5, j = idx&31;
    g_s[(t0+t)*32 + j] = SR[t*SRS + 272 + j];
  }

  if (!FQ) return;

  // ---- stage 8: LN(SR) -> SX2 (for next layer's QKV) ----
  {
    int w = tid>>5, lane = tid&31;
    if (w < T){
      const float* R = SR + w*SRS;
      float ss = 0.f;
      #pragma unroll
      for(int r=0;r<8;r++){
        int li = lane + 32*r; int o = li>>4, a = li&15;
        float v = R[o*17 + a]; ss += v*v*c_inner[a];
      }
      #pragma unroll
      for(int off=16;off;off>>=1) ss += __shfl_xor_sync(0xffffffffu, ss, off);
      float sc = rsqrtf(ss*0.0625f + 1e-6f);
      #pragma unroll
      for(int r=0;r<8;r++){
        int li = lane + 32*r; int o = li>>4, a = li&15;
        SX2[w*352 + a*20 + o] = R[o*17 + a]*sc;
      }
      float v = R[272+lane];
      float s2 = v*v;
      #pragma unroll
      for(int off=16;off;off>>=1) s2 += __shfl_xor_sync(0xffffffffu, s2, off);
      SX2[w*352 + 320 + lane] = v * rsqrtf(s2*0.03125f + 1e-6f);
    }
  }
  __syncthreads();

  // ---- stage 9: next-layer QKV equi -> SH as SY (stride 864) ----
  for(int out = tid; out < 864; out += NT){
    if (out < 768){
      int o = out % 48, a = out / 48;
      int kd = c_kdiag[a], pr = c_pair[a], ko = c_koff[a];
      u64 wd2[8], wp2[8], wsm2[16];
      load_wmv_row(nq_wmv, o, kd, ko, pr, wd2, wp2);
      if (a == 0){
        #pragma unroll
        for(int j=0;j<16;j++) wsm2[j] = pack2f(nq_wsm[o*32+2*j], nq_wsm[o*32+2*j+1]);
      }
      for(int t=0; t<T; t+=2){
        float r0, r1;
        equi_mv_val2(SX2 + t*352, SX2 + (t+1)*352, a, pr, wd2, wp2, wsm2, r0, r1);
        SH[t*864 + a*48 + o] = r0;
        SH[(t+1)*864 + a*48 + o] = r1;
      }
    } else {
      int o = out - 768;  // 0..95
      u64 wss2[16], wms2[8];
      #pragma unroll
      for(int j=0;j<16;j++) wss2[j] = pack2f(nq_wss[o*32+2*j], nq_wss[o*32+2*j+1]);
      #pragma unroll
      for(int i=0;i<8;i++)  wms2[i] = pack2f(nq_wms[o*16+2*i], nq_wms[o*16+2*i+1]);
      for(int t=0; t<T; t+=2){
        float r0, r1;
        equi_s_val2(SX2 + t*352, SX2 + (t+1)*352, wss2, wms2, r0, r1);
        SH[t*864 + 768 + o] = r0;
        SH[(t+1)*864 + 768 + o] = r1;
      }
    }
  }
  __syncthreads();

  // ---- stage 10: pack Q/K/V ----
  for(int idx=tid; idx<8*T*20; idx+=NT){           // Q
    int h = idx/(T*20), rem = idx%(T*20), t = rem/20, e = rem%20;
    float v;
    if (e < 16){ int ci=e>>3, ib=e&7, a=c_iblades[ib]; v = SH[t*864 + a*48 + (h*2+ci)]; }
    else       { v = SH[t*864 + 768 + h*4 + (e-16)]; }
    g_Q[((size_t)(b*8+h)*NSEQ + n0 + t)*20 + e] = v;
  }
  for(int idx=tid; idx<8*T*20; idx+=NT){           // K
    int h = idx/(T*20), rem = idx%(T*20), t = rem/20, e = rem%20;
    float v;
    if (e < 16){ int ci=e>>3, ib=e&7, a=c_iblades[ib]; v = SH[t*864 + a*48 + (16 + h*2+ci)]; }
    else       { v = SH[t*864 + 768 + 32 + h*4 + (e-16)]; }
    g_K[((size_t)(b*8+h)*NSEQ + n0 + t)*20 + e] = v;
  }
  for(int idx=tid; idx<8*T*36; idx+=NT){           // V
    int h = idx/(T*36), rem = idx%(T*36), t = rem/36, e = rem%36;
    float v;
    if (e < 32){ int ci=e>>4, a=e&15; v = SH[t*864 + a*48 + (32 + h*2+ci)]; }
    else       { v = SH[t*864 + 768 + 64 + h*4 + (e-32)]; }
    g_V[((size_t)(b*8+h)*NSEQ + n0 + t)*36 + e] = v;
  }
}

// ---------------- final projection + mean ----------------
__global__ void final_kernel(const float* __restrict__ wout_mv,
                             const float* __restrict__ wout_sm,
                             float* __restrict__ out){
  int b = blockIdx.x, tid = threadIdx.x;
  __shared__ float red[256];
  float acc = 0.f;
  for(int n=tid; n<NSEQ; n+=256){
    size_t t = (size_t)b*NSEQ + n;
    const float* M = g_mv + t*256;
    const float* S = g_s + t*32;
    float v = 0.f;
    #pragma unroll
    for(int i=0;i<16;i++) v += wout_mv[i*9] * M[i*16];
    #pragma unroll
    for(int j=0;j<32;j++) v += wout_sm[j] * S[j];
    acc += v;
  }
  red[tid] = acc; __syncthreads();
  for(int s=128; s; s>>=1){ if (tid < s) red[tid] += red[tid+s]; __syncthreads(); }
  if (tid == 0) out[b] = red[0] * (1.f/NSEQ);
}

// ---------------- host ----------------
extern "C" void kernel_launch(void* const* d_in, const int* in_sizes, int n_in,
                              void* d_out, int out_size) {
  const float* inputs    = (const float*)d_in[0];
  const float* win_mv    = (const float*)d_in[1];
  const float* win_bs    = (const float*)d_in[3];
  const float* qkv_wmv   = (const float*)d_in[4];
  const float* qkv_wsm   = (const float*)d_in[5];
  const float* qkv_wms   = (const float*)d_in[6];
  const float* qkv_wss   = (const float*)d_in[7];
  const float* aout_wmv  = (const float*)d_in[8];
  const float* aout_wsm  = (const float*)d_in[9];
  const float* aout_wms  = (const float*)d_in[10];
  const float* aout_wss  = (const float*)d_in[11];
  const float* m1_wmv    = (const float*)d_in[12];
  const float* m1_wsm    = (const float*)d_in[13];
  const float* m1_wms    = (const float*)d_in[14];
  const float* m1_wss    = (const float*)d_in[15];
  const float* m2_wmv    = (const float*)d_in[16];
  const float* m2_wsm    = (const float*)d_in[17];
  const float* m2_wms    = (const float*)d_in[18];
  const float* m2_wss    = (const float*)d_in[19];
  const float* wout_mv   = (const float*)d_in[20];
  const float* wout_sm   = (const float*)d_in[21];

  const int smem_qkv  = (16*352 + 16*864) * 4;                        // 77824
  const int smem_blk  = (16*352 + 16*304 + 16*8*NSPLIT + 16*864) * 4; // 99328
  const int smem_attn = (2*640 + 2*1152) * 16;                        // 57344
  cudaFuncSetAttribute((const void*)qkv_kernel,
                       cudaFuncAttributeMaxDynamicSharedMemorySize, smem_qkv);
  cudaFuncSetAttribute((const void*)block2_kernel<true>,
                       cudaFuncAttributeMaxDynamicSharedMemorySize, smem_blk);
  cudaFuncSetAttribute((const void*)block2_kernel<false>,
                       cudaFuncAttributeMaxDynamicSharedMemorySize, smem_blk);
  cudaFuncSetAttribute((const void*)attn_kernel,
                       cudaFuncAttributeMaxDynamicSharedMemorySize, smem_attn);

  embed_kernel<<<(NTOK*48 + 255)/256, 256>>>(inputs, win_mv, win_bs);

  qkv_kernel<<<NTOK/16, 864, smem_qkv>>>(
      qkv_wmv, qkv_wsm, qkv_wms, qkv_wss);

  for (int l = 0; l < 8; l++){
    attn_kernel<<<dim3(64, NSEQ/256, NSPLIT), 128, smem_attn>>>();
    if (l < 7){
      int ln = l + 1;
      block2_kernel<true><<<NTOK/16, 576, smem_blk>>>(
          aout_wmv + (size_t)l*16*16*9, aout_wsm + (size_t)l*16*32,
          aout_wms + (size_t)l*32*16,   aout_wss + (size_t)l*32*32,
          m1_wmv  + (size_t)l*32*16*9,  m1_wsm  + (size_t)l*32*32,
          m1_wms  + (size_t)l*64*16,    m1_wss  + (size_t)l*64*32,
          m2_wmv  + (size_t)l*16*16*9,  m2_wsm  + (size_t)l*16*32,
          m2_wms  + (size_t)l*32*16,    m2_wss  + (size_t)l*32*32,
          qkv_wmv + (size_t)ln*48*16*9, qkv_wsm + (size_t)ln*48*32,
          qkv_wms + (size_t)ln*96*16,   qkv_wss + (size_t)ln*96*32);
    } else {
      block2_kernel<false><<<NTOK/16, 576, smem_blk>>>(
          aout_wmv + (size_t)l*16*16*9, aout_wsm + (size_t)l*16*32,
          aout_wms + (size_t)l*32*16,   aout_wss + (size_t)l*32*32,
          m1_wmv  + (size_t)l*32*16*9,  m1_wsm  + (size_t)l*32*32,
          m1_wms  + (size_t)l*64*16,    m1_wss  + (size_t)l*64*32,
          m2_wmv  + (size_t)l*16*16*9,  m2_wsm  + (size_t)l*16*32,
          m2_wms  + (size_t)l*32*16,    m2_wss  + (size_t)l*32*32,
          qkv_wmv, qkv_wsm, qkv_wms, qkv_wss);
    }
  }

  final_kernel<<<NBAT, 256>>>(wout_mv, wout_sm, (float*)d_out);
}